// round 5
// baseline (speedup 1.0000x reference)
#include <cuda_runtime.h>
#include <cstdint>

#define BB 128
#define LCDIM 256
#define LEDIM 1024
#define DDIM 256
#define MMDIM 512
#define NEGV -1e9f

// ---------------- scratch ----------------------------------------------------
__device__ float g_c[(size_t)BB * LCDIM * DDIM];      // c (tf32-rounded), later r1-pre (fp32)
__device__ float g_e[(size_t)BB * LEDIM * DDIM];      // e (tf32-rounded), later r2-pre (fp32)
__device__ float g_align[(size_t)BB * LCDIM * LEDIM]; // align fp32, then alpha (rounded) in-place
__device__ float g_betaT[(size_t)BB * LCDIM * LEDIM]; // beta^T rounded
__device__ float g_attc[(size_t)BB * LCDIM * DDIM];   // rounded
__device__ float g_atte[(size_t)BB * LEDIM * DDIM];   // rounded
__device__ float g_ehrT[(size_t)BB * LEDIM * DDIM];   // rounded (D, Le)
__device__ float g_critT[(size_t)BB * LCDIM * DDIM];  // rounded (D, Lc)
__device__ float g_ehrR[(size_t)BB * LEDIM * DDIM];   // rounded row-major ehr
__device__ float g_critR[(size_t)BB * LCDIM * DDIM];  // rounded row-major criteria
__device__ float g_WaT[DDIM * DDIM];                  // rounded
__device__ float g_WrT[2 * DDIM * DDIM];              // rounded
__device__ float g_r1p[BB * 4 * DDIM];
__device__ float g_r2p[BB * 4 * DDIM];
__device__ float g_cmx[BB * LEDIM];
__device__ float g_cinv[BB * LEDIM];

// ---------------- helpers -----------------------------------------------------
__device__ __forceinline__ uint32_t tf32rna(float x) {
    uint32_t u;
    asm("cvt.rna.tf32.f32 %0, %1;" : "=r"(u) : "f"(x));
    return u;
}
__device__ __forceinline__ float tf32rnaf(float x) {
    return __uint_as_float(tf32rna(x));
}

__device__ __forceinline__ void ldsm4(uint32_t& r0, uint32_t& r1, uint32_t& r2,
                                      uint32_t& r3, const uint32_t* p) {
    uint32_t addr = (uint32_t)__cvta_generic_to_shared(p);
    asm volatile("ldmatrix.sync.aligned.m8n8.x4.shared.b16 {%0,%1,%2,%3}, [%4];"
                 : "=r"(r0), "=r"(r1), "=r"(r2), "=r"(r3) : "r"(addr));
}

__device__ __forceinline__ void mma8(float* c, const uint32_t* a, uint32_t b0, uint32_t b1) {
    asm volatile(
        "mma.sync.aligned.m16n8k8.row.col.f32.tf32.tf32.f32 "
        "{%0,%1,%2,%3}, {%4,%5,%6,%7}, {%8,%9}, {%0,%1,%2,%3};"
        : "+f"(c[0]), "+f"(c[1]), "+f"(c[2]), "+f"(c[3])
        : "r"(a[0]), "r"(a[1]), "r"(a[2]), "r"(a[3]), "r"(b0), "r"(b1));
}

// ---------------- TF32 tensor-core GEMM, all operands pre-rounded ------------
// All operand tensors hold values already rounded to tf32 (cvt.rna applied at
// production time) -> hardware bit-truncation inside HMMA is exact, and the
// hot loop has ZERO cvt instructions.
// C[M,N] row-major = epilogue(A@B). A[m][k] at A + m*sAm + k (sAk==1).
// B logical [k][n] stored n-major: B + n*sBn + k. A2: k >= Ksplit (concat).
#define BM 128
#define BN 128
#define BKT 16
#define PAD 20

__global__ __launch_bounds__(256) void gemm_tc(
    const float* __restrict__ A, const float* __restrict__ A2, int Ksplit,
    const float* __restrict__ B, const float* __restrict__ bias,
    float* __restrict__ C,
    int M, int N, int K,
    long sAm, long bsA, long sBn, long bsB, long bsC,
    int do_relu, int round_out)
{
    A += (long)blockIdx.z * bsA;
    if (A2) A2 += (long)blockIdx.z * bsA;
    B += (long)blockIdx.z * bsB;
    C += (long)blockIdx.z * bsC;

    __shared__ uint32_t As[2][BM * PAD];
    __shared__ uint32_t Bs[2][BN * PAD];

    const int tid = threadIdx.x;
    const int lane = tid & 31;
    const int w = tid >> 5;
    const int wm = (w & 1) * 64;
    const int wn = (w >> 1) * 32;
    const int m0 = blockIdx.y * BM;
    const int n0 = blockIdx.x * BN;

    const int lrow0 = tid >> 2;              // 0..63
    const int lk = (tid & 3) * 4;            // 0,4,8,12

    uint4 ra[2], rb[2];

    auto loadA = [&](int k0) {
        const float* Ap = A; int kb = k0;
        if (A2 && k0 >= Ksplit) { Ap = A2; kb = k0 - Ksplit; }
#pragma unroll
        for (int i = 0; i < 2; i++) {
            int m = lrow0 + i * 64;
            ra[i] = *reinterpret_cast<const uint4*>(Ap + (long)(m0 + m) * sAm + kb + lk);
        }
    };
    auto loadB = [&](int k0) {
#pragma unroll
        for (int i = 0; i < 2; i++) {
            int n = lrow0 + i * 64;
            rb[i] = *reinterpret_cast<const uint4*>(B + (long)(n0 + n) * sBn + k0 + lk);
        }
    };
    auto stage = [&](int s) {
#pragma unroll
        for (int i = 0; i < 2; i++) {
            int r = lrow0 + i * 64;
            *reinterpret_cast<uint4*>(&As[s][r * PAD + lk]) = ra[i];
            *reinterpret_cast<uint4*>(&Bs[s][r * PAD + lk]) = rb[i];
        }
    };

    float acc[4][4][4];
#pragma unroll
    for (int i = 0; i < 4; i++)
#pragma unroll
        for (int j = 0; j < 4; j++)
#pragma unroll
            for (int r = 0; r < 4; r++) acc[i][j][r] = 0.f;

    loadA(0); loadB(0);
    stage(0);
    __syncthreads();

    const int T = K / BKT;
    for (int t = 0; t < T; t++) {
        if (t + 1 < T) { loadA((t + 1) * BKT); loadB((t + 1) * BKT); }
        const int s = t & 1;

#pragma unroll
        for (int kk = 0; kk < 2; kk++) {
            const int ks = kk * 8;
            uint32_t a[4][4], bfr[2][4];

            const int arow = (lane < 16 ? lane : lane - 16);
            const int acol = ks + (lane < 16 ? 0 : 4);
#pragma unroll
            for (int mt = 0; mt < 4; mt++)
                ldsm4(a[mt][0], a[mt][1], a[mt][2], a[mt][3],
                      &As[s][(wm + mt * 16 + arow) * PAD + acol]);

            const int brow = (lane & 7) + (lane >= 16 ? 8 : 0);
            const int bcol = ks + ((lane & 8) ? 4 : 0);
#pragma unroll
            for (int np = 0; np < 2; np++)
                ldsm4(bfr[np][0], bfr[np][1], bfr[np][2], bfr[np][3],
                      &Bs[s][(wn + np * 16 + brow) * PAD + bcol]);

#pragma unroll
            for (int mt = 0; mt < 4; mt++)
#pragma unroll
                for (int nt = 0; nt < 4; nt++)
                    mma8(acc[mt][nt], a[mt],
                         bfr[nt >> 1][(nt & 1) * 2], bfr[nt >> 1][(nt & 1) * 2 + 1]);
        }

        if (t + 1 < T) {
            stage(s ^ 1);
            __syncthreads();
        }
    }

    // epilogue
    const int g = lane >> 2, tg = lane & 3;
#pragma unroll
    for (int mt = 0; mt < 4; mt++) {
#pragma unroll
        for (int nt = 0; nt < 4; nt++) {
            int row = m0 + wm + mt * 16 + g;
            int col = n0 + wn + nt * 8 + tg * 2;
            float bv0 = 0.f, bv1 = 0.f;
            if (bias) { bv0 = bias[col]; bv1 = bias[col + 1]; }
#pragma unroll
            for (int h = 0; h < 2; h++) {
                long ci = (long)(row + h * 8) * N + col;
                float v0 = acc[mt][nt][2 * h] + bv0;
                float v1 = acc[mt][nt][2 * h + 1] + bv1;
                if (do_relu) { v0 = fmaxf(v0, 0.f); v1 = fmaxf(v1, 0.f); }
                if (round_out) { v0 = tf32rnaf(v0); v1 = tf32rnaf(v1); }
                *reinterpret_cast<float2*>(C + ci) = make_float2(v0, v1);
            }
        }
    }
}

// ---------------- elementwise tf32 rounding copy -----------------------------
__global__ __launch_bounds__(256) void round_copy_k(const float* __restrict__ in,
                                                    float* __restrict__ out, long n)
{
    long i = ((long)blockIdx.x * 256 + threadIdx.x) * 4;
    if (i < n) {
        float4 v = *reinterpret_cast<const float4*>(in + i);
        v.x = tf32rnaf(v.x); v.y = tf32rnaf(v.y);
        v.z = tf32rnaf(v.z); v.w = tf32rnaf(v.w);
        *reinterpret_cast<float4*>(out + i) = v;
    }
}

// ---------------- tiled transpose (writes tf32-rounded) ----------------------
__global__ __launch_bounds__(256) void transpose_k(const float* __restrict__ in,
                                                   float* __restrict__ out,
                                                   int R, int C, long ibs, long obs)
{
    __shared__ float tile[32][33];
    in += (long)blockIdx.z * ibs;
    out += (long)blockIdx.z * obs;
    int c0 = blockIdx.x * 32, r0 = blockIdx.y * 32;
#pragma unroll
    for (int j = 0; j < 32; j += 8)
        tile[threadIdx.y + j][threadIdx.x] =
            tf32rnaf(in[(long)(r0 + threadIdx.y + j) * C + c0 + threadIdx.x]);
    __syncthreads();
#pragma unroll
    for (int j = 0; j < 32; j += 8)
        out[(long)(c0 + threadIdx.y + j) * R + r0 + threadIdx.x] =
            tile[threadIdx.x][threadIdx.y + j];
}

// ---------------- alpha: softmax over Le, in-place, rounded output -----------
__global__ __launch_bounds__(256) void alpha_kernel(float* __restrict__ align,
                                                    const int* __restrict__ em)
{
    int b = blockIdx.x / LCDIM;
    long base = (long)blockIdx.x * LEDIM;
    int t = threadIdx.x;

    float v[4];
    float mx = -3.4e38f;
#pragma unroll
    for (int i = 0; i < 4; i++) {
        int e = t + i * 256;
        float x = align[base + e];
        if (em[b * LEDIM + e] == 0) x += NEGV;
        v[i] = x;
        mx = fmaxf(mx, x);
    }
    __shared__ float red[256];
    red[t] = mx; __syncthreads();
    for (int s = 128; s > 0; s >>= 1) { if (t < s) red[t] = fmaxf(red[t], red[t + s]); __syncthreads(); }
    mx = red[0]; __syncthreads();

    float sm = 0.f;
#pragma unroll
    for (int i = 0; i < 4; i++) { v[i] = __expf(v[i] - mx); sm += v[i]; }
    red[t] = sm; __syncthreads();
    for (int s = 128; s > 0; s >>= 1) { if (t < s) red[t] += red[t + s]; __syncthreads(); }
    float inv = 1.f / red[0];

#pragma unroll
    for (int i = 0; i < 4; i++)
        align[base + t + i * 256] = tf32rnaf(v[i] * inv);
}

// ---------------- beta: online column stats (1 read pass) --------------------
__global__ __launch_bounds__(256) void colstats_kernel(const float* __restrict__ align,
                                                       const int* __restrict__ cm,
                                                       float* __restrict__ mxo,
                                                       float* __restrict__ invo)
{
    int b = blockIdx.x / (LEDIM / 256);
    int e = (blockIdx.x % (LEDIM / 256)) * 256 + threadIdx.x;

    __shared__ float negs[LCDIM];
    for (int l = threadIdx.x; l < LCDIM; l += 256)
        negs[l] = cm[b * LCDIM + l] ? 0.f : NEGV;
    __syncthreads();

    const float* col = align + (long)b * LCDIM * LEDIM + e;
    float m = -3.4e38f, s = 0.f;
#pragma unroll 4
    for (int l = 0; l < LCDIM; l++) {
        float x = col[(long)l * LEDIM] + negs[l];
        float nm = fmaxf(m, x);
        s = s * __expf(m - nm) + __expf(x - nm);
        m = nm;
    }
    mxo[b * LEDIM + e] = m;
    invo[b * LEDIM + e] = 1.f / s;
}

// ---------------- beta write: softmax-normalize + transpose, rounded ---------
__global__ void betaT_kernel(const float* __restrict__ align,
                             float* __restrict__ betaT,
                             const int* __restrict__ cm,
                             const float* __restrict__ mx,
                             const float* __restrict__ inv)
{
    int b = blockIdx.z;
    int e0 = blockIdx.x * 32, l0 = blockIdx.y * 32;
    __shared__ float tile[32][33];
    const float* al = align + (long)b * LCDIM * LEDIM;
#pragma unroll
    for (int j = 0; j < 32; j += 8) {
        int l = l0 + threadIdx.y + j, e = e0 + threadIdx.x;
        float neg = cm[b * LCDIM + l] ? 0.f : NEGV;
        tile[threadIdx.y + j][threadIdx.x] = tf32rnaf(
            __expf(al[(long)l * LEDIM + e] + neg - mx[b * LEDIM + e]) * inv[b * LEDIM + e]);
    }
    __syncthreads();
    float* out = betaT + (long)b * LCDIM * LEDIM;
#pragma unroll
    for (int j = 0; j < 32; j += 8)
        out[(long)(e0 + threadIdx.y + j) * LCDIM + l0 + threadIdx.x] =
            tile[threadIdx.x][threadIdx.y + j];
}

// ---------------- segment-sum over L into 4 partials per batch ---------------
__global__ __launch_bounds__(256) void reduce_kernel(const float* __restrict__ tmp,
                                                     float* __restrict__ part, int Lvar)
{
    int b = blockIdx.x, s = blockIdx.y, n = threadIdx.x;
    int chunk = Lvar / 4;
    const float* p = tmp + ((long)b * Lvar + (long)s * chunk) * DDIM + n;
    float acc = 0.f;
#pragma unroll 8
    for (int l = 0; l < chunk; l++) acc += p[(long)l * DDIM];
    part[(b * 4 + s) * DDIM + n] = acc;
}

// ---------------- final MLP --------------------------------------------------
__global__ __launch_bounds__(512) void final_kernel(
    const float* __restrict__ r1p, const float* __restrict__ r2p,
    const float* __restrict__ Wm, const float* __restrict__ bm,
    const float* __restrict__ Wo, const float* __restrict__ bo,
    float* __restrict__ out)
{
    int b = blockIdx.x;
    int t = threadIdx.x;

    __shared__ float ms[4 * DDIM];
    __shared__ float hs[MMDIM];

    if (t < DDIM) {
        float r1 = 0.f, r2 = 0.f;
#pragma unroll
        for (int s = 0; s < 4; s++) {
            r1 += r1p[(b * 4 + s) * DDIM + t];
            r2 += r2p[(b * 4 + s) * DDIM + t];
        }
        ms[t] = r1;
        ms[DDIM + t] = r2;
        ms[2 * DDIM + t] = r1 * r2;
        ms[3 * DDIM + t] = r1 - r2;
    }
    __syncthreads();

    float acc = bm[t];
#pragma unroll 8
    for (int k = 0; k < 4 * DDIM; k++) acc += ms[k] * Wm[(long)k * MMDIM + t];
    hs[t] = fmaxf(acc, 0.f);
    __syncthreads();

    int w = t >> 5, lane = t & 31;
    if (w < 3) {
        float s = 0.f;
        for (int j = lane; j < MMDIM; j += 32) s += hs[j] * Wo[j * 3 + w];
#pragma unroll
        for (int off = 16; off; off >>= 1) s += __shfl_down_sync(0xffffffffu, s, off);
        if (lane == 0) out[b * 3 + w] = s + bo[w];
    }
}

// ---------------- launch -----------------------------------------------------
extern "C" void kernel_launch(void* const* d_in, const int* in_sizes, int n_in,
                              void* d_out, int out_size)
{
    const float *criteria, *ehr, *Wa, *ba, *Wr, *br, *Wm, *bm, *Wo, *bo;
    const int *cmask, *emask;

    if (in_sizes[2] == BB * LCDIM) {
        criteria = (const float*)d_in[0]; ehr = (const float*)d_in[1];
        cmask = (const int*)d_in[2]; emask = (const int*)d_in[3];
        Wa = (const float*)d_in[4]; ba = (const float*)d_in[5];
        Wr = (const float*)d_in[6]; br = (const float*)d_in[7];
        Wm = (const float*)d_in[8]; bm = (const float*)d_in[9];
        Wo = (const float*)d_in[10]; bo = (const float*)d_in[11];
    } else {
        criteria = (const float*)d_in[0]; ehr = (const float*)d_in[1];
        Wa = (const float*)d_in[2]; ba = (const float*)d_in[3];
        Wr = (const float*)d_in[4]; br = (const float*)d_in[5];
        Wm = (const float*)d_in[6]; bm = (const float*)d_in[7];
        Wo = (const float*)d_in[8]; bo = (const float*)d_in[9];
        cmask = (const int*)d_in[10]; emask = (const int*)d_in[11];
    }

    float *c, *e, *al, *beT, *attc, *atte, *ehrT, *critT, *ehrR, *critR;
    float *WaT, *WrT, *r1p, *r2p, *cmx, *cinv;
    cudaGetSymbolAddress((void**)&c,     g_c);
    cudaGetSymbolAddress((void**)&e,     g_e);
    cudaGetSymbolAddress((void**)&al,    g_align);
    cudaGetSymbolAddress((void**)&beT,   g_betaT);
    cudaGetSymbolAddress((void**)&attc,  g_attc);
    cudaGetSymbolAddress((void**)&atte,  g_atte);
    cudaGetSymbolAddress((void**)&ehrT,  g_ehrT);
    cudaGetSymbolAddress((void**)&critT, g_critT);
    cudaGetSymbolAddress((void**)&ehrR,  g_ehrR);
    cudaGetSymbolAddress((void**)&critR, g_critR);
    cudaGetSymbolAddress((void**)&WaT,   g_WaT);
    cudaGetSymbolAddress((void**)&WrT,   g_WrT);
    cudaGetSymbolAddress((void**)&r1p,   g_r1p);
    cudaGetSymbolAddress((void**)&r2p,   g_r2p);
    cudaGetSymbolAddress((void**)&cmx,   g_cmx);
    cudaGetSymbolAddress((void**)&cinv,  g_cinv);

    const long LCD = (long)LCDIM * DDIM;   // 65536
    const long LED = (long)LEDIM * DDIM;   // 262144
    const long LCE = (long)LCDIM * LEDIM;  // 262144

    dim3 tb(32, 8);

    // pre-round inputs (row-major copies) + rounded transposes
    round_copy_k<<<(BB * LCD / 4 + 255) / 256, 256>>>(criteria, critR, BB * LCD);
    round_copy_k<<<(BB * LED / 4 + 255) / 256, 256>>>(ehr, ehrR, BB * LED);
    transpose_k<<<dim3(8, 8, 1),  tb>>>(Wa, WaT, DDIM, DDIM, 0, 0);
    transpose_k<<<dim3(8, 16, 1), tb>>>(Wr, WrT, 2 * DDIM, DDIM, 0, 0);
    transpose_k<<<dim3(8, 32, BB), tb>>>(ehr, ehrT, LEDIM, DDIM, LED, LED);
    transpose_k<<<dim3(8, 8, BB),  tb>>>(criteria, critT, LCDIM, DDIM, LCD, LCD);

    // c = relu(criteria @ Wa + ba), rounded output (feeds align GEMM)
    gemm_tc<<<dim3(DDIM / BN, (BB * LCDIM) / BM, 1), 256>>>(
        critR, nullptr, 0, WaT, ba, c, BB * LCDIM, DDIM, DDIM,
        DDIM, 0, DDIM, 0, 0, 1, 1);

    // e = relu(ehr @ Wa + ba), rounded output
    gemm_tc<<<dim3(DDIM / BN, (BB * LEDIM) / BM, 1), 256>>>(
        ehrR, nullptr, 0, WaT, ba, e, BB * LEDIM, DDIM, DDIM,
        DDIM, 0, DDIM, 0, 0, 1, 1);

    // align[b] = c[b] @ e[b]^T (fp32 output, feeds softmax)
    gemm_tc<<<dim3(LEDIM / BN, LCDIM / BM, BB), 256>>>(
        c, nullptr, 0, e, nullptr, al, LCDIM, LEDIM, DDIM,
        DDIM, LCD, DDIM, LED, LCE, 0, 0);

    // beta stats + transposed rounded write (before alpha clobbers align)
    colstats_kernel<<<BB * (LEDIM / 256), 256>>>(al, cmask, cmx, cinv);
    betaT_kernel<<<dim3(LEDIM / 32, LCDIM / 32, BB), tb>>>(al, beT, cmask, cmx, cinv);

    // alpha in-place (rounded write)
    alpha_kernel<<<BB * LCDIM, 256>>>(al, emask);

    // att_c[b] = alpha[b] @ ehr[b], rounded output (feeds r1 GEMM)
    gemm_tc<<<dim3(DDIM / BN, LCDIM / BM, BB), 256>>>(
        al, nullptr, 0, ehrT, nullptr, attc, LCDIM, DDIM, LEDIM,
        LEDIM, LCE, LEDIM, LED, LCD, 0, 1);

    // att_e[b] = beta[b]^T @ criteria[b], rounded output
    gemm_tc<<<dim3(DDIM / BN, LEDIM / BM, BB), 256>>>(
        beT, nullptr, 0, critT, nullptr, atte, LEDIM, DDIM, LCDIM,
        LCDIM, LCE, LCDIM, LCD, LED, 0, 1);

    // r1-pre (reuse g_c) = relu([attc, criteria] @ Wr + br), fp32 out
    gemm_tc<<<dim3(DDIM / BN, (BB * LCDIM) / BM, 1), 256>>>(
        attc, critR, DDIM, WrT, br, c, BB * LCDIM, DDIM, 2 * DDIM,
        DDIM, 0, 2 * DDIM, 0, 0, 1, 0);

    // r2-pre (reuse g_e) = relu([atte, ehr] @ Wr + br), fp32 out
    gemm_tc<<<dim3(DDIM / BN, (BB * LEDIM) / BM, 1), 256>>>(
        atte, ehrR, DDIM, WrT, br, e, BB * LEDIM, DDIM, 2 * DDIM,
        DDIM, 0, 2 * DDIM, 0, 0, 1, 0);

    // r1/r2 partial sums
    reduce_kernel<<<dim3(BB, 4), 256>>>(c, r1p, LCDIM);
    reduce_kernel<<<dim3(BB, 4), 256>>>(e, r2p, LEDIM);

    final_kernel<<<BB, 512>>>(r1p, r2p, Wm, bm, Wo, bo, (float*)d_out);
}

// round 7
// speedup vs baseline: 1.7096x; 1.7096x over previous
#include <cuda_runtime.h>
#include <cuda_fp16.h>
#include <cstdint>

#define BB 128
#define LCDIM 256
#define LEDIM 1024
#define DDIM 256
#define MMDIM 512
#define NEGV -1e9f

// ---------------- scratch ----------------------------------------------------
__device__ __align__(16) __half g_critH[(size_t)BB * LCDIM * DDIM];
__device__ __align__(16) __half g_ehrH[(size_t)BB * LEDIM * DDIM];
__device__ __align__(16) __half g_cH[(size_t)BB * LCDIM * DDIM];
__device__ __align__(16) __half g_eH[(size_t)BB * LEDIM * DDIM];
__device__ __align__(16) __half g_alphaH[(size_t)BB * LCDIM * LEDIM];
__device__ __align__(16) __half g_beTH[(size_t)BB * LCDIM * LEDIM];
__device__ __align__(16) __half g_ehrTH[(size_t)BB * LEDIM * DDIM];
__device__ __align__(16) __half g_critTH[(size_t)BB * LCDIM * DDIM];
__device__ __align__(16) __half g_attcH[(size_t)BB * LCDIM * DDIM];
__device__ __align__(16) __half g_atteH[(size_t)BB * LEDIM * DDIM];
__device__ __align__(16) __half g_WaTH[DDIM * DDIM];
__device__ __align__(16) __half g_WrTH[DDIM * 2 * DDIM];
__device__ float g_align[(size_t)BB * LCDIM * LEDIM];  // align; later r2-pre
__device__ float g_r1pre[(size_t)BB * LCDIM * DDIM];
__device__ float g_r1p[BB * 4 * DDIM];
__device__ float g_r2p[BB * 4 * DDIM];
__device__ float g_cmx[BB * LEDIM];
__device__ float g_cinv[BB * LEDIM];

// ---------------- helpers -----------------------------------------------------
__device__ __forceinline__ uint32_t smem_u32(const void* p) {
    uint32_t a;
    asm("{ .reg .u64 t; cvta.to.shared.u64 t, %1; cvt.u32.u64 %0, t; }"
        : "=r"(a) : "l"(p));
    return a;
}

#define SW128B(o) ((o) ^ (((o) >> 3) & 0x70))

__device__ __forceinline__ void ldsm4h(uint32_t& r0, uint32_t& r1, uint32_t& r2,
                                       uint32_t& r3, uint32_t addr) {
    asm volatile("ldmatrix.sync.aligned.m8n8.x4.shared.b16 {%0,%1,%2,%3}, [%4];"
                 : "=r"(r0), "=r"(r1), "=r"(r2), "=r"(r3) : "r"(addr));
}

__device__ __forceinline__ void mma16(float* c, const uint32_t* a, uint32_t b0, uint32_t b1) {
    asm volatile(
        "mma.sync.aligned.m16n8k16.row.col.f32.f16.f16.f32 "
        "{%0,%1,%2,%3}, {%4,%5,%6,%7}, {%8,%9}, {%0,%1,%2,%3};"
        : "+f"(c[0]), "+f"(c[1]), "+f"(c[2]), "+f"(c[3])
        : "r"(a[0]), "r"(a[1]), "r"(a[2]), "r"(a[3]), "r"(b0), "r"(b1));
}

#define CP16(d, g) \
    asm volatile("cp.async.cg.shared.global [%0], [%1], 16;" :: "r"(d), "l"(g))

// ---------------- FP16 tensor-core GEMM ---------------------------------------
// C[M,N] row-major = epi(A@B). A fp16 [m][k] k-contig (A + m*sAm + k).
// B fp16 [n][k] k-contig (B + n*sBn + k). A2: k >= Ksplit (fused concat).
// fp32 accumulate; output fp32 or fp16 (out_half). K-chunk 64, SW128 tiles,
// cp.async double buffering.
#define BM 128
#define BN 128
#define BKH 64
#define SA_OFF(s) ((s) * 16384)
#define SB_OFF(s) (32768 + (s) * 16384)
#define GSM_TOTAL 65536

__global__ __launch_bounds__(256, 2) void gemm_h(
    const __half* __restrict__ A, const __half* __restrict__ A2, int Ksplit,
    const __half* __restrict__ B, const float* __restrict__ bias,
    void* __restrict__ Cv,
    int M, int N, int K,
    long sAm, long bsA, long sBn, long bsB, long bsC,
    int do_relu, int out_half)
{
    extern __shared__ char sm[];
    A += (long)blockIdx.z * bsA;
    if (A2) A2 += (long)blockIdx.z * bsA;
    B += (long)blockIdx.z * bsB;

    const int tid = threadIdx.x;
    const int lane = tid & 31;
    const int w = tid >> 5;
    const int wm = (w & 1) * 64;
    const int wn = (w >> 1) * 32;
    const int m0 = blockIdx.y * BM;
    const int n0 = blockIdx.x * BN;
    const uint32_t sb = smem_u32(sm);

    auto issueA = [&](int k0, int s) {
        const __half* Ap = A; int kb = k0;
        if (A2 && k0 >= Ksplit) { Ap = A2; kb = k0 - Ksplit; }
        uint32_t base = sb + SA_OFF(s);
#pragma unroll
        for (int i = 0; i < 4; i++) {
            int f = tid + i * 256;            // 1024 x 16B: 128 rows x 8 chunks
            int row = f >> 3, hq = (f & 7) * 8;
            CP16(base + SW128B(row * 128 + hq * 2),
                 Ap + (long)(m0 + row) * sAm + kb + hq);
        }
    };
    auto issueB = [&](int k0, int s) {
        uint32_t base = sb + SB_OFF(s);
#pragma unroll
        for (int i = 0; i < 4; i++) {
            int f = tid + i * 256;
            int row = f >> 3, hq = (f & 7) * 8;
            CP16(base + SW128B(row * 128 + hq * 2),
                 B + (long)(n0 + row) * sBn + k0 + hq);
        }
    };

    float acc[4][4][4];
#pragma unroll
    for (int i = 0; i < 4; i++)
#pragma unroll
        for (int j = 0; j < 4; j++)
#pragma unroll
            for (int r = 0; r < 4; r++) acc[i][j][r] = 0.f;

    issueA(0, 0); issueB(0, 0);
    asm volatile("cp.async.commit_group;" ::: "memory");

    const int T = K / BKH;
    for (int t = 0; t < T; t++) {
        const int s = t & 1;
        asm volatile("cp.async.wait_group 0;" ::: "memory");
        __syncthreads();
        if (t + 1 < T) {
            issueA((t + 1) * BKH, s ^ 1);
            issueB((t + 1) * BKH, s ^ 1);
            asm volatile("cp.async.commit_group;" ::: "memory");
        }

        const uint32_t abase = sb + SA_OFF(s);
        const uint32_t bbase = sb + SB_OFF(s);
#pragma unroll
        for (int ks = 0; ks < 4; ks++) {
            uint32_t a[4][4], bf[2][4];

            const int arow = lane & 15;
            const int acolh = ks * 16 + (lane >> 4) * 8;
#pragma unroll
            for (int mt = 0; mt < 4; mt++)
                ldsm4h(a[mt][0], a[mt][1], a[mt][2], a[mt][3],
                       abase + SW128B((wm + mt * 16 + arow) * 128 + acolh * 2));

            const int brow = (lane & 7) + (lane >= 16 ? 8 : 0);
            const int bcolh = ks * 16 + ((lane >> 3) & 1) * 8;
#pragma unroll
            for (int np = 0; np < 2; np++)
                ldsm4h(bf[np][0], bf[np][1], bf[np][2], bf[np][3],
                       bbase + SW128B((wn + np * 16 + brow) * 128 + bcolh * 2));

#pragma unroll
            for (int mt = 0; mt < 4; mt++)
#pragma unroll
                for (int nt = 0; nt < 4; nt++)
                    mma16(acc[mt][nt], a[mt],
                          bf[nt >> 1][(nt & 1) * 2], bf[nt >> 1][(nt & 1) * 2 + 1]);
        }
    }

    // epilogue (register -> global, no smem)
    const int g = lane >> 2, tg = lane & 3;
#pragma unroll
    for (int mt = 0; mt < 4; mt++) {
#pragma unroll
        for (int nt = 0; nt < 4; nt++) {
            int row = m0 + wm + mt * 16 + g;
            int col = n0 + wn + nt * 8 + tg * 2;
            float bv0 = 0.f, bv1 = 0.f;
            if (bias) { bv0 = bias[col]; bv1 = bias[col + 1]; }
#pragma unroll
            for (int h = 0; h < 2; h++) {
                long ci = (long)(row + h * 8) * N + col + (long)blockIdx.z * bsC;
                float v0 = acc[mt][nt][2 * h] + bv0;
                float v1 = acc[mt][nt][2 * h + 1] + bv1;
                if (do_relu) { v0 = fmaxf(v0, 0.f); v1 = fmaxf(v1, 0.f); }
                if (out_half) {
                    __half2 hv = __floats2half2_rn(v0, v1);
                    *reinterpret_cast<__half2*>((__half*)Cv + ci) = hv;
                } else {
                    *reinterpret_cast<float2*>((float*)Cv + ci) = make_float2(v0, v1);
                }
            }
        }
    }
}

// ---------------- fp32 -> fp16 copy -------------------------------------------
__global__ __launch_bounds__(256) void tohalf_k(const float* __restrict__ in,
                                                __half* __restrict__ out, long n)
{
    long i = ((long)blockIdx.x * 256 + threadIdx.x) * 8;
    if (i < n) {
        float4 a = *reinterpret_cast<const float4*>(in + i);
        float4 b = *reinterpret_cast<const float4*>(in + i + 4);
        __half2 h0 = __floats2half2_rn(a.x, a.y);
        __half2 h1 = __floats2half2_rn(a.z, a.w);
        __half2 h2 = __floats2half2_rn(b.x, b.y);
        __half2 h3 = __floats2half2_rn(b.z, b.w);
        uint4 u;
        u.x = *reinterpret_cast<uint32_t*>(&h0);
        u.y = *reinterpret_cast<uint32_t*>(&h1);
        u.z = *reinterpret_cast<uint32_t*>(&h2);
        u.w = *reinterpret_cast<uint32_t*>(&h3);
        *reinterpret_cast<uint4*>(out + i) = u;
    }
}

// ---------------- tiled transpose fp32 -> fp16 --------------------------------
__global__ __launch_bounds__(256) void transpose_h(const float* __restrict__ in,
                                                   __half* __restrict__ out,
                                                   int R, int C, long ibs, long obs)
{
    __shared__ float tile[32][33];
    in += (long)blockIdx.z * ibs;
    out += (long)blockIdx.z * obs;
    int c0 = blockIdx.x * 32, r0 = blockIdx.y * 32;
#pragma unroll
    for (int j = 0; j < 32; j += 8)
        tile[threadIdx.y + j][threadIdx.x] =
            in[(long)(r0 + threadIdx.y + j) * C + c0 + threadIdx.x];
    __syncthreads();
#pragma unroll
    for (int j = 0; j < 32; j += 8)
        out[(long)(c0 + threadIdx.y + j) * R + r0 + threadIdx.x] =
            __float2half_rn(tile[threadIdx.x][threadIdx.y + j]);
}

// ---------------- alpha: softmax over Le, fp16 output -------------------------
__global__ __launch_bounds__(256) void alpha_kernel(const float* __restrict__ align,
                                                    __half* __restrict__ alphaH,
                                                    const int* __restrict__ em)
{
    int b = blockIdx.x / LCDIM;
    long base = (long)blockIdx.x * LEDIM;
    int t = threadIdx.x;

    float v[4];
    float mx = -3.4e38f;
#pragma unroll
    for (int i = 0; i < 4; i++) {
        int e = t + i * 256;
        float x = align[base + e];
        if (em[b * LEDIM + e] == 0) x += NEGV;
        v[i] = x;
        mx = fmaxf(mx, x);
    }
    __shared__ float red[256];
    red[t] = mx; __syncthreads();
    for (int s = 128; s > 0; s >>= 1) { if (t < s) red[t] = fmaxf(red[t], red[t + s]); __syncthreads(); }
    mx = red[0]; __syncthreads();

    float sm = 0.f;
#pragma unroll
    for (int i = 0; i < 4; i++) { v[i] = __expf(v[i] - mx); sm += v[i]; }
    red[t] = sm; __syncthreads();
    for (int s = 128; s > 0; s >>= 1) { if (t < s) red[t] += red[t + s]; __syncthreads(); }
    float inv = 1.f / red[0];

#pragma unroll
    for (int i = 0; i < 4; i++)
        alphaH[base + t + i * 256] = __float2half_rn(v[i] * inv);
}

// ---------------- beta: online column stats -----------------------------------
__global__ __launch_bounds__(256) void colstats_kernel(const float* __restrict__ align,
                                                       const int* __restrict__ cm,
                                                       float* __restrict__ mxo,
                                                       float* __restrict__ invo)
{
    int b = blockIdx.x / (LEDIM / 256);
    int e = (blockIdx.x % (LEDIM / 256)) * 256 + threadIdx.x;

    __shared__ float negs[LCDIM];
    for (int l = threadIdx.x; l < LCDIM; l += 256)
        negs[l] = cm[b * LCDIM + l] ? 0.f : NEGV;
    __syncthreads();

    const float* col = align + (long)b * LCDIM * LEDIM + e;
    float m = -3.4e38f, s = 0.f;
#pragma unroll 4
    for (int l = 0; l < LCDIM; l++) {
        float x = col[(long)l * LEDIM] + negs[l];
        float nm = fmaxf(m, x);
        s = s * __expf(m - nm) + __expf(x - nm);
        m = nm;
    }
    mxo[b * LEDIM + e] = m;
    invo[b * LEDIM + e] = 1.f / s;
}

// ---------------- beta write: normalize + transpose, fp16 output --------------
__global__ void betaT_kernel(const float* __restrict__ align,
                             __half* __restrict__ betaT,
                             const int* __restrict__ cm,
                             const float* __restrict__ mx,
                             const float* __restrict__ inv)
{
    int b = blockIdx.z;
    int e0 = blockIdx.x * 32, l0 = blockIdx.y * 32;
    __shared__ float tile[32][33];
    const float* al = align + (long)b * LCDIM * LEDIM;
#pragma unroll
    for (int j = 0; j < 32; j += 8) {
        int l = l0 + threadIdx.y + j, e = e0 + threadIdx.x;
        float neg = cm[b * LCDIM + l] ? 0.f : NEGV;
        tile[threadIdx.y + j][threadIdx.x] =
            __expf(al[(long)l * LEDIM + e] + neg - mx[b * LEDIM + e]) * inv[b * LEDIM + e];
    }
    __syncthreads();
    __half* out = betaT + (long)b * LCDIM * LEDIM;
#pragma unroll
    for (int j = 0; j < 32; j += 8)
        out[(long)(e0 + threadIdx.y + j) * LCDIM + l0 + threadIdx.x] =
            __float2half_rn(tile[threadIdx.x][threadIdx.y + j]);
}

// ---------------- segment-sum over L into 4 partials per batch ----------------
__global__ __launch_bounds__(256) void reduce_kernel(const float* __restrict__ tmp,
                                                     float* __restrict__ part, int Lvar)
{
    int b = blockIdx.x, s = blockIdx.y, n = threadIdx.x;
    int chunk = Lvar / 4;
    const float* p = tmp + ((long)b * Lvar + (long)s * chunk) * DDIM + n;
    float acc = 0.f;
#pragma unroll 8
    for (int l = 0; l < chunk; l++) acc += p[(long)l * DDIM];
    part[(b * 4 + s) * DDIM + n] = acc;
}

// ---------------- final MLP ---------------------------------------------------
__global__ __launch_bounds__(512) void final_kernel(
    const float* __restrict__ r1p, const float* __restrict__ r2p,
    const float* __restrict__ Wm, const float* __restrict__ bm,
    const float* __restrict__ Wo, const float* __restrict__ bo,
    float* __restrict__ out)
{
    int b = blockIdx.x;
    int t = threadIdx.x;

    __shared__ float ms[4 * DDIM];
    __shared__ float hs[MMDIM];

    if (t < DDIM) {
        float r1 = 0.f, r2 = 0.f;
#pragma unroll
        for (int s = 0; s < 4; s++) {
            r1 += r1p[(b * 4 + s) * DDIM + t];
            r2 += r2p[(b * 4 + s) * DDIM + t];
        }
        ms[t] = r1;
        ms[DDIM + t] = r2;
        ms[2 * DDIM + t] = r1 * r2;
        ms[3 * DDIM + t] = r1 - r2;
    }
    __syncthreads();

    float acc = bm[t];
#pragma unroll 8
    for (int k = 0; k < 4 * DDIM; k++) acc += ms[k] * Wm[(long)k * MMDIM + t];
    hs[t] = fmaxf(acc, 0.f);
    __syncthreads();

    int w = t >> 5, lane = t & 31;
    if (w < 3) {
        float s = 0.f;
        for (int j = lane; j < MMDIM; j += 32) s += hs[j] * Wo[j * 3 + w];
#pragma unroll
        for (int off = 16; off; off >>= 1) s += __shfl_down_sync(0xffffffffu, s, off);
        if (lane == 0) out[b * 3 + w] = s + bo[w];
    }
}

// ---------------- launch ------------------------------------------------------
extern "C" void kernel_launch(void* const* d_in, const int* in_sizes, int n_in,
                              void* d_out, int out_size)
{
    const float *criteria, *ehr, *Wa, *ba, *Wr, *br, *Wm, *bm, *Wo, *bo;
    const int *cmask, *emask;

    if (in_sizes[2] == BB * LCDIM) {
        criteria = (const float*)d_in[0]; ehr = (const float*)d_in[1];
        cmask = (const int*)d_in[2]; emask = (const int*)d_in[3];
        Wa = (const float*)d_in[4]; ba = (const float*)d_in[5];
        Wr = (const float*)d_in[6]; br = (const float*)d_in[7];
        Wm = (const float*)d_in[8]; bm = (const float*)d_in[9];
        Wo = (const float*)d_in[10]; bo = (const float*)d_in[11];
    } else {
        criteria = (const float*)d_in[0]; ehr = (const float*)d_in[1];
        Wa = (const float*)d_in[2]; ba = (const float*)d_in[3];
        Wr = (const float*)d_in[4]; br = (const float*)d_in[5];
        Wm = (const float*)d_in[6]; bm = (const float*)d_in[7];
        Wo = (const float*)d_in[8]; bo = (const float*)d_in[9];
        cmask = (const int*)d_in[10]; emask = (const int*)d_in[11];
    }

    __half *critH, *ehrH, *cH, *eH, *alphaH, *beTH, *ehrTH, *critTH, *attcH, *atteH;
    __half *WaTH, *WrTH;
    float *al, *r1pre, *r1p, *r2p, *cmx, *cinv;
    cudaGetSymbolAddress((void**)&critH,  g_critH);
    cudaGetSymbolAddress((void**)&ehrH,   g_ehrH);
    cudaGetSymbolAddress((void**)&cH,     g_cH);
    cudaGetSymbolAddress((void**)&eH,     g_eH);
    cudaGetSymbolAddress((void**)&alphaH, g_alphaH);
    cudaGetSymbolAddress((void**)&beTH,   g_beTH);
    cudaGetSymbolAddress((void**)&ehrTH,  g_ehrTH);
    cudaGetSymbolAddress((void**)&critTH, g_critTH);
    cudaGetSymbolAddress((void**)&attcH,  g_attcH);
    cudaGetSymbolAddress((void**)&atteH,  g_atteH);
    cudaGetSymbolAddress((void**)&WaTH,   g_WaTH);
    cudaGetSymbolAddress((void**)&WrTH,   g_WrTH);
    cudaGetSymbolAddress((void**)&al,     g_align);
    cudaGetSymbolAddress((void**)&r1pre,  g_r1pre);
    cudaGetSymbolAddress((void**)&r1p,    g_r1p);
    cudaGetSymbolAddress((void**)&r2p,    g_r2p);
    cudaGetSymbolAddress((void**)&cmx,    g_cmx);
    cudaGetSymbolAddress((void**)&cinv,   g_cinv);

    cudaFuncSetAttribute(gemm_h, cudaFuncAttributeMaxDynamicSharedMemorySize,
                         GSM_TOTAL);

    const long LCD = (long)LCDIM * DDIM;   // 65536
    const long LED = (long)LEDIM * DDIM;   // 262144
    const long LCE = (long)LCDIM * LEDIM;  // 262144

    dim3 tb(32, 8);

    // quantize inputs to fp16 + fp16 transposes
    tohalf_k<<<(int)((BB * LCD / 8 + 255) / 256), 256>>>(criteria, critH, BB * LCD);
    tohalf_k<<<(int)((BB * LED / 8 + 255) / 256), 256>>>(ehr, ehrH, BB * LED);
    transpose_h<<<dim3(8, 8, 1),  tb>>>(Wa, WaTH, DDIM, DDIM, 0, 0);
    transpose_h<<<dim3(8, 16, 1), tb>>>(Wr, WrTH, 2 * DDIM, DDIM, 0, 0);
    transpose_h<<<dim3(8, 32, BB), tb>>>(ehr, ehrTH, LEDIM, DDIM, LED, LED);
    transpose_h<<<dim3(8, 8, BB),  tb>>>(criteria, critTH, LCDIM, DDIM, LCD, LCD);

    // c = relu(criteria @ Wa + ba) -> fp16
    gemm_h<<<dim3(DDIM / BN, (BB * LCDIM) / BM, 1), 256, GSM_TOTAL>>>(
        critH, nullptr, 0, WaTH, ba, cH, BB * LCDIM, DDIM, DDIM,
        DDIM, 0, DDIM, 0, 0, 1, 1);

    // e = relu(ehr @ Wa + ba) -> fp16
    gemm_h<<<dim3(DDIM / BN, (BB * LEDIM) / BM, 1), 256, GSM_TOTAL>>>(
        ehrH, nullptr, 0, WaTH, ba, eH, BB * LEDIM, DDIM, DDIM,
        DDIM, 0, DDIM, 0, 0, 1, 1);

    // align[b] = c[b] @ e[b]^T -> fp32
    gemm_h<<<dim3(LEDIM / BN, LCDIM / BM, BB), 256, GSM_TOTAL>>>(
        cH, nullptr, 0, eH, nullptr, al, LCDIM, LEDIM, DDIM,
        DDIM, LCD, DDIM, LED, LCE, 0, 0);

    // beta stats + transposed fp16 write; alpha fp16 write
    colstats_kernel<<<BB * (LEDIM / 256), 256>>>(al, cmask, cmx, cinv);
    betaT_kernel<<<dim3(LEDIM / 32, LCDIM / 32, BB), tb>>>(al, beTH, cmask, cmx, cinv);
    alpha_kernel<<<BB * LCDIM, 256>>>(al, alphaH, emask);

    // att_c[b] = alpha[b] @ ehr[b] -> fp16
    gemm_h<<<dim3(DDIM / BN, LCDIM / BM, BB), 256, GSM_TOTAL>>>(
        alphaH, nullptr, 0, ehrTH, nullptr, attcH, LCDIM, DDIM, LEDIM,
        LEDIM, LCE, LEDIM, LED, LCD, 0, 1);

    // att_e[b] = beta[b]^T @ criteria[b] -> fp16
    gemm_h<<<dim3(DDIM / BN, LEDIM / BM, BB), 256, GSM_TOTAL>>>(
        beTH, nullptr, 0, critTH, nullptr, atteH, LEDIM, DDIM, LCDIM,
        LCDIM, LCE, LCDIM, LCD, LED, 0, 1);

    // r1-pre = relu([attc, criteria] @ Wr + br) -> fp32
    gemm_h<<<dim3(DDIM / BN, (BB * LCDIM) / BM, 1), 256, GSM_TOTAL>>>(
        attcH, critH, DDIM, WrTH, br, r1pre, BB * LCDIM, DDIM, 2 * DDIM,
        DDIM, 0, 2 * DDIM, 0, 0, 1, 0);

    // r2-pre = relu([atte, ehr] @ Wr + br) -> fp32 (reuses align buffer)
    gemm_h<<<dim3(DDIM / BN, (BB * LEDIM) / BM, 1), 256, GSM_TOTAL>>>(
        atteH, ehrH, DDIM, WrTH, br, al, BB * LEDIM, DDIM, 2 * DDIM,
        DDIM, 0, 2 * DDIM, 0, 0, 1, 0);

    // r1/r2 partial sums
    reduce_kernel<<<dim3(BB, 4), 256>>>(r1pre, r1p, LCDIM);
    reduce_kernel<<<dim3(BB, 4), 256>>>(al, r2p, LEDIM);

    final_kernel<<<BB, 512>>>(r1p, r2p, Wm, bm, Wo, bo, (float*)d_out);
}

// round 8
// speedup vs baseline: 1.8859x; 1.1031x over previous
#include <cuda_runtime.h>
#include <cuda_fp16.h>
#include <cstdint>

#define BB 128
#define LCDIM 256
#define LEDIM 1024
#define DDIM 256
#define MMDIM 512
#define NEGV -1e9f

// ---------------- scratch ----------------------------------------------------
__device__ __align__(16) __half g_critH[(size_t)BB * LCDIM * DDIM];
__device__ __align__(16) __half g_ehrH[(size_t)BB * LEDIM * DDIM];
__device__ __align__(16) __half g_cH[(size_t)BB * LCDIM * DDIM];
__device__ __align__(16) __half g_eH[(size_t)BB * LEDIM * DDIM];
__device__ __align__(16) __half g_alphaH[(size_t)BB * LCDIM * LEDIM];
__device__ __align__(16) __half g_beTH[(size_t)BB * LCDIM * LEDIM];
__device__ __align__(16) __half g_ehrTH[(size_t)BB * LEDIM * DDIM];
__device__ __align__(16) __half g_critTH[(size_t)BB * LCDIM * DDIM];
__device__ __align__(16) __half g_attcH[(size_t)BB * LCDIM * DDIM];
__device__ __align__(16) __half g_atteH[(size_t)BB * LEDIM * DDIM];
__device__ __align__(16) __half g_WaTH[DDIM * DDIM];
__device__ __align__(16) __half g_WrTH[DDIM * 2 * DDIM];
__device__ float g_align[(size_t)BB * LCDIM * LEDIM];
__device__ float g_r1p[BB * 2 * DDIM];   // per-(row-tile, col) partials, Lc: 2 tiles
__device__ float g_r2p[BB * 8 * DDIM];   // Le: 8 tiles
__device__ float g_cmx[BB * LEDIM];
__device__ float g_cinv[BB * LEDIM];

// ---------------- helpers -----------------------------------------------------
__device__ __forceinline__ uint32_t smem_u32(const void* p) {
    uint32_t a;
    asm("{ .reg .u64 t; cvta.to.shared.u64 t, %1; cvt.u32.u64 %0, t; }"
        : "=r"(a) : "l"(p));
    return a;
}

#define SW128B(o) ((o) ^ (((o) >> 3) & 0x70))

__device__ __forceinline__ void ldsm4h(uint32_t& r0, uint32_t& r1, uint32_t& r2,
                                       uint32_t& r3, uint32_t addr) {
    asm volatile("ldmatrix.sync.aligned.m8n8.x4.shared.b16 {%0,%1,%2,%3}, [%4];"
                 : "=r"(r0), "=r"(r1), "=r"(r2), "=r"(r3) : "r"(addr));
}

__device__ __forceinline__ void mma16(float* c, const uint32_t* a, uint32_t b0, uint32_t b1) {
    asm volatile(
        "mma.sync.aligned.m16n8k16.row.col.f32.f16.f16.f32 "
        "{%0,%1,%2,%3}, {%4,%5,%6,%7}, {%8,%9}, {%0,%1,%2,%3};"
        : "+f"(c[0]), "+f"(c[1]), "+f"(c[2]), "+f"(c[3])
        : "r"(a[0]), "r"(a[1]), "r"(a[2]), "r"(a[3]), "r"(b0), "r"(b1));
}

#define CP16(d, g) \
    asm volatile("cp.async.cg.shared.global [%0], [%1], 16;" :: "r"(d), "l"(g))

// ---------------- FP16 tensor-core GEMM ---------------------------------------
// C[M,N] row-major = epi(A@B). A fp16 [m][k] k-contig; B fp16 [n][k] k-contig.
// A2: k >= Ksplit (fused concat). 3-stage cp.async pipeline, SW128 tiles.
// sum_out: instead of storing C rows, reduce over the 128-row tile and
// accumulate into partials[(m0/BM)*N + col] (2 atomics/address from one CTA
// -> deterministic by commutativity; buffer zeroed each launch).
#define BM 128
#define BN 128
#define BKH 64
#define SA_OFF(s) ((s) * 16384)
#define SB_OFF(s) (49152 + (s) * 16384)
#define GSM_TOTAL 98304

__global__ __launch_bounds__(256, 2) void gemm_h(
    const __half* __restrict__ A, const __half* __restrict__ A2, int Ksplit,
    const __half* __restrict__ B, const float* __restrict__ bias,
    void* __restrict__ Cv,
    int M, int N, int K,
    long sAm, long bsA, long sBn, long bsB, long bsC,
    int do_relu, int out_half, int sum_out)
{
    extern __shared__ char sm[];
    A += (long)blockIdx.z * bsA;
    if (A2) A2 += (long)blockIdx.z * bsA;
    B += (long)blockIdx.z * bsB;

    const int tid = threadIdx.x;
    const int lane = tid & 31;
    const int w = tid >> 5;
    const int wm = (w & 1) * 64;
    const int wn = (w >> 1) * 32;
    const int m0 = blockIdx.y * BM;
    const int n0 = blockIdx.x * BN;
    const uint32_t sb = smem_u32(sm);

    auto issueA = [&](int k0, int s) {
        const __half* Ap = A; int kb = k0;
        if (A2 && k0 >= Ksplit) { Ap = A2; kb = k0 - Ksplit; }
        uint32_t base = sb + SA_OFF(s);
#pragma unroll
        for (int i = 0; i < 4; i++) {
            int f = tid + i * 256;
            int row = f >> 3, hq = (f & 7) * 8;
            CP16(base + SW128B(row * 128 + hq * 2),
                 Ap + (long)(m0 + row) * sAm + kb + hq);
        }
    };
    auto issueB = [&](int k0, int s) {
        uint32_t base = sb + SB_OFF(s);
#pragma unroll
        for (int i = 0; i < 4; i++) {
            int f = tid + i * 256;
            int row = f >> 3, hq = (f & 7) * 8;
            CP16(base + SW128B(row * 128 + hq * 2),
                 B + (long)(n0 + row) * sBn + k0 + hq);
        }
    };

    float acc[4][4][4];
#pragma unroll
    for (int i = 0; i < 4; i++)
#pragma unroll
        for (int j = 0; j < 4; j++)
#pragma unroll
            for (int r = 0; r < 4; r++) acc[i][j][r] = 0.f;

    const int T = K / BKH;
    issueA(0, 0); issueB(0, 0);
    asm volatile("cp.async.commit_group;" ::: "memory");
    if (T > 1) {
        issueA(BKH, 1); issueB(BKH, 1);
        asm volatile("cp.async.commit_group;" ::: "memory");
    }

    for (int t = 0; t < T; t++) {
        const int s = t % 3;
        if (t == T - 1)
            asm volatile("cp.async.wait_group 0;" ::: "memory");
        else
            asm volatile("cp.async.wait_group 1;" ::: "memory");
        __syncthreads();
        if (t + 2 < T) {
            issueA((t + 2) * BKH, (t + 2) % 3);
            issueB((t + 2) * BKH, (t + 2) % 3);
            asm volatile("cp.async.commit_group;" ::: "memory");
        }

        const uint32_t abase = sb + SA_OFF(s);
        const uint32_t bbase = sb + SB_OFF(s);
#pragma unroll
        for (int ks = 0; ks < 4; ks++) {
            uint32_t a[4][4], bf[2][4];

            const int arow = lane & 15;
            const int acolh = ks * 16 + (lane >> 4) * 8;
#pragma unroll
            for (int mt = 0; mt < 4; mt++)
                ldsm4h(a[mt][0], a[mt][1], a[mt][2], a[mt][3],
                       abase + SW128B((wm + mt * 16 + arow) * 128 + acolh * 2));

            const int brow = (lane & 7) + (lane >= 16 ? 8 : 0);
            const int bcolh = ks * 16 + ((lane >> 3) & 1) * 8;
#pragma unroll
            for (int np = 0; np < 2; np++)
                ldsm4h(bf[np][0], bf[np][1], bf[np][2], bf[np][3],
                       bbase + SW128B((wn + np * 16 + brow) * 128 + bcolh * 2));

#pragma unroll
            for (int mt = 0; mt < 4; mt++)
#pragma unroll
                for (int nt = 0; nt < 4; nt++)
                    mma16(acc[mt][nt], a[mt],
                          bf[nt >> 1][(nt & 1) * 2], bf[nt >> 1][(nt & 1) * 2 + 1]);
        }
    }

    const int g = lane >> 2, tg = lane & 3;

    if (sum_out) {
        // reduce tile over rows, accumulate into partials[(m0/BM)*N + col]
        float* P = (float*)Cv + (long)(m0 / BM) * N;
#pragma unroll
        for (int nt = 0; nt < 4; nt++) {
            int col = n0 + wn + nt * 8 + tg * 2;
            float bv0 = bias ? bias[col] : 0.f;
            float bv1 = bias ? bias[col + 1] : 0.f;
            float s0 = 0.f, s1 = 0.f;
#pragma unroll
            for (int mt = 0; mt < 4; mt++)
#pragma unroll
                for (int h = 0; h < 2; h++) {
                    float v0 = acc[mt][nt][2 * h] + bv0;
                    float v1 = acc[mt][nt][2 * h + 1] + bv1;
                    if (do_relu) { v0 = fmaxf(v0, 0.f); v1 = fmaxf(v1, 0.f); }
                    s0 += v0; s1 += v1;
                }
#pragma unroll
            for (int off = 16; off >= 4; off >>= 1) {
                s0 += __shfl_xor_sync(0xffffffffu, s0, off);
                s1 += __shfl_xor_sync(0xffffffffu, s1, off);
            }
            if (g == 0) {
                atomicAdd(&P[col], s0);
                atomicAdd(&P[col + 1], s1);
            }
        }
        return;
    }

#pragma unroll
    for (int mt = 0; mt < 4; mt++) {
#pragma unroll
        for (int nt = 0; nt < 4; nt++) {
            int row = m0 + wm + mt * 16 + g;
            int col = n0 + wn + nt * 8 + tg * 2;
            float bv0 = 0.f, bv1 = 0.f;
            if (bias) { bv0 = bias[col]; bv1 = bias[col + 1]; }
#pragma unroll
            for (int h = 0; h < 2; h++) {
                long ci = (long)(row + h * 8) * N + col + (long)blockIdx.z * bsC;
                float v0 = acc[mt][nt][2 * h] + bv0;
                float v1 = acc[mt][nt][2 * h + 1] + bv1;
                if (do_relu) { v0 = fmaxf(v0, 0.f); v1 = fmaxf(v1, 0.f); }
                if (out_half) {
                    __half2 hv = __floats2half2_rn(v0, v1);
                    *reinterpret_cast<__half2*>((__half*)Cv + ci) = hv;
                } else {
                    *reinterpret_cast<float2*>((float*)Cv + ci) = make_float2(v0, v1);
                }
            }
        }
    }
}

// ---------------- zero partials ------------------------------------------------
__global__ __launch_bounds__(256) void zero2_k(float* __restrict__ a, int na,
                                               float* __restrict__ b, int nb)
{
    int i = blockIdx.x * 256 + threadIdx.x;
    if (i < na) a[i] = 0.f;
    if (i < nb) b[i] = 0.f;
}

// ---------------- prep: fp32 -> fp16 row-major + fp16 transposed ---------------
__global__ __launch_bounds__(256) void prep_k(const float* __restrict__ in,
                                              __half* __restrict__ outR,
                                              __half* __restrict__ outT,
                                              int R, int C, long bs)
{
    __shared__ float tile[32][33];
    in += (long)blockIdx.z * bs;
    outR += (long)blockIdx.z * bs;
    outT += (long)blockIdx.z * bs;
    int c0 = blockIdx.x * 32, r0 = blockIdx.y * 32;
#pragma unroll
    for (int j = 0; j < 32; j += 8) {
        float v = in[(long)(r0 + threadIdx.y + j) * C + c0 + threadIdx.x];
        tile[threadIdx.y + j][threadIdx.x] = v;
        outR[(long)(r0 + threadIdx.y + j) * C + c0 + threadIdx.x] = __float2half_rn(v);
    }
    __syncthreads();
#pragma unroll
    for (int j = 0; j < 32; j += 8)
        outT[(long)(c0 + threadIdx.y + j) * R + r0 + threadIdx.x] =
            __float2half_rn(tile[threadIdx.x][threadIdx.y + j]);
}

// ---------------- tiled transpose fp32 -> fp16 (weights) -----------------------
__global__ __launch_bounds__(256) void transpose_h(const float* __restrict__ in,
                                                   __half* __restrict__ out,
                                                   int R, int C, long ibs, long obs)
{
    __shared__ float tile[32][33];
    in += (long)blockIdx.z * ibs;
    out += (long)blockIdx.z * obs;
    int c0 = blockIdx.x * 32, r0 = blockIdx.y * 32;
#pragma unroll
    for (int j = 0; j < 32; j += 8)
        tile[threadIdx.y + j][threadIdx.x] =
            in[(long)(r0 + threadIdx.y + j) * C + c0 + threadIdx.x];
    __syncthreads();
#pragma unroll
    for (int j = 0; j < 32; j += 8)
        out[(long)(c0 + threadIdx.y + j) * R + r0 + threadIdx.x] =
            __float2half_rn(tile[threadIdx.x][threadIdx.y + j]);
}

// ---------------- alpha: softmax over Le, fp16 output --------------------------
__global__ __launch_bounds__(256) void alpha_kernel(const float* __restrict__ align,
                                                    __half* __restrict__ alphaH,
                                                    const int* __restrict__ em)
{
    int b = blockIdx.x / LCDIM;
    long base = (long)blockIdx.x * LEDIM;
    int t = threadIdx.x;

    float v[4];
    float mx = -3.4e38f;
#pragma unroll
    for (int i = 0; i < 4; i++) {
        int e = t + i * 256;
        float x = align[base + e];
        if (em[b * LEDIM + e] == 0) x += NEGV;
        v[i] = x;
        mx = fmaxf(mx, x);
    }
    __shared__ float red[256];
    red[t] = mx; __syncthreads();
    for (int s = 128; s > 0; s >>= 1) { if (t < s) red[t] = fmaxf(red[t], red[t + s]); __syncthreads(); }
    mx = red[0]; __syncthreads();

    float sm = 0.f;
#pragma unroll
    for (int i = 0; i < 4; i++) { v[i] = __expf(v[i] - mx); sm += v[i]; }
    red[t] = sm; __syncthreads();
    for (int s = 128; s > 0; s >>= 1) { if (t < s) red[t] += red[t + s]; __syncthreads(); }
    float inv = 1.f / red[0];

#pragma unroll
    for (int i = 0; i < 4; i++)
        alphaH[base + t + i * 256] = __float2half_rn(v[i] * inv);
}

// ---------------- beta: online column stats ------------------------------------
__global__ __launch_bounds__(256) void colstats_kernel(const float* __restrict__ align,
                                                       const int* __restrict__ cm,
                                                       float* __restrict__ mxo,
                                                       float* __restrict__ invo)
{
    int b = blockIdx.x / (LEDIM / 256);
    int e = (blockIdx.x % (LEDIM / 256)) * 256 + threadIdx.x;

    __shared__ float negs[LCDIM];
    for (int l = threadIdx.x; l < LCDIM; l += 256)
        negs[l] = cm[b * LCDIM + l] ? 0.f : NEGV;
    __syncthreads();

    const float* col = align + (long)b * LCDIM * LEDIM + e;
    float m = -3.4e38f, s = 0.f;
#pragma unroll 4
    for (int l = 0; l < LCDIM; l++) {
        float x = col[(long)l * LEDIM] + negs[l];
        float nm = fmaxf(m, x);
        s = s * __expf(m - nm) + __expf(x - nm);
        m = nm;
    }
    mxo[b * LEDIM + e] = m;
    invo[b * LEDIM + e] = 1.f / s;
}

// ---------------- beta write: normalize + transpose, fp16 output ---------------
__global__ void betaT_kernel(const float* __restrict__ align,
                             __half* __restrict__ betaT,
                             const int* __restrict__ cm,
                             const float* __restrict__ mx,
                             const float* __restrict__ inv)
{
    int b = blockIdx.z;
    int e0 = blockIdx.x * 32, l0 = blockIdx.y * 32;
    __shared__ float tile[32][33];
    const float* al = align + (long)b * LCDIM * LEDIM;
#pragma unroll
    for (int j = 0; j < 32; j += 8) {
        int l = l0 + threadIdx.y + j, e = e0 + threadIdx.x;
        float neg = cm[b * LCDIM + l] ? 0.f : NEGV;
        tile[threadIdx.y + j][threadIdx.x] =
            __expf(al[(long)l * LEDIM + e] + neg - mx[b * LEDIM + e]) * inv[b * LEDIM + e];
    }
    __syncthreads();
    __half* out = betaT + (long)b * LCDIM * LEDIM;
#pragma unroll
    for (int j = 0; j < 32; j += 8)
        out[(long)(e0 + threadIdx.y + j) * LCDIM + l0 + threadIdx.x] =
            __float2half_rn(tile[threadIdx.x][threadIdx.y + j]);
}

// ---------------- final MLP ----------------------------------------------------
__global__ __launch_bounds__(512) void final_kernel(
    const float* __restrict__ r1p, const float* __restrict__ r2p,
    const float* __restrict__ Wm, const float* __restrict__ bm,
    const float* __restrict__ Wo, const float* __restrict__ bo,
    float* __restrict__ out)
{
    int b = blockIdx.x;
    int t = threadIdx.x;

    __shared__ float ms[4 * DDIM];
    __shared__ float hs[MMDIM];

    if (t < DDIM) {
        float r1 = 0.f, r2 = 0.f;
#pragma unroll
        for (int s = 0; s < 2; s++) r1 += r1p[(b * 2 + s) * DDIM + t];
#pragma unroll
        for (int s = 0; s < 8; s++) r2 += r2p[(b * 8 + s) * DDIM + t];
        ms[t] = r1;
        ms[DDIM + t] = r2;
        ms[2 * DDIM + t] = r1 * r2;
        ms[3 * DDIM + t] = r1 - r2;
    }
    __syncthreads();

    float acc = bm[t];
#pragma unroll 8
    for (int k = 0; k < 4 * DDIM; k++) acc += ms[k] * Wm[(long)k * MMDIM + t];
    hs[t] = fmaxf(acc, 0.f);
    __syncthreads();

    int w = t >> 5, lane = t & 31;
    if (w < 3) {
        float s = 0.f;
        for (int j = lane; j < MMDIM; j += 32) s += hs[j] * Wo[j * 3 + w];
#pragma unroll
        for (int off = 16; off; off >>= 1) s += __shfl_down_sync(0xffffffffu, s, off);
        if (lane == 0) out[b * 3 + w] = s + bo[w];
    }
}

// ---------------- launch -------------------------------------------------------
extern "C" void kernel_launch(void* const* d_in, const int* in_sizes, int n_in,
                              void* d_out, int out_size)
{
    const float *criteria, *ehr, *Wa, *ba, *Wr, *br, *Wm, *bm, *Wo, *bo;
    const int *cmask, *emask;

    if (in_sizes[2] == BB * LCDIM) {
        criteria = (const float*)d_in[0]; ehr = (const float*)d_in[1];
        cmask = (const int*)d_in[2]; emask = (const int*)d_in[3];
        Wa = (const float*)d_in[4]; ba = (const float*)d_in[5];
        Wr = (const float*)d_in[6]; br = (const float*)d_in[7];
        Wm = (const float*)d_in[8]; bm = (const float*)d_in[9];
        Wo = (const float*)d_in[10]; bo = (const float*)d_in[11];
    } else {
        criteria = (const float*)d_in[0]; ehr = (const float*)d_in[1];
        Wa = (const float*)d_in[2]; ba = (const float*)d_in[3];
        Wr = (const float*)d_in[4]; br = (const float*)d_in[5];
        Wm = (const float*)d_in[6]; bm = (const float*)d_in[7];
        Wo = (const float*)d_in[8]; bo = (const float*)d_in[9];
        cmask = (const int*)d_in[10]; emask = (const int*)d_in[11];
    }

    __half *critH, *ehrH, *cH, *eH, *alphaH, *beTH, *ehrTH, *critTH, *attcH, *atteH;
    __half *WaTH, *WrTH;
    float *al, *r1p, *r2p, *cmx, *cinv;
    cudaGetSymbolAddress((void**)&critH,  g_critH);
    cudaGetSymbolAddress((void**)&ehrH,   g_ehrH);
    cudaGetSymbolAddress((void**)&cH,     g_cH);
    cudaGetSymbolAddress((void**)&eH,     g_eH);
    cudaGetSymbolAddress((void**)&alphaH, g_alphaH);
    cudaGetSymbolAddress((void**)&beTH,   g_beTH);
    cudaGetSymbolAddress((void**)&ehrTH,  g_ehrTH);
    cudaGetSymbolAddress((void**)&critTH, g_critTH);
    cudaGetSymbolAddress((void**)&attcH,  g_attcH);
    cudaGetSymbolAddress((void**)&atteH,  g_atteH);
    cudaGetSymbolAddress((void**)&WaTH,   g_WaTH);
    cudaGetSymbolAddress((void**)&WrTH,   g_WrTH);
    cudaGetSymbolAddress((void**)&al,     g_align);
    cudaGetSymbolAddress((void**)&r1p,    g_r1p);
    cudaGetSymbolAddress((void**)&r2p,    g_r2p);
    cudaGetSymbolAddress((void**)&cmx,    g_cmx);
    cudaGetSymbolAddress((void**)&cinv,   g_cinv);

    cudaFuncSetAttribute(gemm_h, cudaFuncAttributeMaxDynamicSharedMemorySize,
                         GSM_TOTAL);

    const long LCD = (long)LCDIM * DDIM;   // 65536
    const long LED = (long)LEDIM * DDIM;   // 262144
    const long LCE = (long)LCDIM * LEDIM;  // 262144

    dim3 tb(32, 8);

    // prologue: fp16 copies + transposes (single read per input), zero partials
    prep_k<<<dim3(8, 8, BB),  tb>>>(criteria, critH, critTH, LCDIM, DDIM, LCD);
    prep_k<<<dim3(8, 32, BB), tb>>>(ehr, ehrH, ehrTH, LEDIM, DDIM, LED);
    transpose_h<<<dim3(8, 8, 1),  tb>>>(Wa, WaTH, DDIM, DDIM, 0, 0);
    transpose_h<<<dim3(8, 16, 1), tb>>>(Wr, WrTH, 2 * DDIM, DDIM, 0, 0);
    zero2_k<<<1024, 256>>>(r1p, BB * 2 * DDIM, r2p, BB * 8 * DDIM);

    // c = relu(criteria @ Wa + ba) -> fp16
    gemm_h<<<dim3(DDIM / BN, (BB * LCDIM) / BM, 1), 256, GSM_TOTAL>>>(
        critH, nullptr, 0, WaTH, ba, cH, BB * LCDIM, DDIM, DDIM,
        DDIM, 0, DDIM, 0, 0, 1, 1, 0);

    // e = relu(ehr @ Wa + ba) -> fp16
    gemm_h<<<dim3(DDIM / BN, (BB * LEDIM) / BM, 1), 256, GSM_TOTAL>>>(
        ehrH, nullptr, 0, WaTH, ba, eH, BB * LEDIM, DDIM, DDIM,
        DDIM, 0, DDIM, 0, 0, 1, 1, 0);

    // align[b] = c[b] @ e[b]^T -> fp32
    gemm_h<<<dim3(LEDIM / BN, LCDIM / BM, BB), 256, GSM_TOTAL>>>(
        cH, nullptr, 0, eH, nullptr, al, LCDIM, LEDIM, DDIM,
        DDIM, LCD, DDIM, LED, LCE, 0, 0, 0);

    // beta stats + transposed fp16 write; alpha fp16 write
    colstats_kernel<<<BB * (LEDIM / 256), 256>>>(al, cmask, cmx, cinv);
    betaT_kernel<<<dim3(LEDIM / 32, LCDIM / 32, BB), tb>>>(al, beTH, cmask, cmx, cinv);
    alpha_kernel<<<BB * LCDIM, 256>>>(al, alphaH, emask);

    // att_c[b] = alpha[b] @ ehr[b] -> fp16
    gemm_h<<<dim3(DDIM / BN, LCDIM / BM, BB), 256, GSM_TOTAL>>>(
        alphaH, nullptr, 0, ehrTH, nullptr, attcH, LCDIM, DDIM, LEDIM,
        LEDIM, LCE, LEDIM, LED, LCD, 0, 1, 0);

    // att_e[b] = beta[b]^T @ criteria[b] -> fp16
    gemm_h<<<dim3(DDIM / BN, LEDIM / BM, BB), 256, GSM_TOTAL>>>(
        beTH, nullptr, 0, critTH, nullptr, atteH, LEDIM, DDIM, LCDIM,
        LCDIM, LCE, LCDIM, LCD, LED, 0, 1, 0);

    // r1 partials = rowsum(relu([attc, criteria] @ Wr + br)) (fused epilogue)
    gemm_h<<<dim3(DDIM / BN, (BB * LCDIM) / BM, 1), 256, GSM_TOTAL>>>(
        attcH, critH, DDIM, WrTH, br, r1p, BB * LCDIM, DDIM, 2 * DDIM,
        DDIM, 0, 2 * DDIM, 0, 0, 1, 0, 1);

    // r2 partials = rowsum(relu([atte, ehr] @ Wr + br))
    gemm_h<<<dim3(DDIM / BN, (BB * LEDIM) / BM, 1), 256, GSM_TOTAL>>>(
        atteH, ehrH, DDIM, WrTH, br, r2p, BB * LEDIM, DDIM, 2 * DDIM,
        DDIM, 0, 2 * DDIM, 0, 0, 1, 0, 1);

    final_kernel<<<BB, 512>>>(r1p, r2p, Wm, bm, Wo, bo, (float*)d_out);
}

// round 9
// speedup vs baseline: 1.9259x; 1.0212x over previous
#include <cuda_runtime.h>
#include <cuda_fp16.h>
#include <cstdint>

#define BB 128
#define LCDIM 256
#define LEDIM 1024
#define DDIM 256
#define MMDIM 512
#define NEGV -1e9f

// ---------------- scratch ----------------------------------------------------
__device__ __align__(16) __half g_critH[(size_t)BB * LCDIM * DDIM];
__device__ __align__(16) __half g_ehrH[(size_t)BB * LEDIM * DDIM];
__device__ __align__(16) __half g_cH[(size_t)BB * LCDIM * DDIM];
__device__ __align__(16) __half g_eH[(size_t)BB * LEDIM * DDIM];
__device__ __align__(16) __half g_alignH[(size_t)BB * LCDIM * LEDIM]; // fp16 logits
__device__ __align__(16) __half g_alphaH[(size_t)BB * LCDIM * LEDIM];
__device__ __align__(16) __half g_beTH[(size_t)BB * LCDIM * LEDIM];
__device__ __align__(16) __half g_ehrTH[(size_t)BB * LEDIM * DDIM];
__device__ __align__(16) __half g_critTH[(size_t)BB * LCDIM * DDIM];
__device__ __align__(16) __half g_attcH[(size_t)BB * LCDIM * DDIM];
__device__ __align__(16) __half g_atteH[(size_t)BB * LEDIM * DDIM];
__device__ __align__(16) __half g_WaTH[DDIM * DDIM];
__device__ __align__(16) __half g_WrTH[DDIM * 2 * DDIM];
__device__ float g_r1p[BB * 2 * DDIM];   // per-(row-tile, col) partials, Lc: 2 tiles
__device__ float g_r2p[BB * 8 * DDIM];   // Le: 8 tiles
__device__ float g_cmx[BB * LEDIM];
__device__ float g_cinv[BB * LEDIM];

// ---------------- helpers -----------------------------------------------------
__device__ __forceinline__ uint32_t smem_u32(const void* p) {
    uint32_t a;
    asm("{ .reg .u64 t; cvta.to.shared.u64 t, %1; cvt.u32.u64 %0, t; }"
        : "=r"(a) : "l"(p));
    return a;
}

#define SW128B(o) ((o) ^ (((o) >> 3) & 0x70))

__device__ __forceinline__ void ldsm4h(uint32_t& r0, uint32_t& r1, uint32_t& r2,
                                       uint32_t& r3, uint32_t addr) {
    asm volatile("ldmatrix.sync.aligned.m8n8.x4.shared.b16 {%0,%1,%2,%3}, [%4];"
                 : "=r"(r0), "=r"(r1), "=r"(r2), "=r"(r3) : "r"(addr));
}

__device__ __forceinline__ void mma16(float* c, const uint32_t* a, uint32_t b0, uint32_t b1) {
    asm volatile(
        "mma.sync.aligned.m16n8k16.row.col.f32.f16.f16.f32 "
        "{%0,%1,%2,%3}, {%4,%5,%6,%7}, {%8,%9}, {%0,%1,%2,%3};"
        : "+f"(c[0]), "+f"(c[1]), "+f"(c[2]), "+f"(c[3])
        : "r"(a[0]), "r"(a[1]), "r"(a[2]), "r"(a[3]), "r"(b0), "r"(b1));
}

#define CP16(d, g) \
    asm volatile("cp.async.cg.shared.global [%0], [%1], 16;" :: "r"(d), "l"(g))

// ---------------- FP16 tensor-core GEMM ---------------------------------------
// C[M,N] row-major = epi(A@B). A fp16 [m][k] k-contig; B fp16 [n][k] k-contig.
// A2: k >= Ksplit (fused concat). 3-stage cp.async pipeline, SW128 tiles.
// sum_out: reduce over the 128-row tile and accumulate into
// partials[(m0/BM)*N + col] (2 atomics/address from one CTA -> deterministic
// by commutativity; buffer zeroed each launch).
#define BM 128
#define BN 128
#define BKH 64
#define SA_OFF(s) ((s) * 16384)
#define SB_OFF(s) (49152 + (s) * 16384)
#define GSM_TOTAL 98304

__global__ __launch_bounds__(256, 2) void gemm_h(
    const __half* __restrict__ A, const __half* __restrict__ A2, int Ksplit,
    const __half* __restrict__ B, const float* __restrict__ bias,
    void* __restrict__ Cv,
    int M, int N, int K,
    long sAm, long bsA, long sBn, long bsB, long bsC,
    int do_relu, int out_half, int sum_out)
{
    extern __shared__ char sm[];
    A += (long)blockIdx.z * bsA;
    if (A2) A2 += (long)blockIdx.z * bsA;
    B += (long)blockIdx.z * bsB;

    const int tid = threadIdx.x;
    const int lane = tid & 31;
    const int w = tid >> 5;
    const int wm = (w & 1) * 64;
    const int wn = (w >> 1) * 32;
    const int m0 = blockIdx.y * BM;
    const int n0 = blockIdx.x * BN;
    const uint32_t sb = smem_u32(sm);

    auto issueA = [&](int k0, int s) {
        const __half* Ap = A; int kb = k0;
        if (A2 && k0 >= Ksplit) { Ap = A2; kb = k0 - Ksplit; }
        uint32_t base = sb + SA_OFF(s);
#pragma unroll
        for (int i = 0; i < 4; i++) {
            int f = tid + i * 256;
            int row = f >> 3, hq = (f & 7) * 8;
            CP16(base + SW128B(row * 128 + hq * 2),
                 Ap + (long)(m0 + row) * sAm + kb + hq);
        }
    };
    auto issueB = [&](int k0, int s) {
        uint32_t base = sb + SB_OFF(s);
#pragma unroll
        for (int i = 0; i < 4; i++) {
            int f = tid + i * 256;
            int row = f >> 3, hq = (f & 7) * 8;
            CP16(base + SW128B(row * 128 + hq * 2),
                 B + (long)(n0 + row) * sBn + k0 + hq);
        }
    };

    float acc[4][4][4];
#pragma unroll
    for (int i = 0; i < 4; i++)
#pragma unroll
        for (int j = 0; j < 4; j++)
#pragma unroll
            for (int r = 0; r < 4; r++) acc[i][j][r] = 0.f;

    const int T = K / BKH;
    issueA(0, 0); issueB(0, 0);
    asm volatile("cp.async.commit_group;" ::: "memory");
    if (T > 1) {
        issueA(BKH, 1); issueB(BKH, 1);
        asm volatile("cp.async.commit_group;" ::: "memory");
    }

    for (int t = 0; t < T; t++) {
        const int s = t % 3;
        if (t == T - 1)
            asm volatile("cp.async.wait_group 0;" ::: "memory");
        else
            asm volatile("cp.async.wait_group 1;" ::: "memory");
        __syncthreads();
        if (t + 2 < T) {
            issueA((t + 2) * BKH, (t + 2) % 3);
            issueB((t + 2) * BKH, (t + 2) % 3);
            asm volatile("cp.async.commit_group;" ::: "memory");
        }

        const uint32_t abase = sb + SA_OFF(s);
        const uint32_t bbase = sb + SB_OFF(s);
#pragma unroll
        for (int ks = 0; ks < 4; ks++) {
            uint32_t a[4][4], bf[2][4];

            const int arow = lane & 15;
            const int acolh = ks * 16 + (lane >> 4) * 8;
#pragma unroll
            for (int mt = 0; mt < 4; mt++)
                ldsm4h(a[mt][0], a[mt][1], a[mt][2], a[mt][3],
                       abase + SW128B((wm + mt * 16 + arow) * 128 + acolh * 2));

            const int brow = (lane & 7) + (lane >= 16 ? 8 : 0);
            const int bcolh = ks * 16 + ((lane >> 3) & 1) * 8;
#pragma unroll
            for (int np = 0; np < 2; np++)
                ldsm4h(bf[np][0], bf[np][1], bf[np][2], bf[np][3],
                       bbase + SW128B((wn + np * 16 + brow) * 128 + bcolh * 2));

#pragma unroll
            for (int mt = 0; mt < 4; mt++)
#pragma unroll
                for (int nt = 0; nt < 4; nt++)
                    mma16(acc[mt][nt], a[mt],
                          bf[nt >> 1][(nt & 1) * 2], bf[nt >> 1][(nt & 1) * 2 + 1]);
        }
    }

    const int g = lane >> 2, tg = lane & 3;

    if (sum_out) {
        float* P = (float*)Cv + (long)(m0 / BM) * N;
#pragma unroll
        for (int nt = 0; nt < 4; nt++) {
            int col = n0 + wn + nt * 8 + tg * 2;
            float bv0 = bias ? bias[col] : 0.f;
            float bv1 = bias ? bias[col + 1] : 0.f;
            float s0 = 0.f, s1 = 0.f;
#pragma unroll
            for (int mt = 0; mt < 4; mt++)
#pragma unroll
                for (int h = 0; h < 2; h++) {
                    float v0 = acc[mt][nt][2 * h] + bv0;
                    float v1 = acc[mt][nt][2 * h + 1] + bv1;
                    if (do_relu) { v0 = fmaxf(v0, 0.f); v1 = fmaxf(v1, 0.f); }
                    s0 += v0; s1 += v1;
                }
#pragma unroll
            for (int off = 16; off >= 4; off >>= 1) {
                s0 += __shfl_xor_sync(0xffffffffu, s0, off);
                s1 += __shfl_xor_sync(0xffffffffu, s1, off);
            }
            if (g == 0) {
                atomicAdd(&P[col], s0);
                atomicAdd(&P[col + 1], s1);
            }
        }
        return;
    }

#pragma unroll
    for (int mt = 0; mt < 4; mt++) {
#pragma unroll
        for (int nt = 0; nt < 4; nt++) {
            int row = m0 + wm + mt * 16 + g;
            int col = n0 + wn + nt * 8 + tg * 2;
            float bv0 = 0.f, bv1 = 0.f;
            if (bias) { bv0 = bias[col]; bv1 = bias[col + 1]; }
#pragma unroll
            for (int h = 0; h < 2; h++) {
                long ci = (long)(row + h * 8) * N + col + (long)blockIdx.z * bsC;
                float v0 = acc[mt][nt][2 * h] + bv0;
                float v1 = acc[mt][nt][2 * h + 1] + bv1;
                if (do_relu) { v0 = fmaxf(v0, 0.f); v1 = fmaxf(v1, 0.f); }
                if (out_half) {
                    __half2 hv = __floats2half2_rn(v0, v1);
                    *reinterpret_cast<__half2*>((__half*)Cv + ci) = hv;
                } else {
                    *reinterpret_cast<float2*>((float*)Cv + ci) = make_float2(v0, v1);
                }
            }
        }
    }
}

// ---------------- zero partials ------------------------------------------------
__global__ __launch_bounds__(256) void zero2_k(float* __restrict__ a, int na,
                                               float* __restrict__ b, int nb)
{
    int i = blockIdx.x * 256 + threadIdx.x;
    if (i < na) a[i] = 0.f;
    if (i < nb) b[i] = 0.f;
}

// ---------------- prep: fp32 -> fp16 row-major + fp16 transposed ---------------
__global__ __launch_bounds__(256) void prep_k(const float* __restrict__ in,
                                              __half* __restrict__ outR,
                                              __half* __restrict__ outT,
                                              int R, int C, long bs)
{
    __shared__ float tile[32][33];
    in += (long)blockIdx.z * bs;
    outR += (long)blockIdx.z * bs;
    outT += (long)blockIdx.z * bs;
    int c0 = blockIdx.x * 32, r0 = blockIdx.y * 32;
#pragma unroll
    for (int j = 0; j < 32; j += 8) {
        float v = in[(long)(r0 + threadIdx.y + j) * C + c0 + threadIdx.x];
        tile[threadIdx.y + j][threadIdx.x] = v;
        outR[(long)(r0 + threadIdx.y + j) * C + c0 + threadIdx.x] = __float2half_rn(v);
    }
    __syncthreads();
#pragma unroll
    for (int j = 0; j < 32; j += 8)
        outT[(long)(c0 + threadIdx.y + j) * R + r0 + threadIdx.x] =
            __float2half_rn(tile[threadIdx.x][threadIdx.y + j]);
}

// ---------------- tiled transpose fp32 -> fp16 (weights) -----------------------
__global__ __launch_bounds__(256) void transpose_h(const float* __restrict__ in,
                                                   __half* __restrict__ out,
                                                   int R, int C, long ibs, long obs)
{
    __shared__ float tile[32][33];
    in += (long)blockIdx.z * ibs;
    out += (long)blockIdx.z * obs;
    int c0 = blockIdx.x * 32, r0 = blockIdx.y * 32;
#pragma unroll
    for (int j = 0; j < 32; j += 8)
        tile[threadIdx.y + j][threadIdx.x] =
            in[(long)(r0 + threadIdx.y + j) * C + c0 + threadIdx.x];
    __syncthreads();
#pragma unroll
    for (int j = 0; j < 32; j += 8)
        out[(long)(c0 + threadIdx.y + j) * R + r0 + threadIdx.x] =
            __float2half_rn(tile[threadIdx.x][threadIdx.y + j]);
}

// ---------------- alpha: softmax over Le (fp16 in, fp16 out) -------------------
__global__ __launch_bounds__(256) void alpha_kernel(const __half* __restrict__ align,
                                                    __half* __restrict__ alphaH,
                                                    const int* __restrict__ em)
{
    int b = blockIdx.x / LCDIM;
    long base = (long)blockIdx.x * LEDIM;
    int t = threadIdx.x;

    float v[4];
    float mx = -3.4e38f;
#pragma unroll
    for (int i = 0; i < 4; i++) {
        int e = t + i * 256;
        float x = __half2float(align[base + e]);
        if (em[b * LEDIM + e] == 0) x += NEGV;
        v[i] = x;
        mx = fmaxf(mx, x);
    }
    __shared__ float red[256];
    red[t] = mx; __syncthreads();
    for (int s = 128; s > 0; s >>= 1) { if (t < s) red[t] = fmaxf(red[t], red[t + s]); __syncthreads(); }
    mx = red[0]; __syncthreads();

    float sm = 0.f;
#pragma unroll
    for (int i = 0; i < 4; i++) { v[i] = __expf(v[i] - mx); sm += v[i]; }
    red[t] = sm; __syncthreads();
    for (int s = 128; s > 0; s >>= 1) { if (t < s) red[t] += red[t + s]; __syncthreads(); }
    float inv = 1.f / red[0];

#pragma unroll
    for (int i = 0; i < 4; i++)
        alphaH[base + t + i * 256] = __float2half_rn(v[i] * inv);
}

// ---------------- beta: online column stats (fp16 in) --------------------------
__global__ __launch_bounds__(256) void colstats_kernel(const __half* __restrict__ align,
                                                       const int* __restrict__ cm,
                                                       float* __restrict__ mxo,
                                                       float* __restrict__ invo)
{
    int b = blockIdx.x / (LEDIM / 256);
    int e = (blockIdx.x % (LEDIM / 256)) * 256 + threadIdx.x;

    __shared__ float negs[LCDIM];
    for (int l = threadIdx.x; l < LCDIM; l += 256)
        negs[l] = cm[b * LCDIM + l] ? 0.f : NEGV;
    __syncthreads();

    const __half* col = align + (long)b * LCDIM * LEDIM + e;
    float m = -3.4e38f, s = 0.f;
#pragma unroll 4
    for (int l = 0; l < LCDIM; l++) {
        float x = __half2float(col[(long)l * LEDIM]) + negs[l];
        float nm = fmaxf(m, x);
        s = s * __expf(m - nm) + __expf(x - nm);
        m = nm;
    }
    mxo[b * LEDIM + e] = m;
    invo[b * LEDIM + e] = 1.f / s;
}

// ---------------- beta write: normalize + transpose (fp16 in/out) --------------
__global__ void betaT_kernel(const __half* __restrict__ align,
                             __half* __restrict__ betaT,
                             const int* __restrict__ cm,
                             const float* __restrict__ mx,
                             const float* __restrict__ inv)
{
    int b = blockIdx.z;
    int e0 = blockIdx.x * 32, l0 = blockIdx.y * 32;
    __shared__ float tile[32][33];
    const __half* al = align + (long)b * LCDIM * LEDIM;
#pragma unroll
    for (int j = 0; j < 32; j += 8) {
        int l = l0 + threadIdx.y + j, e = e0 + threadIdx.x;
        float neg = cm[b * LCDIM + l] ? 0.f : NEGV;
        tile[threadIdx.y + j][threadIdx.x] =
            __expf(__half2float(al[(long)l * LEDIM + e]) + neg - mx[b * LEDIM + e])
            * inv[b * LEDIM + e];
    }
    __syncthreads();
    __half* out = betaT + (long)b * LCDIM * LEDIM;
#pragma unroll
    for (int j = 0; j < 32; j += 8)
        out[(long)(e0 + threadIdx.y + j) * LCDIM + l0 + threadIdx.x] =
            __float2half_rn(tile[threadIdx.x][threadIdx.y + j]);
}

// ---------------- final MLP ----------------------------------------------------
__global__ __launch_bounds__(512) void final_kernel(
    const float* __restrict__ r1p, const float* __restrict__ r2p,
    const float* __restrict__ Wm, const float* __restrict__ bm,
    const float* __restrict__ Wo, const float* __restrict__ bo,
    float* __restrict__ out)
{
    int b = blockIdx.x;
    int t = threadIdx.x;

    __shared__ float ms[4 * DDIM];
    __shared__ float hs[MMDIM];

    if (t < DDIM) {
        float r1 = 0.f, r2 = 0.f;
#pragma unroll
        for (int s = 0; s < 2; s++) r1 += r1p[(b * 2 + s) * DDIM + t];
#pragma unroll
        for (int s = 0; s < 8; s++) r2 += r2p[(b * 8 + s) * DDIM + t];
        ms[t] = r1;
        ms[DDIM + t] = r2;
        ms[2 * DDIM + t] = r1 * r2;
        ms[3 * DDIM + t] = r1 - r2;
    }
    __syncthreads();

    float acc = bm[t];
#pragma unroll 8
    for (int k = 0; k < 4 * DDIM; k++) acc += ms[k] * Wm[(long)k * MMDIM + t];
    hs[t] = fmaxf(acc, 0.f);
    __syncthreads();

    int w = t >> 5, lane = t & 31;
    if (w < 3) {
        float s = 0.f;
        for (int j = lane; j < MMDIM; j += 32) s += hs[j] * Wo[j * 3 + w];
#pragma unroll
        for (int off = 16; off; off >>= 1) s += __shfl_down_sync(0xffffffffu, s, off);
        if (lane == 0) out[b * 3 + w] = s + bo[w];
    }
}

// ---------------- launch -------------------------------------------------------
extern "C" void kernel_launch(void* const* d_in, const int* in_sizes, int n_in,
                              void* d_out, int out_size)
{
    const float *criteria, *ehr, *Wa, *ba, *Wr, *br, *Wm, *bm, *Wo, *bo;
    const int *cmask, *emask;

    if (in_sizes[2] == BB * LCDIM) {
        criteria = (const float*)d_in[0]; ehr = (const float*)d_in[1];
        cmask = (const int*)d_in[2]; emask = (const int*)d_in[3];
        Wa = (const float*)d_in[4]; ba = (const float*)d_in[5];
        Wr = (const float*)d_in[6]; br = (const float*)d_in[7];
        Wm = (const float*)d_in[8]; bm = (const float*)d_in[9];
        Wo = (const float*)d_in[10]; bo = (const float*)d_in[11];
    } else {
        criteria = (const float*)d_in[0]; ehr = (const float*)d_in[1];
        Wa = (const float*)d_in[2]; ba = (const float*)d_in[3];
        Wr = (const float*)d_in[4]; br = (const float*)d_in[5];
        Wm = (const float*)d_in[6]; bm = (const float*)d_in[7];
        Wo = (const float*)d_in[8]; bo = (const float*)d_in[9];
        cmask = (const int*)d_in[10]; emask = (const int*)d_in[11];
    }

    __half *critH, *ehrH, *cH, *eH, *alignH, *alphaH, *beTH, *ehrTH, *critTH;
    __half *attcH, *atteH, *WaTH, *WrTH;
    float *r1p, *r2p, *cmx, *cinv;
    cudaGetSymbolAddress((void**)&critH,  g_critH);
    cudaGetSymbolAddress((void**)&ehrH,   g_ehrH);
    cudaGetSymbolAddress((void**)&cH,     g_cH);
    cudaGetSymbolAddress((void**)&eH,     g_eH);
    cudaGetSymbolAddress((void**)&alignH, g_alignH);
    cudaGetSymbolAddress((void**)&alphaH, g_alphaH);
    cudaGetSymbolAddress((void**)&beTH,   g_beTH);
    cudaGetSymbolAddress((void**)&ehrTH,  g_ehrTH);
    cudaGetSymbolAddress((void**)&critTH, g_critTH);
    cudaGetSymbolAddress((void**)&attcH,  g_attcH);
    cudaGetSymbolAddress((void**)&atteH,  g_atteH);
    cudaGetSymbolAddress((void**)&WaTH,   g_WaTH);
    cudaGetSymbolAddress((void**)&WrTH,   g_WrTH);
    cudaGetSymbolAddress((void**)&r1p,    g_r1p);
    cudaGetSymbolAddress((void**)&r2p,    g_r2p);
    cudaGetSymbolAddress((void**)&cmx,    g_cmx);
    cudaGetSymbolAddress((void**)&cinv,   g_cinv);

    cudaFuncSetAttribute(gemm_h, cudaFuncAttributeMaxDynamicSharedMemorySize,
                         GSM_TOTAL);

    const long LCD = (long)LCDIM * DDIM;   // 65536
    const long LED = (long)LEDIM * DDIM;   // 262144
    const long LCE = (long)LCDIM * LEDIM;  // 262144

    dim3 tb(32, 8);

    // prologue: fp16 copies + transposes, zero partials
    prep_k<<<dim3(8, 8, BB),  tb>>>(criteria, critH, critTH, LCDIM, DDIM, LCD);
    prep_k<<<dim3(8, 32, BB), tb>>>(ehr, ehrH, ehrTH, LEDIM, DDIM, LED);
    transpose_h<<<dim3(8, 8, 1),  tb>>>(Wa, WaTH, DDIM, DDIM, 0, 0);
    transpose_h<<<dim3(8, 16, 1), tb>>>(Wr, WrTH, 2 * DDIM, DDIM, 0, 0);
    zero2_k<<<1024, 256>>>(r1p, BB * 2 * DDIM, r2p, BB * 8 * DDIM);

    // c = relu(criteria @ Wa + ba) -> fp16
    gemm_h<<<dim3(DDIM / BN, (BB * LCDIM) / BM, 1), 256, GSM_TOTAL>>>(
        critH, nullptr, 0, WaTH, ba, cH, BB * LCDIM, DDIM, DDIM,
        DDIM, 0, DDIM, 0, 0, 1, 1, 0);

    // e = relu(ehr @ Wa + ba) -> fp16
    gemm_h<<<dim3(DDIM / BN, (BB * LEDIM) / BM, 1), 256, GSM_TOTAL>>>(
        ehrH, nullptr, 0, WaTH, ba, eH, BB * LEDIM, DDIM, DDIM,
        DDIM, 0, DDIM, 0, 0, 1, 1, 0);

    // align[b] = c[b] @ e[b]^T -> fp16 (halves softmax-stage traffic)
    gemm_h<<<dim3(LEDIM / BN, LCDIM / BM, BB), 256, GSM_TOTAL>>>(
        cH, nullptr, 0, eH, nullptr, alignH, LCDIM, LEDIM, DDIM,
        DDIM, LCD, DDIM, LED, LCE, 0, 1, 0);

    // beta stats + transposed fp16 write; alpha fp16 write
    colstats_kernel<<<BB * (LEDIM / 256), 256>>>(alignH, cmask, cmx, cinv);
    betaT_kernel<<<dim3(LEDIM / 32, LCDIM / 32, BB), tb>>>(alignH, beTH, cmask, cmx, cinv);
    alpha_kernel<<<BB * LCDIM, 256>>>(alignH, alphaH, emask);

    // att_c[b] = alpha[b] @ ehr[b] -> fp16
    gemm_h<<<dim3(DDIM / BN, LCDIM / BM, BB), 256, GSM_TOTAL>>>(
        alphaH, nullptr, 0, ehrTH, nullptr, attcH, LCDIM, DDIM, LEDIM,
        LEDIM, LCE, LEDIM, LED, LCD, 0, 1, 0);

    // att_e[b] = beta[b]^T @ criteria[b] -> fp16
    gemm_h<<<dim3(DDIM / BN, LEDIM / BM, BB), 256, GSM_TOTAL>>>(
        beTH, nullptr, 0, critTH, nullptr, atteH, LEDIM, DDIM, LCDIM,
        LCDIM, LCE, LCDIM, LCD, LED, 0, 1, 0);

    // r1 partials = rowsum(relu([attc, criteria] @ Wr + br)) (fused epilogue)
    gemm_h<<<dim3(DDIM / BN, (BB * LCDIM) / BM, 1), 256, GSM_TOTAL>>>(
        attcH, critH, DDIM, WrTH, br, r1p, BB * LCDIM, DDIM, 2 * DDIM,
        DDIM, 0, 2 * DDIM, 0, 0, 1, 0, 1);

    // r2 partials = rowsum(relu([atte, ehr] @ Wr + br))
    gemm_h<<<dim3(DDIM / BN, (BB * LEDIM) / BM, 1), 256, GSM_TOTAL>>>(
        atteH, ehrH, DDIM, WrTH, br, r2p, BB * LEDIM, DDIM, 2 * DDIM,
        DDIM, 0, 2 * DDIM, 0, 0, 1, 0, 1);

    final_kernel<<<BB, 512>>>(r1p, r2p, Wm, bm, Wo, bo, (float*)d_out);
}

// round 11
// speedup vs baseline: 2.1093x; 1.0952x over previous
#include <cuda_runtime.h>
#include <cuda_fp16.h>
#include <cstdint>

#define BB 128
#define LCDIM 256
#define LEDIM 1024
#define DDIM 256
#define MMDIM 512
#define NEGV -1e9f

// ---------------- scratch ----------------------------------------------------
__device__ __align__(16) __half g_critH[(size_t)BB * LCDIM * DDIM];
__device__ __align__(16) __half g_ehrH[(size_t)BB * LEDIM * DDIM];
__device__ __align__(16) __half g_cH[(size_t)BB * LCDIM * DDIM];
__device__ __align__(16) __half g_eH[(size_t)BB * LEDIM * DDIM];
__device__ __align__(16) __half g_alignH[(size_t)BB * LCDIM * LEDIM];
__device__ __align__(16) __half g_alphaH[(size_t)BB * LCDIM * LEDIM];
__device__ __align__(16) __half g_beTH[(size_t)BB * LCDIM * LEDIM];
__device__ __align__(16) __half g_ehrTH[(size_t)BB * LEDIM * DDIM];
__device__ __align__(16) __half g_critTH[(size_t)BB * LCDIM * DDIM];
__device__ __align__(16) __half g_attcH[(size_t)BB * LCDIM * DDIM];
__device__ __align__(16) __half g_atteH[(size_t)BB * LEDIM * DDIM];
__device__ __align__(16) __half g_WaTH[DDIM * DDIM];
__device__ __align__(16) __half g_WrTH[DDIM * 2 * DDIM];
__device__ float g_r1p[BB * 2 * DDIM];
__device__ float g_r2p[BB * 8 * DDIM];
__device__ float g_cmx[BB * LEDIM];
__device__ float g_cinv[BB * LEDIM];

// ---------------- helpers -----------------------------------------------------
__device__ __forceinline__ uint32_t smem_u32(const void* p) {
    uint32_t a;
    asm("{ .reg .u64 t; cvta.to.shared.u64 t, %1; cvt.u32.u64 %0, t; }"
        : "=r"(a) : "l"(p));
    return a;
}

#define SW128B(o) ((o) ^ (((o) >> 3) & 0x70))

__device__ __forceinline__ void ldsm4h(uint32_t& r0, uint32_t& r1, uint32_t& r2,
                                       uint32_t& r3, uint32_t addr) {
    asm volatile("ldmatrix.sync.aligned.m8n8.x4.shared.b16 {%0,%1,%2,%3}, [%4];"
                 : "=r"(r0), "=r"(r1), "=r"(r2), "=r"(r3) : "r"(addr));
}

__device__ __forceinline__ void mma16(float* c, const uint32_t* a, uint32_t b0, uint32_t b1) {
    asm volatile(
        "mma.sync.aligned.m16n8k16.row.col.f32.f16.f16.f32 "
        "{%0,%1,%2,%3}, {%4,%5,%6,%7}, {%8,%9}, {%0,%1,%2,%3};"
        : "+f"(c[0]), "+f"(c[1]), "+f"(c[2]), "+f"(c[3])
        : "r"(a[0]), "r"(a[1]), "r"(a[2]), "r"(a[3]), "r"(b0), "r"(b1));
}

#define CP16(d, g) \
    asm volatile("cp.async.cg.shared.global [%0], [%1], 16;" :: "r"(d), "l"(g))

// ---------------- FP16 tensor-core GEMM (unchanged core) -----------------------
#define BM 128
#define BN 128
#define BKH 64
#define SA_OFF(s) ((s) * 16384)
#define SB_OFF(s) (49152 + (s) * 16384)
#define GSM_TOTAL 98304

__global__ __launch_bounds__(256, 2) void gemm_h(
    const __half* __restrict__ A, const __half* __restrict__ A2, int Ksplit,
    const __half* __restrict__ B, const float* __restrict__ bias,
    void* __restrict__ Cv,
    int M, int N, int K,
    long sAm, long bsA, long sBn, long bsB, long bsC,
    int do_relu, int out_half, int sum_out)
{
    extern __shared__ char sm[];
    A += (long)blockIdx.z * bsA;
    if (A2) A2 += (long)blockIdx.z * bsA;
    B += (long)blockIdx.z * bsB;

    const int tid = threadIdx.x;
    const int lane = tid & 31;
    const int w = tid >> 5;
    const int wm = (w & 1) * 64;
    const int wn = (w >> 1) * 32;
    const int m0 = blockIdx.y * BM;
    const int n0 = blockIdx.x * BN;
    const uint32_t sb = smem_u32(sm);

    auto issueA = [&](int k0, int s) {
        const __half* Ap = A; int kb = k0;
        if (A2 && k0 >= Ksplit) { Ap = A2; kb = k0 - Ksplit; }
        uint32_t base = sb + SA_OFF(s);
#pragma unroll
        for (int i = 0; i < 4; i++) {
            int f = tid + i * 256;
            int row = f >> 3, hq = (f & 7) * 8;
            CP16(base + SW128B(row * 128 + hq * 2),
                 Ap + (long)(m0 + row) * sAm + kb + hq);
        }
    };
    auto issueB = [&](int k0, int s) {
        uint32_t base = sb + SB_OFF(s);
#pragma unroll
        for (int i = 0; i < 4; i++) {
            int f = tid + i * 256;
            int row = f >> 3, hq = (f & 7) * 8;
            CP16(base + SW128B(row * 128 + hq * 2),
                 B + (long)(n0 + row) * sBn + k0 + hq);
        }
    };

    float acc[4][4][4];
#pragma unroll
    for (int i = 0; i < 4; i++)
#pragma unroll
        for (int j = 0; j < 4; j++)
#pragma unroll
            for (int r = 0; r < 4; r++) acc[i][j][r] = 0.f;

    const int T = K / BKH;
    issueA(0, 0); issueB(0, 0);
    asm volatile("cp.async.commit_group;" ::: "memory");
    if (T > 1) {
        issueA(BKH, 1); issueB(BKH, 1);
        asm volatile("cp.async.commit_group;" ::: "memory");
    }

    for (int t = 0; t < T; t++) {
        const int s = t % 3;
        if (t == T - 1)
            asm volatile("cp.async.wait_group 0;" ::: "memory");
        else
            asm volatile("cp.async.wait_group 1;" ::: "memory");
        __syncthreads();
        if (t + 2 < T) {
            issueA((t + 2) * BKH, (t + 2) % 3);
            issueB((t + 2) * BKH, (t + 2) % 3);
            asm volatile("cp.async.commit_group;" ::: "memory");
        }

        const uint32_t abase = sb + SA_OFF(s);
        const uint32_t bbase = sb + SB_OFF(s);
#pragma unroll
        for (int ks = 0; ks < 4; ks++) {
            uint32_t a[4][4], bf[2][4];

            const int arow = lane & 15;
            const int acolh = ks * 16 + (lane >> 4) * 8;
#pragma unroll
            for (int mt = 0; mt < 4; mt++)
                ldsm4h(a[mt][0], a[mt][1], a[mt][2], a[mt][3],
                       abase + SW128B((wm + mt * 16 + arow) * 128 + acolh * 2));

            const int brow = (lane & 7) + (lane >= 16 ? 8 : 0);
            const int bcolh = ks * 16 + ((lane >> 3) & 1) * 8;
#pragma unroll
            for (int np = 0; np < 2; np++)
                ldsm4h(bf[np][0], bf[np][1], bf[np][2], bf[np][3],
                       bbase + SW128B((wn + np * 16 + brow) * 128 + bcolh * 2));

#pragma unroll
            for (int mt = 0; mt < 4; mt++)
#pragma unroll
                for (int nt = 0; nt < 4; nt++)
                    mma16(acc[mt][nt], a[mt],
                          bf[nt >> 1][(nt & 1) * 2], bf[nt >> 1][(nt & 1) * 2 + 1]);
        }
    }

    const int g = lane >> 2, tg = lane & 3;

    if (sum_out) {
        float* P = (float*)Cv + (long)(m0 / BM) * N;
#pragma unroll
        for (int nt = 0; nt < 4; nt++) {
            int col = n0 + wn + nt * 8 + tg * 2;
            float bv0 = bias ? bias[col] : 0.f;
            float bv1 = bias ? bias[col + 1] : 0.f;
            float s0 = 0.f, s1 = 0.f;
#pragma unroll
            for (int mt = 0; mt < 4; mt++)
#pragma unroll
                for (int h = 0; h < 2; h++) {
                    float v0 = acc[mt][nt][2 * h] + bv0;
                    float v1 = acc[mt][nt][2 * h + 1] + bv1;
                    if (do_relu) { v0 = fmaxf(v0, 0.f); v1 = fmaxf(v1, 0.f); }
                    s0 += v0; s1 += v1;
                }
#pragma unroll
            for (int off = 16; off >= 4; off >>= 1) {
                s0 += __shfl_xor_sync(0xffffffffu, s0, off);
                s1 += __shfl_xor_sync(0xffffffffu, s1, off);
            }
            if (g == 0) {
                atomicAdd(&P[col], s0);
                atomicAdd(&P[col + 1], s1);
            }
        }
        return;
    }

#pragma unroll
    for (int mt = 0; mt < 4; mt++) {
#pragma unroll
        for (int nt = 0; nt < 4; nt++) {
            int row = m0 + wm + mt * 16 + g;
            int col = n0 + wn + nt * 8 + tg * 2;
            float bv0 = 0.f, bv1 = 0.f;
            if (bias) { bv0 = bias[col]; bv1 = bias[col + 1]; }
#pragma unroll
            for (int h = 0; h < 2; h++) {
                long ci = (long)(row + h * 8) * N + col + (long)blockIdx.z * bsC;
                float v0 = acc[mt][nt][2 * h] + bv0;
                float v1 = acc[mt][nt][2 * h + 1] + bv1;
                if (do_relu) { v0 = fmaxf(v0, 0.f); v1 = fmaxf(v1, 0.f); }
                if (out_half) {
                    __half2 hv = __floats2half2_rn(v0, v1);
                    *reinterpret_cast<__half2*>((__half*)Cv + ci) = hv;
                } else {
                    *reinterpret_cast<float2*>((float*)Cv + ci) = make_float2(v0, v1);
                }
            }
        }
    }
}

// ---------------- prep: fp32 -> fp16 row-major + fp16 transposed ---------------
__global__ __launch_bounds__(256) void prep_k(const float* __restrict__ in,
                                              __half* __restrict__ outR,
                                              __half* __restrict__ outT,
                                              int R, int C, long bs)
{
    __shared__ float tile[32][33];
    in += (long)blockIdx.z * bs;
    outR += (long)blockIdx.z * bs;
    outT += (long)blockIdx.z * bs;
    int c0 = blockIdx.x * 32, r0 = blockIdx.y * 32;
#pragma unroll
    for (int j = 0; j < 32; j += 8) {
        float v = in[(long)(r0 + threadIdx.y + j) * C + c0 + threadIdx.x];
        tile[threadIdx.y + j][threadIdx.x] = v;
        outR[(long)(r0 + threadIdx.y + j) * C + c0 + threadIdx.x] = __float2half_rn(v);
    }
    __syncthreads();
#pragma unroll
    for (int j = 0; j < 32; j += 8)
        outT[(long)(c0 + threadIdx.y + j) * R + r0 + threadIdx.x] =
            __float2half_rn(tile[threadIdx.x][threadIdx.y + j]);
}

// ---------------- setup: Wa^T + Wr^T + zero partials in ONE launch -------------
__global__ __launch_bounds__(256) void setup_k(
    const float* __restrict__ Wa, __half* __restrict__ WaT,
    const float* __restrict__ Wr, __half* __restrict__ WrT,
    float* __restrict__ r1p, int n1, float* __restrict__ r2p, int n2)
{
    int ty = blockIdx.y;
    if (ty == 24) {
        int i = blockIdx.x * 256 + threadIdx.y * 32 + threadIdx.x; // 0..2047
        for (int j = i; j < n1; j += 2048) r1p[j] = 0.f;
        for (int j = i; j < n2; j += 2048) r2p[j] = 0.f;
        return;
    }
    const float* in; __half* out; int R, r0;
    if (ty < 8) { in = Wa; out = WaT; R = DDIM;     r0 = ty * 32; }
    else        { in = Wr; out = WrT; R = 2 * DDIM; r0 = (ty - 8) * 32; }
    const int C = DDIM;
    __shared__ float tile[32][33];
    int c0 = blockIdx.x * 32;
#pragma unroll
    for (int j = 0; j < 32; j += 8)
        tile[threadIdx.y + j][threadIdx.x] =
            in[(long)(r0 + threadIdx.y + j) * C + c0 + threadIdx.x];
    __syncthreads();
#pragma unroll
    for (int j = 0; j < 32; j += 8)
        out[(long)(c0 + threadIdx.y + j) * R + r0 + threadIdx.x] =
            __float2half_rn(tile[threadIdx.x][threadIdx.y + j]);
}

// ---------------- fused alpha + betaT: ONE read of alignH ----------------------
// grid (LCDIM/32, BB), 256 threads. Tile 32 rows x 1024 cols fp16 in SMEM,
// row stride 1026 halves (513 words, ODD) -> conflict-free row AND column LDS.
// Staging: LDG.128 from global, 4x STS.32 into the odd-strided tile (4B-aligned
// for every row; the previous uint4 STS faulted on odd rows: 2052 % 16 != 0).
#define ABPAD 1026
#define ABSM (32 * ABPAD * 2)

__global__ __launch_bounds__(256) void alphabeta_k(
    const __half* __restrict__ align,
    __half* __restrict__ alphaH, __half* __restrict__ betaT,
    const int* __restrict__ cm, const int* __restrict__ em,
    const float* __restrict__ cmx, const float* __restrict__ cinv)
{
    extern __shared__ char sm[];
    __half* tile = reinterpret_cast<__half*>(sm);
    uint32_t* tw = reinterpret_cast<uint32_t*>(sm);
    const int b = blockIdx.y, l0 = blockIdx.x * 32;
    const int tid = threadIdx.x, lane = tid & 31, w = tid >> 5;
    const __half* al = align + ((long)b * LCDIM + l0) * LEDIM;

    // load 32x1024 halves: LDG.128 (4096 uint4), store as 4x STS.32
#pragma unroll
    for (int i = 0; i < 16; i++) {
        int f = tid + i * 256;
        int row = f >> 7, seg = (f & 127) * 4;      // word segment within row
        uint4 v = *reinterpret_cast<const uint4*>(&al[(long)row * LEDIM + seg * 2]);
        uint32_t* d = tw + row * (ABPAD / 2) + seg;  // ABPAD/2 = 513 words
        d[0] = v.x; d[1] = v.y; d[2] = v.z; d[3] = v.w;
    }
    __syncthreads();

    // per-lane ehr-mask offsets (same e-set for every row)
    float negs[32];
#pragma unroll
    for (int i = 0; i < 32; i++)
        negs[i] = em[b * LEDIM + lane + i * 32] ? 0.f : NEGV;

    // Phase A: alpha (row softmax), warp w handles rows w*4..w*4+3
#pragma unroll 1
    for (int r = 0; r < 4; r++) {
        int row = w * 4 + r;
        float vals[32];
        float mx = -3.4e38f;
#pragma unroll
        for (int i = 0; i < 32; i++) {
            float x = __half2float(tile[row * ABPAD + lane + i * 32]) + negs[i];
            vals[i] = x;
            mx = fmaxf(mx, x);
        }
#pragma unroll
        for (int off = 16; off; off >>= 1)
            mx = fmaxf(mx, __shfl_xor_sync(0xffffffffu, mx, off));
        float sum = 0.f;
#pragma unroll
        for (int i = 0; i < 32; i++) { vals[i] = __expf(vals[i] - mx); sum += vals[i]; }
#pragma unroll
        for (int off = 16; off; off >>= 1)
            sum += __shfl_xor_sync(0xffffffffu, sum, off);
        float inv = 1.f / sum;
        long gbase = ((long)b * LCDIM + l0 + row) * LEDIM;
#pragma unroll
        for (int i = 0; i < 32; i++)
            alphaH[gbase + lane + i * 32] = __float2half_rn(vals[i] * inv);
    }

    // Phase B: betaT — warp w covers e in [w*128, w*128+128); lane = l offset
    float negl = cm[b * LCDIM + l0 + lane] ? 0.f : NEGV;
    const float* cmxb = cmx + b * LEDIM;
    const float* cinvb = cinv + b * LEDIM;
    __half* outb = betaT + (long)b * LCDIM * LEDIM + l0 + lane;
#pragma unroll 4
    for (int i = 0; i < 128; i++) {
        int e = w * 128 + i;
        float x = __half2float(tile[lane * ABPAD + e]);   // odd word stride: no conflicts
        float v = __expf(x + negl - cmxb[e]) * cinvb[e];
        outb[(long)e * LCDIM] = __float2half_rn(v);
    }
}

// ---------------- beta: online column stats (fp16 in) --------------------------
__global__ __launch_bounds__(256) void colstats_kernel(const __half* __restrict__ align,
                                                       const int* __restrict__ cm,
                                                       float* __restrict__ mxo,
                                                       float* __restrict__ invo)
{
    int b = blockIdx.x / (LEDIM / 256);
    int e = (blockIdx.x % (LEDIM / 256)) * 256 + threadIdx.x;

    __shared__ float negs[LCDIM];
    for (int l = threadIdx.x; l < LCDIM; l += 256)
        negs[l] = cm[b * LCDIM + l] ? 0.f : NEGV;
    __syncthreads();

    const __half* col = align + (long)b * LCDIM * LEDIM + e;
    float m = -3.4e38f, s = 0.f;
#pragma unroll 4
    for (int l = 0; l < LCDIM; l++) {
        float x = __half2float(col[(long)l * LEDIM]) + negs[l];
        float nm = fmaxf(m, x);
        s = s * __expf(m - nm) + __expf(x - nm);
        m = nm;
    }
    mxo[b * LEDIM + e] = m;
    invo[b * LEDIM + e] = 1.f / s;
}

// ---------------- final MLP ----------------------------------------------------
__global__ __launch_bounds__(512) void final_kernel(
    const float* __restrict__ r1p, const float* __restrict__ r2p,
    const float* __restrict__ Wm, const float* __restrict__ bm,
    const float* __restrict__ Wo, const float* __restrict__ bo,
    float* __restrict__ out)
{
    int b = blockIdx.x;
    int t = threadIdx.x;

    __shared__ float ms[4 * DDIM];
    __shared__ float hs[MMDIM];

    if (t < DDIM) {
        float r1 = 0.f, r2 = 0.f;
#pragma unroll
        for (int s = 0; s < 2; s++) r1 += r1p[(b * 2 + s) * DDIM + t];
#pragma unroll
        for (int s = 0; s < 8; s++) r2 += r2p[(b * 8 + s) * DDIM + t];
        ms[t] = r1;
        ms[DDIM + t] = r2;
        ms[2 * DDIM + t] = r1 * r2;
        ms[3 * DDIM + t] = r1 - r2;
    }
    __syncthreads();

    float acc = bm[t];
#pragma unroll 8
    for (int k = 0; k < 4 * DDIM; k++) acc += ms[k] * Wm[(long)k * MMDIM + t];
    hs[t] = fmaxf(acc, 0.f);
    __syncthreads();

    int w = t >> 5, lane = t & 31;
    if (w < 3) {
        float s = 0.f;
        for (int j = lane; j < MMDIM; j += 32) s += hs[j] * Wo[j * 3 + w];
#pragma unroll
        for (int off = 16; off; off >>= 1) s += __shfl_down_sync(0xffffffffu, s, off);
        if (lane == 0) out[b * 3 + w] = s + bo[w];
    }
}

// ---------------- launch -------------------------------------------------------
extern "C" void kernel_launch(void* const* d_in, const int* in_sizes, int n_in,
                              void* d_out, int out_size)
{
    const float *criteria, *ehr, *Wa, *ba, *Wr, *br, *Wm, *bm, *Wo, *bo;
    const int *cmask, *emask;

    if (in_sizes[2] == BB * LCDIM) {
        criteria = (const float*)d_in[0]; ehr = (const float*)d_in[1];
        cmask = (const int*)d_in[2]; emask = (const int*)d_in[3];
        Wa = (const float*)d_in[4]; ba = (const float*)d_in[5];
        Wr = (const float*)d_in[6]; br = (const float*)d_in[7];
        Wm = (const float*)d_in[8]; bm = (const float*)d_in[9];
        Wo = (const float*)d_in[10]; bo = (const float*)d_in[11];
    } else {
        criteria = (const float*)d_in[0]; ehr = (const float*)d_in[1];
        Wa = (const float*)d_in[2]; ba = (const float*)d_in[3];
        Wr = (const float*)d_in[4]; br = (const float*)d_in[5];
        Wm = (const float*)d_in[6]; bm = (const float*)d_in[7];
        Wo = (const float*)d_in[8]; bo = (const float*)d_in[9];
        cmask = (const int*)d_in[10]; emask = (const int*)d_in[11];
    }

    __half *critH, *ehrH, *cH, *eH, *alignH, *alphaH, *beTH, *ehrTH, *critTH;
    __half *attcH, *atteH, *WaTH, *WrTH;
    float *r1p, *r2p, *cmx, *cinv;
    cudaGetSymbolAddress((void**)&critH,  g_critH);
    cudaGetSymbolAddress((void**)&ehrH,   g_ehrH);
    cudaGetSymbolAddress((void**)&cH,     g_cH);
    cudaGetSymbolAddress((void**)&eH,     g_eH);
    cudaGetSymbolAddress((void**)&alignH, g_alignH);
    cudaGetSymbolAddress((void**)&alphaH, g_alphaH);
    cudaGetSymbolAddress((void**)&beTH,   g_beTH);
    cudaGetSymbolAddress((void**)&ehrTH,  g_ehrTH);
    cudaGetSymbolAddress((void**)&critTH, g_critTH);
    cudaGetSymbolAddress((void**)&attcH,  g_attcH);
    cudaGetSymbolAddress((void**)&atteH,  g_atteH);
    cudaGetSymbolAddress((void**)&WaTH,   g_WaTH);
    cudaGetSymbolAddress((void**)&WrTH,   g_WrTH);
    cudaGetSymbolAddress((void**)&r1p,    g_r1p);
    cudaGetSymbolAddress((void**)&r2p,    g_r2p);
    cudaGetSymbolAddress((void**)&cmx,    g_cmx);
    cudaGetSymbolAddress((void**)&cinv,   g_cinv);

    cudaFuncSetAttribute(gemm_h, cudaFuncAttributeMaxDynamicSharedMemorySize,
                         GSM_TOTAL);
    cudaFuncSetAttribute(alphabeta_k, cudaFuncAttributeMaxDynamicSharedMemorySize,
                         ABSM);

    const long LCD = (long)LCDIM * DDIM;   // 65536
    const long LED = (long)LEDIM * DDIM;   // 262144
    const long LCE = (long)LCDIM * LEDIM;  // 262144

    dim3 tb(32, 8);

    // prologue: fp16 copies + transposes + zero partials
    prep_k<<<dim3(8, 8, BB),  tb>>>(criteria, critH, critTH, LCDIM, DDIM, LCD);
    prep_k<<<dim3(8, 32, BB), tb>>>(ehr, ehrH, ehrTH, LEDIM, DDIM, LED);
    setup_k<<<dim3(8, 25), tb>>>(Wa, WaTH, Wr, WrTH,
                                 r1p, BB * 2 * DDIM, r2p, BB * 8 * DDIM);

    // c = relu(criteria @ Wa + ba) -> fp16
    gemm_h<<<dim3(DDIM / BN, (BB * LCDIM) / BM, 1), 256, GSM_TOTAL>>>(
        critH, nullptr, 0, WaTH, ba, cH, BB * LCDIM, DDIM, DDIM,
        DDIM, 0, DDIM, 0, 0, 1, 1, 0);

    // e = relu(ehr @ Wa + ba) -> fp16
    gemm_h<<<dim3(DDIM / BN, (BB * LEDIM) / BM, 1), 256, GSM_TOTAL>>>(
        ehrH, nullptr, 0, WaTH, ba, eH, BB * LEDIM, DDIM, DDIM,
        DDIM, 0, DDIM, 0, 0, 1, 1, 0);

    // align[b] = c[b] @ e[b]^T -> fp16
    gemm_h<<<dim3(LEDIM / BN, LCDIM / BM, BB), 256, GSM_TOTAL>>>(
        cH, nullptr, 0, eH, nullptr, alignH, LCDIM, LEDIM, DDIM,
        DDIM, LCD, DDIM, LED, LCE, 0, 1, 0);

    // column stats, then fused alpha + betaT (single alignH read)
    colstats_kernel<<<BB * (LEDIM / 256), 256>>>(alignH, cmask, cmx, cinv);
    alphabeta_k<<<dim3(LCDIM / 32, BB), 256, ABSM>>>(
        alignH, alphaH, beTH, cmask, emask, cmx, cinv);

    // att_c[b] = alpha[b] @ ehr[b] -> fp16
    gemm_h<<<dim3(DDIM / BN, LCDIM / BM, BB), 256, GSM_TOTAL>>>(
        alphaH, nullptr, 0, ehrTH, nullptr, attcH, LCDIM, DDIM, LEDIM,
        LEDIM, LCE, LEDIM, LED, LCD, 0, 1, 0);

    // att_e[b] = beta[b]^T @ criteria[b] -> fp16
    gemm_h<<<dim3(DDIM / BN, LEDIM / BM, BB), 256, GSM_TOTAL>>>(
        beTH, nullptr, 0, critTH, nullptr, atteH, LEDIM, DDIM, LCDIM,
        LCDIM, LCE, LCDIM, LCD, LED, 0, 1, 0);

    // r1 partials = rowsum(relu([attc, criteria] @ Wr + br)) (fused epilogue)
    gemm_h<<<dim3(DDIM / BN, (BB * LCDIM) / BM, 1), 256, GSM_TOTAL>>>(
        attcH, critH, DDIM, WrTH, br, r1p, BB * LCDIM, DDIM, 2 * DDIM,
        DDIM, 0, 2 * DDIM, 0, 0, 1, 0, 1);

    // r2 partials = rowsum(relu([atte, ehr] @ Wr + br))
    gemm_h<<<dim3(DDIM / BN, (BB * LEDIM) / BM, 1), 256, GSM_TOTAL>>>(
        atteH, ehrH, DDIM, WrTH, br, r2p, BB * LEDIM, DDIM, 2 * DDIM,
        DDIM, 0, 2 * DDIM, 0, 0, 1, 0, 1);

    final_kernel<<<BB, 512>>>(r1p, r2p, Wm, bm, Wo, bo, (float*)d_out);
}

// round 12
// speedup vs baseline: 2.3001x; 1.0905x over previous
#include <cuda_runtime.h>
#include <cuda_fp16.h>
#include <cstdint>

#define BB 128
#define LCDIM 256
#define LEDIM 1024
#define DDIM 256
#define MMDIM 512
#define NEGV -1e9f

// ---------------- scratch ----------------------------------------------------
// concatenated buffers so independent GEMMs merge into single launches
__device__ __align__(16) __half g_inH[(size_t)BB * (LCDIM + LEDIM) * DDIM];  // critH | ehrH
__device__ __align__(16) __half g_ceH[(size_t)BB * (LCDIM + LEDIM) * DDIM];  // cH | eH
__device__ __align__(16) __half g_attH[(size_t)BB * (LCDIM + LEDIM) * DDIM]; // attcH | atteH
__device__ __align__(16) __half g_alignH[(size_t)BB * LCDIM * LEDIM];
__device__ __align__(16) __half g_alphaH[(size_t)BB * LCDIM * LEDIM];
__device__ __align__(16) __half g_beTH[(size_t)BB * LCDIM * LEDIM];
__device__ __align__(16) __half g_ehrTH[(size_t)BB * LEDIM * DDIM];
__device__ __align__(16) __half g_critTH[(size_t)BB * LCDIM * DDIM];
__device__ __align__(16) __half g_WaTH[DDIM * DDIM];
__device__ __align__(16) __half g_WrTH[DDIM * 2 * DDIM];
__device__ float g_rp[(2 + 8) * BB * DDIM];   // r1 tiles [0,256) | r2 tiles [256,1280)
__device__ float g_colsum[BB * LEDIM];        // sum_l exp(align + negl)

// ---------------- helpers -----------------------------------------------------
__device__ __forceinline__ uint32_t smem_u32(const void* p) {
    uint32_t a;
    asm("{ .reg .u64 t; cvta.to.shared.u64 t, %1; cvt.u32.u64 %0, t; }"
        : "=r"(a) : "l"(p));
    return a;
}

#define SW128B(o) ((o) ^ (((o) >> 3) & 0x70))

__device__ __forceinline__ void ldsm4h(uint32_t& r0, uint32_t& r1, uint32_t& r2,
                                       uint32_t& r3, uint32_t addr) {
    asm volatile("ldmatrix.sync.aligned.m8n8.x4.shared.b16 {%0,%1,%2,%3}, [%4];"
                 : "=r"(r0), "=r"(r1), "=r"(r2), "=r"(r3) : "r"(addr));
}

__device__ __forceinline__ void mma16(float* c, const uint32_t* a, uint32_t b0, uint32_t b1) {
    asm volatile(
        "mma.sync.aligned.m16n8k16.row.col.f32.f16.f16.f32 "
        "{%0,%1,%2,%3}, {%4,%5,%6,%7}, {%8,%9}, {%0,%1,%2,%3};"
        : "+f"(c[0]), "+f"(c[1]), "+f"(c[2]), "+f"(c[3])
        : "r"(a[0]), "r"(a[1]), "r"(a[2]), "r"(a[3]), "r"(b0), "r"(b1));
}

#define CP16(d, g) \
    asm volatile("cp.async.cg.shared.global [%0], [%1], 16;" :: "r"(d), "l"(g))

// ---------------- FP16 tensor-core GEMM (mainloop unchanged) -------------------
// New optional epilogue: colsum != nullptr -> also accumulate per-column
// sum_row exp(fp16(acc) + (cmrow[row]?0:NEG)) into colsum[z*csN + col].
// smem-reduced (2 smem atomics/col) then 1 global atomic per CTA per col;
// 2 m-tile CTAs per column -> 2 commutative adds = deterministic.
#define BM 128
#define BN 128
#define BKH 64
#define SA_OFF(s) ((s) * 16384)
#define SB_OFF(s) (49152 + (s) * 16384)
#define GSM_TOTAL 98304

__global__ __launch_bounds__(256, 2) void gemm_h(
    const __half* __restrict__ A, const __half* __restrict__ A2, int Ksplit,
    const __half* __restrict__ B, const float* __restrict__ bias,
    void* __restrict__ Cv,
    int M, int N, int K,
    long sAm, long bsA, long sBn, long bsB, long bsC,
    int do_relu, int out_half, int sum_out,
    float* __restrict__ colsum, const int* __restrict__ cmrow, long csN)
{
    extern __shared__ char sm[];
    A += (long)blockIdx.z * bsA;
    if (A2) A2 += (long)blockIdx.z * bsA;
    B += (long)blockIdx.z * bsB;

    const int tid = threadIdx.x;
    const int lane = tid & 31;
    const int w = tid >> 5;
    const int wm = (w & 1) * 64;
    const int wn = (w >> 1) * 32;
    const int m0 = blockIdx.y * BM;
    const int n0 = blockIdx.x * BN;
    const uint32_t sb = smem_u32(sm);

    auto issueA = [&](int k0, int s) {
        const __half* Ap = A; int kb = k0;
        if (A2 && k0 >= Ksplit) { Ap = A2; kb = k0 - Ksplit; }
        uint32_t base = sb + SA_OFF(s);
#pragma unroll
        for (int i = 0; i < 4; i++) {
            int f = tid + i * 256;
            int row = f >> 3, hq = (f & 7) * 8;
            CP16(base + SW128B(row * 128 + hq * 2),
                 Ap + (long)(m0 + row) * sAm + kb + hq);
        }
    };
    auto issueB = [&](int k0, int s) {
        uint32_t base = sb + SB_OFF(s);
#pragma unroll
        for (int i = 0; i < 4; i++) {
            int f = tid + i * 256;
            int row = f >> 3, hq = (f & 7) * 8;
            CP16(base + SW128B(row * 128 + hq * 2),
                 B + (long)(n0 + row) * sBn + k0 + hq);
        }
    };

    float acc[4][4][4];
#pragma unroll
    for (int i = 0; i < 4; i++)
#pragma unroll
        for (int j = 0; j < 4; j++)
#pragma unroll
            for (int r = 0; r < 4; r++) acc[i][j][r] = 0.f;

    const int T = K / BKH;
    issueA(0, 0); issueB(0, 0);
    asm volatile("cp.async.commit_group;" ::: "memory");
    if (T > 1) {
        issueA(BKH, 1); issueB(BKH, 1);
        asm volatile("cp.async.commit_group;" ::: "memory");
    }

    for (int t = 0; t < T; t++) {
        const int s = t % 3;
        if (t == T - 1)
            asm volatile("cp.async.wait_group 0;" ::: "memory");
        else
            asm volatile("cp.async.wait_group 1;" ::: "memory");
        __syncthreads();
        if (t + 2 < T) {
            issueA((t + 2) * BKH, (t + 2) % 3);
            issueB((t + 2) * BKH, (t + 2) % 3);
            asm volatile("cp.async.commit_group;" ::: "memory");
        }

        const uint32_t abase = sb + SA_OFF(s);
        const uint32_t bbase = sb + SB_OFF(s);
#pragma unroll
        for (int ks = 0; ks < 4; ks++) {
            uint32_t a[4][4], bf[2][4];

            const int arow = lane & 15;
            const int acolh = ks * 16 + (lane >> 4) * 8;
#pragma unroll
            for (int mt = 0; mt < 4; mt++)
                ldsm4h(a[mt][0], a[mt][1], a[mt][2], a[mt][3],
                       abase + SW128B((wm + mt * 16 + arow) * 128 + acolh * 2));

            const int brow = (lane & 7) + (lane >= 16 ? 8 : 0);
            const int bcolh = ks * 16 + ((lane >> 3) & 1) * 8;
#pragma unroll
            for (int np = 0; np < 2; np++)
                ldsm4h(bf[np][0], bf[np][1], bf[np][2], bf[np][3],
                       bbase + SW128B((wn + np * 16 + brow) * 128 + bcolh * 2));

#pragma unroll
            for (int mt = 0; mt < 4; mt++)
#pragma unroll
                for (int nt = 0; nt < 4; nt++)
                    mma16(acc[mt][nt], a[mt],
                          bf[nt >> 1][(nt & 1) * 2], bf[nt >> 1][(nt & 1) * 2 + 1]);
        }
    }

    const int g = lane >> 2, tg = lane & 3;

    if (sum_out) {
        float* P = (float*)Cv + (long)(m0 / BM) * N;
#pragma unroll
        for (int nt = 0; nt < 4; nt++) {
            int col = n0 + wn + nt * 8 + tg * 2;
            float bv0 = bias ? bias[col] : 0.f;
            float bv1 = bias ? bias[col + 1] : 0.f;
            float s0 = 0.f, s1 = 0.f;
#pragma unroll
            for (int mt = 0; mt < 4; mt++)
#pragma unroll
                for (int h = 0; h < 2; h++) {
                    float v0 = acc[mt][nt][2 * h] + bv0;
                    float v1 = acc[mt][nt][2 * h + 1] + bv1;
                    if (do_relu) { v0 = fmaxf(v0, 0.f); v1 = fmaxf(v1, 0.f); }
                    s0 += v0; s1 += v1;
                }
#pragma unroll
            for (int off = 16; off >= 4; off >>= 1) {
                s0 += __shfl_xor_sync(0xffffffffu, s0, off);
                s1 += __shfl_xor_sync(0xffffffffu, s1, off);
            }
            if (g == 0) {
                atomicAdd(&P[col], s0);
                atomicAdd(&P[col + 1], s1);
            }
        }
        return;
    }

#pragma unroll
    for (int mt = 0; mt < 4; mt++) {
#pragma unroll
        for (int nt = 0; nt < 4; nt++) {
            int row = m0 + wm + mt * 16 + g;
            int col = n0 + wn + nt * 8 + tg * 2;
            float bv0 = 0.f, bv1 = 0.f;
            if (bias) { bv0 = bias[col]; bv1 = bias[col + 1]; }
#pragma unroll
            for (int h = 0; h < 2; h++) {
                long ci = (long)(row + h * 8) * N + col + (long)blockIdx.z * bsC;
                float v0 = acc[mt][nt][2 * h] + bv0;
                float v1 = acc[mt][nt][2 * h + 1] + bv1;
                if (do_relu) { v0 = fmaxf(v0, 0.f); v1 = fmaxf(v1, 0.f); }
                if (out_half) {
                    __half2 hv = __floats2half2_rn(v0, v1);
                    *reinterpret_cast<__half2*>((__half*)Cv + ci) = hv;
                } else {
                    *reinterpret_cast<float2*>((float*)Cv + ci) = make_float2(v0, v1);
                }
            }
        }
    }

    if (colsum) {
        // reuse stage smem for reduction scratch (all MMA reads done; sync first)
        __syncthreads();
        float* negs_s = reinterpret_cast<float*>(sm);          // BM floats
        float* csum_s = reinterpret_cast<float*>(sm + 512);    // BN floats
        const int* cmb = cmrow + (long)blockIdx.z * LCDIM;
        if (tid < BM) negs_s[tid] = cmb[m0 + tid] ? 0.f : NEGV;
        if (tid < BN) csum_s[tid] = 0.f;
        __syncthreads();
        float* csb = colsum + (long)blockIdx.z * csN;
#pragma unroll
        for (int nt = 0; nt < 4; nt++) {
            int coll = wn + nt * 8 + tg * 2;
            float s0 = 0.f, s1 = 0.f;
#pragma unroll
            for (int mt = 0; mt < 4; mt++)
#pragma unroll
                for (int h = 0; h < 2; h++) {
                    int row = wm + mt * 16 + g + h * 8;
                    float ng = negs_s[row];
                    // use the fp16-ROUNDED value -> consistent with alignH readers
                    float v0 = __half2float(__float2half_rn(acc[mt][nt][2 * h]));
                    float v1 = __half2float(__float2half_rn(acc[mt][nt][2 * h + 1]));
                    s0 += __expf(v0 + ng);
                    s1 += __expf(v1 + ng);
                }
#pragma unroll
            for (int off = 16; off >= 4; off >>= 1) {
                s0 += __shfl_xor_sync(0xffffffffu, s0, off);
                s1 += __shfl_xor_sync(0xffffffffu, s1, off);
            }
            if (g == 0) {
                atomicAdd(&csum_s[coll], s0);      // 2 warps (wm) per col
                atomicAdd(&csum_s[coll + 1], s1);
            }
        }
        __syncthreads();
        if (tid < BN) atomicAdd(&csb[n0 + tid], csum_s[tid]);  // 2 m-tiles per col
    }
}

// ---------------- prep: fp32 -> fp16 row-major + fp16 transposed ---------------
__global__ __launch_bounds__(256) void prep_k(const float* __restrict__ in,
                                              __half* __restrict__ outR,
                                              __half* __restrict__ outT,
                                              int R, int C, long bs)
{
    __shared__ float tile[32][33];
    in += (long)blockIdx.z * bs;
    outR += (long)blockIdx.z * bs;
    outT += (long)blockIdx.z * bs;
    int c0 = blockIdx.x * 32, r0 = blockIdx.y * 32;
#pragma unroll
    for (int j = 0; j < 32; j += 8) {
        float v = in[(long)(r0 + threadIdx.y + j) * C + c0 + threadIdx.x];
        tile[threadIdx.y + j][threadIdx.x] = v;
        outR[(long)(r0 + threadIdx.y + j) * C + c0 + threadIdx.x] = __float2half_rn(v);
    }
    __syncthreads();
#pragma unroll
    for (int j = 0; j < 32; j += 8)
        outT[(long)(c0 + threadIdx.y + j) * R + r0 + threadIdx.x] =
            __float2half_rn(tile[threadIdx.x][threadIdx.y + j]);
}

// ---------------- setup: Wa^T + Wr^T + zero (rp, colsum) -----------------------
__global__ __launch_bounds__(256) void setup_k(
    const float* __restrict__ Wa, __half* __restrict__ WaT,
    const float* __restrict__ Wr, __half* __restrict__ WrT,
    float* __restrict__ z1, int n1, float* __restrict__ z2, int n2)
{
    int ty = blockIdx.y;
    if (ty == 24) {
        int i = blockIdx.x * 256 + threadIdx.y * 32 + threadIdx.x; // 0..2047
        for (int j = i; j < n1; j += 2048) z1[j] = 0.f;
        for (int j = i; j < n2; j += 2048) z2[j] = 0.f;
        return;
    }
    const float* in; __half* out; int R, r0;
    if (ty < 8) { in = Wa; out = WaT; R = DDIM;     r0 = ty * 32; }
    else        { in = Wr; out = WrT; R = 2 * DDIM; r0 = (ty - 8) * 32; }
    const int C = DDIM;
    __shared__ float tile[32][33];
    int c0 = blockIdx.x * 32;
#pragma unroll
    for (int j = 0; j < 32; j += 8)
        tile[threadIdx.y + j][threadIdx.x] =
            in[(long)(r0 + threadIdx.y + j) * C + c0 + threadIdx.x];
    __syncthreads();
#pragma unroll
    for (int j = 0; j < 32; j += 8)
        out[(long)(c0 + threadIdx.y + j) * R + r0 + threadIdx.x] =
            __float2half_rn(tile[threadIdx.x][threadIdx.y + j]);
}

// ---------------- fused alpha + betaT (unnormalized exp; one alignH read) ------
// grid (LCDIM/32, BB). Tile 32x1024 halves, row stride 1026 (odd word stride
// -> conflict-free row AND column access). colsum precomputed by align-GEMM
// epilogue; reciprocal cached in smem.
#define ABPAD 1026
#define ABSM (32 * ABPAD * 2 + LEDIM * 4)

__global__ __launch_bounds__(256) void alphabeta_k(
    const __half* __restrict__ align,
    __half* __restrict__ alphaH, __half* __restrict__ betaT,
    const int* __restrict__ cm, const int* __restrict__ em,
    const float* __restrict__ colsum)
{
    extern __shared__ char sm[];
    __half* tile = reinterpret_cast<__half*>(sm);
    uint32_t* tw = reinterpret_cast<uint32_t*>(sm);
    float* cinv_s = reinterpret_cast<float*>(sm + 32 * ABPAD * 2);
    const int b = blockIdx.y, l0 = blockIdx.x * 32;
    const int tid = threadIdx.x, lane = tid & 31, w = tid >> 5;
    const __half* al = align + ((long)b * LCDIM + l0) * LEDIM;

    // load 32x1024 halves: LDG.128, 4x STS.32 (4B-aligned for every row)
#pragma unroll
    for (int i = 0; i < 16; i++) {
        int f = tid + i * 256;
        int row = f >> 7, seg = (f & 127) * 4;
        uint4 v = *reinterpret_cast<const uint4*>(&al[(long)row * LEDIM + seg * 2]);
        uint32_t* d = tw + row * (ABPAD / 2) + seg;
        d[0] = v.x; d[1] = v.y; d[2] = v.z; d[3] = v.w;
    }
    for (int i = tid; i < LEDIM; i += 256)
        cinv_s[i] = 1.f / colsum[(long)b * LEDIM + i];
    __syncthreads();

    float negs[32];
#pragma unroll
    for (int i = 0; i < 32; i++)
        negs[i] = em[b * LEDIM + lane + i * 32] ? 0.f : NEGV;

    // Phase A: alpha rows (unnormalized exp, single sum reduction)
#pragma unroll 1
    for (int r = 0; r < 4; r++) {
        int row = w * 4 + r;
        float vals[32];
        float sum = 0.f;
#pragma unroll
        for (int i = 0; i < 32; i++) {
            float x = __half2float(tile[row * ABPAD + lane + i * 32]);
            vals[i] = __expf(x + negs[i]);
            sum += vals[i];
        }
#pragma unroll
        for (int off = 16; off; off >>= 1)
            sum += __shfl_xor_sync(0xffffffffu, sum, off);
        float inv = 1.f / sum;
        long gbase = ((long)b * LCDIM + l0 + row) * LEDIM;
#pragma unroll
        for (int i = 0; i < 32; i++)
            alphaH[gbase + lane + i * 32] = __float2half_rn(vals[i] * inv);
    }

    // Phase B: betaT via colsum reciprocal
    float negl = cm[b * LCDIM + l0 + lane] ? 0.f : NEGV;
    __half* outb = betaT + (long)b * LCDIM * LEDIM + l0 + lane;
#pragma unroll 4
    for (int i = 0; i < 128; i++) {
        int e = w * 128 + i;
        float x = __half2float(tile[lane * ABPAD + e]);
        float v = __expf(x + negl) * cinv_s[e];
        outb[(long)e * LCDIM] = __float2half_rn(v);
    }
}

// ---------------- final MLP ----------------------------------------------------
__global__ __launch_bounds__(512) void final_kernel(
    const float* __restrict__ r1p, const float* __restrict__ r2p,
    const float* __restrict__ Wm, const float* __restrict__ bm,
    const float* __restrict__ Wo, const float* __restrict__ bo,
    float* __restrict__ out)
{
    int b = blockIdx.x;
    int t = threadIdx.x;

    __shared__ float ms[4 * DDIM];
    __shared__ float hs[MMDIM];

    if (t < DDIM) {
        float r1 = 0.f, r2 = 0.f;
#pragma unroll
        for (int s = 0; s < 2; s++) r1 += r1p[(b * 2 + s) * DDIM + t];
#pragma unroll
        for (int s = 0; s < 8; s++) r2 += r2p[(b * 8 + s) * DDIM + t];
        ms[t] = r1;
        ms[DDIM + t] = r2;
        ms[2 * DDIM + t] = r1 * r2;
        ms[3 * DDIM + t] = r1 - r2;
    }
    __syncthreads();

    float acc = bm[t];
#pragma unroll 8
    for (int k = 0; k < 4 * DDIM; k++) acc += ms[k] * Wm[(long)k * MMDIM + t];
    hs[t] = fmaxf(acc, 0.f);
    __syncthreads();

    int w = t >> 5, lane = t & 31;
    if (w < 3) {
        float s = 0.f;
        for (int j = lane; j < MMDIM; j += 32) s += hs[j] * Wo[j * 3 + w];
#pragma unroll
        for (int off = 16; off; off >>= 1) s += __shfl_down_sync(0xffffffffu, s, off);
        if (lane == 0) out[b * 3 + w] = s + bo[w];
    }
}

// ---------------- launch -------------------------------------------------------
extern "C" void kernel_launch(void* const* d_in, const int* in_sizes, int n_in,
                              void* d_out, int out_size)
{
    const float *criteria, *ehr, *Wa, *ba, *Wr, *br, *Wm, *bm, *Wo, *bo;
    const int *cmask, *emask;

    if (in_sizes[2] == BB * LCDIM) {
        criteria = (const float*)d_in[0]; ehr = (const float*)d_in[1];
        cmask = (const int*)d_in[2]; emask = (const int*)d_in[3];
        Wa = (const float*)d_in[4]; ba = (const float*)d_in[5];
        Wr = (const float*)d_in[6]; br = (const float*)d_in[7];
        Wm = (const float*)d_in[8]; bm = (const float*)d_in[9];
        Wo = (const float*)d_in[10]; bo = (const float*)d_in[11];
    } else {
        criteria = (const float*)d_in[0]; ehr = (const float*)d_in[1];
        Wa = (const float*)d_in[2]; ba = (const float*)d_in[3];
        Wr = (const float*)d_in[4]; br = (const float*)d_in[5];
        Wm = (const float*)d_in[6]; bm = (const float*)d_in[7];
        Wo = (const float*)d_in[8]; bo = (const float*)d_in[9];
        cmask = (const int*)d_in[10]; emask = (const int*)d_in[11];
    }

    __half *inH, *ceH, *attH, *alignH, *alphaH, *beTH, *ehrTH, *critTH, *WaTH, *WrTH;
    float *rp, *colsum;
    cudaGetSymbolAddress((void**)&inH,    g_inH);
    cudaGetSymbolAddress((void**)&ceH,    g_ceH);
    cudaGetSymbolAddress((void**)&attH,   g_attH);
    cudaGetSymbolAddress((void**)&alignH, g_alignH);
    cudaGetSymbolAddress((void**)&alphaH, g_alphaH);
    cudaGetSymbolAddress((void**)&beTH,   g_beTH);
    cudaGetSymbolAddress((void**)&ehrTH,  g_ehrTH);
    cudaGetSymbolAddress((void**)&critTH, g_critTH);
    cudaGetSymbolAddress((void**)&WaTH,   g_WaTH);
    cudaGetSymbolAddress((void**)&WrTH,   g_WrTH);
    cudaGetSymbolAddress((void**)&rp,     g_rp);
    cudaGetSymbolAddress((void**)&colsum, g_colsum);

    const long LCD = (long)LCDIM * DDIM;   // 65536
    const long LED = (long)LEDIM * DDIM;   // 262144
    const long LCE = (long)LCDIM * LEDIM;  // 262144

    __half* critH = inH;
    __half* ehrH  = inH + (size_t)BB * LCD;
    __half* cH    = ceH;
    __half* eH    = ceH + (size_t)BB * LCD;
    __half* attcH = attH;
    __half* atteH = attH + (size_t)BB * LCD;
    float*  r1p   = rp;
    float*  r2p   = rp + (size_t)BB * 2 * DDIM;

    cudaFuncSetAttribute(gemm_h, cudaFuncAttributeMaxDynamicSharedMemorySize,
                         GSM_TOTAL);
    cudaFuncSetAttribute(alphabeta_k, cudaFuncAttributeMaxDynamicSharedMemorySize,
                         ABSM);

    dim3 tb(32, 8);
    const int MTOT = BB * (LCDIM + LEDIM);          // 163840 rows, 1280 tiles

    // prologue
    prep_k<<<dim3(8, 8, BB),  tb>>>(criteria, critH, critTH, LCDIM, DDIM, LCD);
    prep_k<<<dim3(8, 32, BB), tb>>>(ehr, ehrH, ehrTH, LEDIM, DDIM, LED);
    setup_k<<<dim3(8, 25), tb>>>(Wa, WaTH, Wr, WrTH,
                                 rp, (2 + 8) * BB * DDIM, colsum, BB * LEDIM);

    // [c ; e] = relu([criteria; ehr] @ Wa + ba) -> fp16, ONE launch
    gemm_h<<<dim3(DDIM / BN, MTOT / BM, 1), 256, GSM_TOTAL>>>(
        inH, nullptr, 0, WaTH, ba, ceH, MTOT, DDIM, DDIM,
        DDIM, 0, DDIM, 0, 0, 1, 1, 0, nullptr, nullptr, 0);

    // align[b] = c[b] @ e[b]^T -> fp16 + fused column exp-sums
    gemm_h<<<dim3(LEDIM / BN, LCDIM / BM, BB), 256, GSM_TOTAL>>>(
        cH, nullptr, 0, eH, nullptr, alignH, LCDIM, LEDIM, DDIM,
        DDIM, LCD, DDIM, LED, LCE, 0, 1, 0, colsum, cmask, LEDIM);

    // fused alpha + betaT (single alignH read, unnormalized exp)
    alphabeta_k<<<dim3(LCDIM / 32, BB), 256, ABSM>>>(
        alignH, alphaH, beTH, cmask, emask, colsum);

    // att_c[b] = alpha[b] @ ehr[b] -> fp16
    gemm_h<<<dim3(DDIM / BN, LCDIM / BM, BB), 256, GSM_TOTAL>>>(
        alphaH, nullptr, 0, ehrTH, nullptr, attcH, LCDIM, DDIM, LEDIM,
        LEDIM, LCE, LEDIM, LED, LCD, 0, 1, 0, nullptr, nullptr, 0);

    // att_e[b] = beta[b]^T @ criteria[b] -> fp16
    gemm_h<<<dim3(DDIM / BN, LEDIM / BM, BB), 256, GSM_TOTAL>>>(
        beTH, nullptr, 0, critTH, nullptr, atteH, LEDIM, DDIM, LCDIM,
        LCDIM, LCE, LCDIM, LCD, LED, 0, 1, 0, nullptr, nullptr, 0);

    // [r1p ; r2p] = rowsum(relu([att ; in] @ Wr + br)), ONE launch
    gemm_h<<<dim3(DDIM / BN, MTOT / BM, 1), 256, GSM_TOTAL>>>(
        attH, inH, DDIM, WrTH, br, rp, MTOT, DDIM, 2 * DDIM,
        DDIM, 0, 2 * DDIM, 0, 0, 1, 0, 1, nullptr, nullptr, 0);

    final_kernel<<<BB, 512>>>(r1p, r2p, Wm, bm, Wo, bo, (float*)d_out);
}

// round 13
// speedup vs baseline: 2.3597x; 1.0259x over previous
#include <cuda_runtime.h>
#include <cuda_fp16.h>
#include <cstdint>

#define BB 128
#define LCDIM 256
#define LEDIM 1024
#define DDIM 256
#define MMDIM 512
#define NEGV -1e9f

// ---------------- scratch ----------------------------------------------------
__device__ __align__(16) __half g_inH[(size_t)BB * (LCDIM + LEDIM) * DDIM];  // critH | ehrH
__device__ __align__(16) __half g_ceH[(size_t)BB * (LCDIM + LEDIM) * DDIM];  // cH | eH
__device__ __align__(16) __half g_attH[(size_t)BB * (LCDIM + LEDIM) * DDIM]; // attcH | atteH
__device__ __align__(16) __half g_alignH[(size_t)BB * LCDIM * LEDIM];
__device__ __align__(16) __half g_alphaH[(size_t)BB * LCDIM * LEDIM];
__device__ __align__(16) __half g_beTH[(size_t)BB * LCDIM * LEDIM];
__device__ __align__(16) __half g_ehrTH[(size_t)BB * LEDIM * DDIM];
__device__ __align__(16) __half g_critTH[(size_t)BB * LCDIM * DDIM];
__device__ __align__(16) __half g_WaTH[DDIM * DDIM];
__device__ __align__(16) __half g_WrTH[DDIM * 2 * DDIM];
__device__ float g_rp[(2 + 8) * BB * DDIM];
__device__ float g_colsum[BB * LEDIM];

// ---------------- helpers -----------------------------------------------------
__device__ __forceinline__ uint32_t smem_u32(const void* p) {
    uint32_t a;
    asm("{ .reg .u64 t; cvta.to.shared.u64 t, %1; cvt.u32.u64 %0, t; }"
        : "=r"(a) : "l"(p));
    return a;
}

#define SW128B(o) ((o) ^ (((o) >> 3) & 0x70))

__device__ __forceinline__ void ldsm4h(uint32_t& r0, uint32_t& r1, uint32_t& r2,
                                       uint32_t& r3, uint32_t addr) {
    asm volatile("ldmatrix.sync.aligned.m8n8.x4.shared.b16 {%0,%1,%2,%3}, [%4];"
                 : "=r"(r0), "=r"(r1), "=r"(r2), "=r"(r3) : "r"(addr));
}

__device__ __forceinline__ void mma16(float* c, const uint32_t* a, uint32_t b0, uint32_t b1) {
    asm volatile(
        "mma.sync.aligned.m16n8k16.row.col.f32.f16.f16.f32 "
        "{%0,%1,%2,%3}, {%4,%5,%6,%7}, {%8,%9}, {%0,%1,%2,%3};"
        : "+f"(c[0]), "+f"(c[1]), "+f"(c[2]), "+f"(c[3])
        : "r"(a[0]), "r"(a[1]), "r"(a[2]), "r"(a[3]), "r"(b0), "r"(b1));
}

#define CP16(d, g) \
    asm volatile("cp.async.cg.shared.global [%0], [%1], 16;" :: "r"(d), "l"(g))

// ---------------- FP16 tensor-core GEMM core (validated mainloop) --------------
// All pointers pre-offset by batch. One call site per wrapper kernel.
#define BM 128
#define BN 128
#define BKH 64
#define SA_OFF(s) ((s) * 16384)
#define SB_OFF(s) (49152 + (s) * 16384)
#define GSM_TOTAL 98304

__device__ __forceinline__ void gemm_core(
    const __half* __restrict__ A, const __half* __restrict__ A2, int Ksplit,
    const __half* __restrict__ B, const float* __restrict__ bias,
    void* __restrict__ Cv,
    int N, int K, long sAm, long sBn,
    int do_relu, int out_half, int sum_out,
    float* __restrict__ colsum, const int* __restrict__ cmrow,
    int m0, int n0, char* sm)
{
    const int tid = threadIdx.x;
    const int lane = tid & 31;
    const int w = tid >> 5;
    const int wm = (w & 1) * 64;
    const int wn = (w >> 1) * 32;
    const uint32_t sb = smem_u32(sm);

    auto issueA = [&](int k0, int s) {
        const __half* Ap = A; int kb = k0;
        if (A2 && k0 >= Ksplit) { Ap = A2; kb = k0 - Ksplit; }
        uint32_t base = sb + SA_OFF(s);
#pragma unroll
        for (int i = 0; i < 4; i++) {
            int f = tid + i * 256;
            int row = f >> 3, hq = (f & 7) * 8;
            CP16(base + SW128B(row * 128 + hq * 2),
                 Ap + (long)(m0 + row) * sAm + kb + hq);
        }
    };
    auto issueB = [&](int k0, int s) {
        uint32_t base = sb + SB_OFF(s);
#pragma unroll
        for (int i = 0; i < 4; i++) {
            int f = tid + i * 256;
            int row = f >> 3, hq = (f & 7) * 8;
            CP16(base + SW128B(row * 128 + hq * 2),
                 B + (long)(n0 + row) * sBn + k0 + hq);
        }
    };

    float acc[4][4][4];
#pragma unroll
    for (int i = 0; i < 4; i++)
#pragma unroll
        for (int j = 0; j < 4; j++)
#pragma unroll
            for (int r = 0; r < 4; r++) acc[i][j][r] = 0.f;

    const int T = K / BKH;
    issueA(0, 0); issueB(0, 0);
    asm volatile("cp.async.commit_group;" ::: "memory");
    if (T > 1) {
        issueA(BKH, 1); issueB(BKH, 1);
        asm volatile("cp.async.commit_group;" ::: "memory");
    }

    for (int t = 0; t < T; t++) {
        const int s = t % 3;
        if (t == T - 1)
            asm volatile("cp.async.wait_group 0;" ::: "memory");
        else
            asm volatile("cp.async.wait_group 1;" ::: "memory");
        __syncthreads();
        if (t + 2 < T) {
            issueA((t + 2) * BKH, (t + 2) % 3);
            issueB((t + 2) * BKH, (t + 2) % 3);
            asm volatile("cp.async.commit_group;" ::: "memory");
        }

        const uint32_t abase = sb + SA_OFF(s);
        const uint32_t bbase = sb + SB_OFF(s);
#pragma unroll
        for (int ks = 0; ks < 4; ks++) {
            uint32_t a[4][4], bf[2][4];

            const int arow = lane & 15;
            const int acolh = ks * 16 + (lane >> 4) * 8;
#pragma unroll
            for (int mt = 0; mt < 4; mt++)
                ldsm4h(a[mt][0], a[mt][1], a[mt][2], a[mt][3],
                       abase + SW128B((wm + mt * 16 + arow) * 128 + acolh * 2));

            const int brow = (lane & 7) + (lane >= 16 ? 8 : 0);
            const int bcolh = ks * 16 + ((lane >> 3) & 1) * 8;
#pragma unroll
            for (int np = 0; np < 2; np++)
                ldsm4h(bf[np][0], bf[np][1], bf[np][2], bf[np][3],
                       bbase + SW128B((wn + np * 16 + brow) * 128 + bcolh * 2));

#pragma unroll
            for (int mt = 0; mt < 4; mt++)
#pragma unroll
                for (int nt = 0; nt < 4; nt++)
                    mma16(acc[mt][nt], a[mt],
                          bf[nt >> 1][(nt & 1) * 2], bf[nt >> 1][(nt & 1) * 2 + 1]);
        }
    }

    const int g = lane >> 2, tg = lane & 3;

    if (sum_out) {
        float* P = (float*)Cv + (long)(m0 / BM) * N;
#pragma unroll
        for (int nt = 0; nt < 4; nt++) {
            int col = n0 + wn + nt * 8 + tg * 2;
            float bv0 = bias ? bias[col] : 0.f;
            float bv1 = bias ? bias[col + 1] : 0.f;
            float s0 = 0.f, s1 = 0.f;
#pragma unroll
            for (int mt = 0; mt < 4; mt++)
#pragma unroll
                for (int h = 0; h < 2; h++) {
                    float v0 = acc[mt][nt][2 * h] + bv0;
                    float v1 = acc[mt][nt][2 * h + 1] + bv1;
                    if (do_relu) { v0 = fmaxf(v0, 0.f); v1 = fmaxf(v1, 0.f); }
                    s0 += v0; s1 += v1;
                }
#pragma unroll
            for (int off = 16; off >= 4; off >>= 1) {
                s0 += __shfl_xor_sync(0xffffffffu, s0, off);
                s1 += __shfl_xor_sync(0xffffffffu, s1, off);
            }
            if (g == 0) {
                atomicAdd(&P[col], s0);
                atomicAdd(&P[col + 1], s1);
            }
        }
        return;
    }

#pragma unroll
    for (int mt = 0; mt < 4; mt++) {
#pragma unroll
        for (int nt = 0; nt < 4; nt++) {
            int row = m0 + wm + mt * 16 + g;
            int col = n0 + wn + nt * 8 + tg * 2;
            float bv0 = 0.f, bv1 = 0.f;
            if (bias) { bv0 = bias[col]; bv1 = bias[col + 1]; }
#pragma unroll
            for (int h = 0; h < 2; h++) {
                long ci = (long)(row + h * 8) * N + col;
                float v0 = acc[mt][nt][2 * h] + bv0;
                float v1 = acc[mt][nt][2 * h + 1] + bv1;
                if (do_relu) { v0 = fmaxf(v0, 0.f); v1 = fmaxf(v1, 0.f); }
                if (out_half) {
                    __half2 hv = __floats2half2_rn(v0, v1);
                    *reinterpret_cast<__half2*>((__half*)Cv + ci) = hv;
                } else {
                    *reinterpret_cast<float2*>((float*)Cv + ci) = make_float2(v0, v1);
                }
            }
        }
    }

    if (colsum) {
        __syncthreads();
        float* negs_s = reinterpret_cast<float*>(sm);
        float* csum_s = reinterpret_cast<float*>(sm + 512);
        if (tid < BM) negs_s[tid] = cmrow[m0 + tid] ? 0.f : NEGV;
        if (tid < BN) csum_s[tid] = 0.f;
        __syncthreads();
#pragma unroll
        for (int nt = 0; nt < 4; nt++) {
            int coll = wn + nt * 8 + tg * 2;
            float s0 = 0.f, s1 = 0.f;
#pragma unroll
            for (int mt = 0; mt < 4; mt++)
#pragma unroll
                for (int h = 0; h < 2; h++) {
                    int row = wm + mt * 16 + g + h * 8;
                    float ng = negs_s[row];
                    float v0 = __half2float(__float2half_rn(acc[mt][nt][2 * h]));
                    float v1 = __half2float(__float2half_rn(acc[mt][nt][2 * h + 1]));
                    s0 += __expf(v0 + ng);
                    s1 += __expf(v1 + ng);
                }
#pragma unroll
            for (int off = 16; off >= 4; off >>= 1) {
                s0 += __shfl_xor_sync(0xffffffffu, s0, off);
                s1 += __shfl_xor_sync(0xffffffffu, s1, off);
            }
            if (g == 0) {
                atomicAdd(&csum_s[coll], s0);
                atomicAdd(&csum_s[coll + 1], s1);
            }
        }
        __syncthreads();
        if (tid < BN) atomicAdd(&colsum[n0 + tid], csum_s[tid]);
    }
}

// ---------------- generic wrapper (3-D grid) -----------------------------------
__global__ __launch_bounds__(256, 2) void gemm_h(
    const __half* __restrict__ A, const __half* __restrict__ A2, int Ksplit,
    const __half* __restrict__ B, const float* __restrict__ bias,
    void* __restrict__ Cv,
    int N, int K, long sAm, long bsA, long sBn, long bsB, long bsC,
    int do_relu, int out_half, int sum_out, int elem4,
    float* __restrict__ colsum, const int* __restrict__ cmrow, long csN)
{
    extern __shared__ char sm[];
    long z = blockIdx.z;
    const __half* Ao = A + z * bsA;
    const __half* A2o = A2 ? A2 + z * bsA : nullptr;
    const __half* Bo = B + z * bsB;
    char* Co = (char*)Cv + z * bsC * elem4;
    float* cso = colsum ? colsum + z * csN : nullptr;
    const int* cmo = cmrow ? cmrow + z * LCDIM : nullptr;
    gemm_core(Ao, A2o, Ksplit, Bo, bias, (void*)Co, N, K, sAm, sBn,
              do_relu, out_half, sum_out, cso, cmo,
              blockIdx.y * BM, blockIdx.x * BN, sm);
}

// ---------------- merged att wrapper (1-D grid, att_c tiles first) -------------
__global__ __launch_bounds__(256, 2) void gemm_att(
    const __half* __restrict__ alphaH, const __half* __restrict__ ehrTH,
    __half* __restrict__ attcH,
    const __half* __restrict__ beTH, const __half* __restrict__ critTH,
    __half* __restrict__ atteH)
{
    extern __shared__ char sm[];
    const long LCD = (long)LCDIM * DDIM;
    const long LED = (long)LEDIM * DDIM;
    const long LCE = (long)LCDIM * LEDIM;
    int idx = blockIdx.x;
    const __half *A, *B; __half* C;
    int K; long sAm, sBn; int m0;
    if (idx < 512) {
        // att_c: per batch M=256 (2 m-tiles) x N=256 (2 n-tiles), K=1024
        int z = idx >> 2, r = idx & 3;
        A = alphaH + (long)z * LCE; sAm = LEDIM;
        B = ehrTH + (long)z * LED;  sBn = LEDIM;
        C = attcH + (long)z * LCD;
        K = LEDIM; m0 = (r >> 1) * BM;
        gemm_core(A, nullptr, 0, B, nullptr, C, DDIM, K, sAm, sBn,
                  0, 1, 0, nullptr, nullptr, m0, (r & 1) * BN, sm);
    } else {
        // att_e: per batch M=1024 (8 m-tiles) x N=256 (2 n-tiles), K=256
        int i2 = idx - 512;
        int z = i2 >> 4, r = i2 & 15;
        A = beTH + (long)z * LCE;   sAm = LCDIM;
        B = critTH + (long)z * LCD; sBn = LCDIM;
        C = atteH + (long)z * LED;
        K = LCDIM; m0 = (r >> 1) * BM;
        gemm_core(A, nullptr, 0, B, nullptr, C, DDIM, K, sAm, sBn,
                  0, 1, 0, nullptr, nullptr, m0, (r & 1) * BN, sm);
    }
}

// ---------------- merged prep: both inputs, fp16 row + fp16 transposed ---------
__global__ __launch_bounds__(256) void prep2_k(
    const float* __restrict__ crit, __half* __restrict__ critH,
    __half* __restrict__ critTH,
    const float* __restrict__ ehr, __half* __restrict__ ehrH,
    __half* __restrict__ ehrTH)
{
    __shared__ float tile[32][33];
    const long LCD = (long)LCDIM * DDIM, LED = (long)LEDIM * DDIM;
    int b = blockIdx.z, ty = blockIdx.y;
    const float* in; __half *outR, *outT; int R, r0;
    if (ty < 8) {
        in = crit + b * LCD; outR = critH + b * LCD; outT = critTH + b * LCD;
        R = LCDIM; r0 = ty * 32;
    } else {
        in = ehr + b * LED; outR = ehrH + b * LED; outT = ehrTH + b * LED;
        R = LEDIM; r0 = (ty - 8) * 32;
    }
    const int C = DDIM;
    int c0 = blockIdx.x * 32;
#pragma unroll
    for (int j = 0; j < 32; j += 8) {
        float v = in[(long)(r0 + threadIdx.y + j) * C + c0 + threadIdx.x];
        tile[threadIdx.y + j][threadIdx.x] = v;
        outR[(long)(r0 + threadIdx.y + j) * C + c0 + threadIdx.x] = __float2half_rn(v);
    }
    __syncthreads();
#pragma unroll
    for (int j = 0; j < 32; j += 8)
        outT[(long)(c0 + threadIdx.y + j) * R + r0 + threadIdx.x] =
            __float2half_rn(tile[threadIdx.x][threadIdx.y + j]);
}

// ---------------- setup: Wa^T + Wr^T + zero (rp, colsum) -----------------------
__global__ __launch_bounds__(256) void setup_k(
    const float* __restrict__ Wa, __half* __restrict__ WaT,
    const float* __restrict__ Wr, __half* __restrict__ WrT,
    float* __restrict__ z1, int n1, float* __restrict__ z2, int n2)
{
    int ty = blockIdx.y;
    if (ty == 24) {
        int i = blockIdx.x * 256 + threadIdx.y * 32 + threadIdx.x;
        for (int j = i; j < n1; j += 2048) z1[j] = 0.f;
        for (int j = i; j < n2; j += 2048) z2[j] = 0.f;
        return;
    }
    const float* in; __half* out; int R, r0;
    if (ty < 8) { in = Wa; out = WaT; R = DDIM;     r0 = ty * 32; }
    else        { in = Wr; out = WrT; R = 2 * DDIM; r0 = (ty - 8) * 32; }
    const int C = DDIM;
    __shared__ float tile[32][33];
    int c0 = blockIdx.x * 32;
#pragma unroll
    for (int j = 0; j < 32; j += 8)
        tile[threadIdx.y + j][threadIdx.x] =
            in[(long)(r0 + threadIdx.y + j) * C + c0 + threadIdx.x];
    __syncthreads();
#pragma unroll
    for (int j = 0; j < 32; j += 8)
        out[(long)(c0 + threadIdx.y + j) * R + r0 + threadIdx.x] =
            __float2half_rn(tile[threadIdx.x][threadIdx.y + j]);
}

// ---------------- fused alpha + betaT (unnormalized exp; one alignH read) ------
#define ABPAD 1026
#define ABSM (32 * ABPAD * 2 + LEDIM * 4)

__global__ __launch_bounds__(256) void alphabeta_k(
    const __half* __restrict__ align,
    __half* __restrict__ alphaH, __half* __restrict__ betaT,
    const int* __restrict__ cm, const int* __restrict__ em,
    const float* __restrict__ colsum)
{
    extern __shared__ char sm[];
    __half* tile = reinterpret_cast<__half*>(sm);
    uint32_t* tw = reinterpret_cast<uint32_t*>(sm);
    float* cinv_s = reinterpret_cast<float*>(sm + 32 * ABPAD * 2);
    const int b = blockIdx.y, l0 = blockIdx.x * 32;
    const int tid = threadIdx.x, lane = tid & 31, w = tid >> 5;
    const __half* al = align + ((long)b * LCDIM + l0) * LEDIM;

#pragma unroll
    for (int i = 0; i < 16; i++) {
        int f = tid + i * 256;
        int row = f >> 7, seg = (f & 127) * 4;
        uint4 v = *reinterpret_cast<const uint4*>(&al[(long)row * LEDIM + seg * 2]);
        uint32_t* d = tw + row * (ABPAD / 2) + seg;
        d[0] = v.x; d[1] = v.y; d[2] = v.z; d[3] = v.w;
    }
    for (int i = tid; i < LEDIM; i += 256)
        cinv_s[i] = 1.f / colsum[(long)b * LEDIM + i];
    __syncthreads();

    float negs[32];
#pragma unroll
    for (int i = 0; i < 32; i++)
        negs[i] = em[b * LEDIM + lane + i * 32] ? 0.f : NEGV;

#pragma unroll 1
    for (int r = 0; r < 4; r++) {
        int row = w * 4 + r;
        float vals[32];
        float sum = 0.f;
#pragma unroll
        for (int i = 0; i < 32; i++) {
            float x = __half2float(tile[row * ABPAD + lane + i * 32]);
            vals[i] = __expf(x + negs[i]);
            sum += vals[i];
        }
#pragma unroll
        for (int off = 16; off; off >>= 1)
            sum += __shfl_xor_sync(0xffffffffu, sum, off);
        float inv = 1.f / sum;
        long gbase = ((long)b * LCDIM + l0 + row) * LEDIM;
#pragma unroll
        for (int i = 0; i < 32; i++)
            alphaH[gbase + lane + i * 32] = __float2half_rn(vals[i] * inv);
    }

    float negl = cm[b * LCDIM + l0 + lane] ? 0.f : NEGV;
    __half* outb = betaT + (long)b * LCDIM * LEDIM + l0 + lane;
#pragma unroll 4
    for (int i = 0; i < 128; i++) {
        int e = w * 128 + i;
        float x = __half2float(tile[lane * ABPAD + e]);
        float v = __expf(x + negl) * cinv_s[e];
        outb[(long)e * LCDIM] = __float2half_rn(v);
    }
}

// ---------------- final MLP ----------------------------------------------------
__global__ __launch_bounds__(512) void final_kernel(
    const float* __restrict__ r1p, const float* __restrict__ r2p,
    const float* __restrict__ Wm, const float* __restrict__ bm,
    const float* __restrict__ Wo, const float* __restrict__ bo,
    float* __restrict__ out)
{
    int b = blockIdx.x;
    int t = threadIdx.x;

    __shared__ float ms[4 * DDIM];
    __shared__ float hs[MMDIM];

    if (t < DDIM) {
        float r1 = 0.f, r2 = 0.f;
#pragma unroll
        for (int s = 0; s < 2; s++) r1 += r1p[(b * 2 + s) * DDIM + t];
#pragma unroll
        for (int s = 0; s < 8; s++) r2 += r2p[(b * 8 + s) * DDIM + t];
        ms[t] = r1;
        ms[DDIM + t] = r2;
        ms[2 * DDIM + t] = r1 * r2;
        ms[3 * DDIM + t] = r1 - r2;
    }
    __syncthreads();

    float acc = bm[t];
#pragma unroll 8
    for (int k = 0; k < 4 * DDIM; k++) acc += ms[k] * Wm[(long)k * MMDIM + t];
    hs[t] = fmaxf(acc, 0.f);
    __syncthreads();

    int w = t >> 5, lane = t & 31;
    if (w < 3) {
        float s = 0.f;
        for (int j = lane; j < MMDIM; j += 32) s += hs[j] * Wo[j * 3 + w];
#pragma unroll
        for (int off = 16; off; off >>= 1) s += __shfl_down_sync(0xffffffffu, s, off);
        if (lane == 0) out[b * 3 + w] = s + bo[w];
    }
}

// ---------------- launch -------------------------------------------------------
extern "C" void kernel_launch(void* const* d_in, const int* in_sizes, int n_in,
                              void* d_out, int out_size)
{
    const float *criteria, *ehr, *Wa, *ba, *Wr, *br, *Wm, *bm, *Wo, *bo;
    const int *cmask, *emask;

    if (in_sizes[2] == BB * LCDIM) {
        criteria = (const float*)d_in[0]; ehr = (const float*)d_in[1];
        cmask = (const int*)d_in[2]; emask = (const int*)d_in[3];
        Wa = (const float*)d_in[4]; ba = (const float*)d_in[5];
        Wr = (const float*)d_in[6]; br = (const float*)d_in[7];
        Wm = (const float*)d_in[8]; bm = (const float*)d_in[9];
        Wo = (const float*)d_in[10]; bo = (const float*)d_in[11];
    } else {
        criteria = (const float*)d_in[0]; ehr = (const float*)d_in[1];
        Wa = (const float*)d_in[2]; ba = (const float*)d_in[3];
        Wr = (const float*)d_in[4]; br = (const float*)d_in[5];
        Wm = (const float*)d_in[6]; bm = (const float*)d_in[7];
        Wo = (const float*)d_in[8]; bo = (const float*)d_in[9];
        cmask = (const int*)d_in[10]; emask = (const int*)d_in[11];
    }

    __half *inH, *ceH, *attH, *alignH, *alphaH, *beTH, *ehrTH, *critTH, *WaTH, *WrTH;
    float *rp, *colsum;
    cudaGetSymbolAddress((void**)&inH,    g_inH);
    cudaGetSymbolAddress((void**)&ceH,    g_ceH);
    cudaGetSymbolAddress((void**)&attH,   g_attH);
    cudaGetSymbolAddress((void**)&alignH, g_alignH);
    cudaGetSymbolAddress((void**)&alphaH, g_alphaH);
    cudaGetSymbolAddress((void**)&beTH,   g_beTH);
    cudaGetSymbolAddress((void**)&ehrTH,  g_ehrTH);
    cudaGetSymbolAddress((void**)&critTH, g_critTH);
    cudaGetSymbolAddress((void**)&WaTH,   g_WaTH);
    cudaGetSymbolAddress((void**)&WrTH,   g_WrTH);
    cudaGetSymbolAddress((void**)&rp,     g_rp);
    cudaGetSymbolAddress((void**)&colsum, g_colsum);

    const long LCD = (long)LCDIM * DDIM;   // 65536
    const long LED = (long)LEDIM * DDIM;   // 262144
    const long LCE = (long)LCDIM * LEDIM;  // 262144

    __half* critH = inH;
    __half* ehrH  = inH + (size_t)BB * LCD;
    __half* cH    = ceH;
    __half* eH    = ceH + (size_t)BB * LCD;
    float*  r1p   = rp;
    float*  r2p   = rp + (size_t)BB * 2 * DDIM;

    cudaFuncSetAttribute(gemm_h, cudaFuncAttributeMaxDynamicSharedMemorySize,
                         GSM_TOTAL);
    cudaFuncSetAttribute(gemm_att, cudaFuncAttributeMaxDynamicSharedMemorySize,
                         GSM_TOTAL);
    cudaFuncSetAttribute(alphabeta_k, cudaFuncAttributeMaxDynamicSharedMemorySize,
                         ABSM);

    dim3 tb(32, 8);
    const int MTOT = BB * (LCDIM + LEDIM);          // 163840 rows, 1280 tiles

    // prologue: merged prep + setup
    prep2_k<<<dim3(8, 40, BB), tb>>>(criteria, critH, critTH, ehr, ehrH, ehrTH);
    setup_k<<<dim3(8, 25), tb>>>(Wa, WaTH, Wr, WrTH,
                                 rp, (2 + 8) * BB * DDIM, colsum, BB * LEDIM);

    // [c ; e] = relu([criteria; ehr] @ Wa + ba) -> fp16
    gemm_h<<<dim3(DDIM / BN, MTOT / BM, 1), 256, GSM_TOTAL>>>(
        inH, nullptr, 0, WaTH, ba, ceH, DDIM, DDIM,
        DDIM, 0, DDIM, 0, 0, 1, 1, 0, 2, nullptr, nullptr, 0);

    // align[b] = c[b] @ e[b]^T -> fp16 + fused column exp-sums
    gemm_h<<<dim3(LEDIM / BN, LCDIM / BM, BB), 256, GSM_TOTAL>>>(
        cH, nullptr, 0, eH, nullptr, alignH, LEDIM, DDIM,
        DDIM, LCD, DDIM, LED, LCE, 0, 1, 0, 2, colsum, cmask, LEDIM);

    // fused alpha + betaT (single alignH read)
    alphabeta_k<<<dim3(LCDIM / 32, BB), 256, ABSM>>>(
        alignH, alphaH, beTH, cmask, emask, colsum);

    // merged att_c + att_e (one launch, long-K tiles first)
    gemm_att<<<2560, 256, GSM_TOTAL>>>(alphaH, ehrTH, attH,
                                       beTH, critTH, attH + (size_t)BB * LCD);

    // [r1p ; r2p] = rowsum(relu([att ; in] @ Wr + br))
    gemm_h<<<dim3(DDIM / BN, MTOT / BM, 1), 256, GSM_TOTAL>>>(
        attH, inH, DDIM, WrTH, br, rp, DDIM, 2 * DDIM,
        DDIM, 0, 2 * DDIM, 0, 0, 1, 0, 1, 4, nullptr, nullptr, 0);

    final_kernel<<<BB, 512>>>(r1p, r2p, Wm, bm, Wo, bo, (float*)d_out);
}

// round 14
// speedup vs baseline: 2.3637x; 1.0017x over previous
#include <cuda_runtime.h>
#include <cuda_fp16.h>
#include <cstdint>

#define BB 128
#define LCDIM 256
#define LEDIM 1024
#define DDIM 256
#define MMDIM 512
#define NEGV -1e9f

// ---------------- scratch ----------------------------------------------------
__device__ __align__(16) __half g_inH[(size_t)BB * (LCDIM + LEDIM) * DDIM];  // critH | ehrH
__device__ __align__(16) __half g_ceH[(size_t)BB * (LCDIM + LEDIM) * DDIM];  // cH | eH
__device__ __align__(16) __half g_attH[(size_t)BB * (LCDIM + LEDIM) * DDIM]; // attcH | atteH
__device__ __align__(16) __half g_alignH[(size_t)BB * LCDIM * LEDIM];   // E row-major
__device__ __align__(16) __half g_alignTH[(size_t)BB * LCDIM * LEDIM];  // E^T (Le,Lc)
__device__ __align__(16) __half g_ehrTH[(size_t)BB * LEDIM * DDIM];     // masked by em
__device__ __align__(16) __half g_critTH[(size_t)BB * LCDIM * DDIM];    // masked by cm
__device__ __align__(16) __half g_WaTH[DDIM * DDIM];
__device__ __align__(16) __half g_WrTH[DDIM * 2 * DDIM];
__device__ float g_rp[(2 + 8) * BB * DDIM];
__device__ float g_colsum[BB * LEDIM];
__device__ float g_rowsum[BB * LCDIM];

// ---------------- helpers -----------------------------------------------------
__device__ __forceinline__ uint32_t smem_u32(const void* p) {
    uint32_t a;
    asm("{ .reg .u64 t; cvta.to.shared.u64 t, %1; cvt.u32.u64 %0, t; }"
        : "=r"(a) : "l"(p));
    return a;
}

#define SW128B(o) ((o) ^ (((o) >> 3) & 0x70))

__device__ __forceinline__ void ldsm4h(uint32_t& r0, uint32_t& r1, uint32_t& r2,
                                       uint32_t& r3, uint32_t addr) {
    asm volatile("ldmatrix.sync.aligned.m8n8.x4.shared.b16 {%0,%1,%2,%3}, [%4];"
                 : "=r"(r0), "=r"(r1), "=r"(r2), "=r"(r3) : "r"(addr));
}

__device__ __forceinline__ void mma16(float* c, const uint32_t* a, uint32_t b0, uint32_t b1) {
    asm volatile(
        "mma.sync.aligned.m16n8k16.row.col.f32.f16.f16.f32 "
        "{%0,%1,%2,%3}, {%4,%5,%6,%7}, {%8,%9}, {%0,%1,%2,%3};"
        : "+f"(c[0]), "+f"(c[1]), "+f"(c[2]), "+f"(c[3])
        : "r"(a[0]), "r"(a[1]), "r"(a[2]), "r"(a[3]), "r"(b0), "r"(b1));
}

#define CP16(d, g) \
    asm volatile("cp.async.cg.shared.global [%0], [%1], 16;" :: "r"(d), "l"(g))

// ---------------- FP16 tensor-core GEMM core (validated mainloop) --------------
#define BM 128
#define BN 128
#define BKH 64
#define SA_OFF(s) ((s) * 16384)
#define SB_OFF(s) (49152 + (s) * 16384)
#define GSM_TOTAL 98304
#define TP 130   // epilogue tile pad (halves); 65 words (odd) -> conflict-free

__device__ __forceinline__ void gemm_core(
    const __half* __restrict__ A, const __half* __restrict__ A2, int Ksplit,
    const __half* __restrict__ B, const float* __restrict__ bias,
    void* __restrict__ Cv,
    int N, int K, long sAm, long sBn,
    int do_relu, int out_half, int sum_out,
    const float* __restrict__ rowscale,          // att: scale rows by 1/rowscale
    __half* __restrict__ expT, float* __restrict__ rowsum,
    float* __restrict__ colsum,
    const int* __restrict__ cmrow, const int* __restrict__ emcol, int expT_ld,
    int m0, int n0, char* sm)
{
    const int tid = threadIdx.x;
    const int lane = tid & 31;
    const int w = tid >> 5;
    const int wm = (w & 1) * 64;
    const int wn = (w >> 1) * 32;
    const uint32_t sb = smem_u32(sm);

    auto issueA = [&](int k0, int s) {
        const __half* Ap = A; int kb = k0;
        if (A2 && k0 >= Ksplit) { Ap = A2; kb = k0 - Ksplit; }
        uint32_t base = sb + SA_OFF(s);
#pragma unroll
        for (int i = 0; i < 4; i++) {
            int f = tid + i * 256;
            int row = f >> 3, hq = (f & 7) * 8;
            CP16(base + SW128B(row * 128 + hq * 2),
                 Ap + (long)(m0 + row) * sAm + kb + hq);
        }
    };
    auto issueB = [&](int k0, int s) {
        uint32_t base = sb + SB_OFF(s);
#pragma unroll
        for (int i = 0; i < 4; i++) {
            int f = tid + i * 256;
            int row = f >> 3, hq = (f & 7) * 8;
            CP16(base + SW128B(row * 128 + hq * 2),
                 B + (long)(n0 + row) * sBn + k0 + hq);
        }
    };

    float acc[4][4][4];
#pragma unroll
    for (int i = 0; i < 4; i++)
#pragma unroll
        for (int j = 0; j < 4; j++)
#pragma unroll
            for (int r = 0; r < 4; r++) acc[i][j][r] = 0.f;

    const int T = K / BKH;
    issueA(0, 0); issueB(0, 0);
    asm volatile("cp.async.commit_group;" ::: "memory");
    if (T > 1) {
        issueA(BKH, 1); issueB(BKH, 1);
        asm volatile("cp.async.commit_group;" ::: "memory");
    }

    for (int t = 0; t < T; t++) {
        const int s = t % 3;
        if (t == T - 1)
            asm volatile("cp.async.wait_group 0;" ::: "memory");
        else
            asm volatile("cp.async.wait_group 1;" ::: "memory");
        __syncthreads();
        if (t + 2 < T) {
            issueA((t + 2) * BKH, (t + 2) % 3);
            issueB((t + 2) * BKH, (t + 2) % 3);
            asm volatile("cp.async.commit_group;" ::: "memory");
        }

        const uint32_t abase = sb + SA_OFF(s);
        const uint32_t bbase = sb + SB_OFF(s);
#pragma unroll
        for (int ks = 0; ks < 4; ks++) {
            uint32_t a[4][4], bf[2][4];

            const int arow = lane & 15;
            const int acolh = ks * 16 + (lane >> 4) * 8;
#pragma unroll
            for (int mt = 0; mt < 4; mt++)
                ldsm4h(a[mt][0], a[mt][1], a[mt][2], a[mt][3],
                       abase + SW128B((wm + mt * 16 + arow) * 128 + acolh * 2));

            const int brow = (lane & 7) + (lane >= 16 ? 8 : 0);
            const int bcolh = ks * 16 + ((lane >> 3) & 1) * 8;
#pragma unroll
            for (int np = 0; np < 2; np++)
                ldsm4h(bf[np][0], bf[np][1], bf[np][2], bf[np][3],
                       bbase + SW128B((wn + np * 16 + brow) * 128 + bcolh * 2));

#pragma unroll
            for (int mt = 0; mt < 4; mt++)
#pragma unroll
                for (int nt = 0; nt < 4; nt++)
                    mma16(acc[mt][nt], a[mt],
                          bf[nt >> 1][(nt & 1) * 2], bf[nt >> 1][(nt & 1) * 2 + 1]);
        }
    }

    const int g = lane >> 2, tg = lane & 3;

    if (sum_out) {
        float* P = (float*)Cv + (long)(m0 / BM) * N;
#pragma unroll
        for (int nt = 0; nt < 4; nt++) {
            int col = n0 + wn + nt * 8 + tg * 2;
            float bv0 = bias ? bias[col] : 0.f;
            float bv1 = bias ? bias[col + 1] : 0.f;
            float s0 = 0.f, s1 = 0.f;
#pragma unroll
            for (int mt = 0; mt < 4; mt++)
#pragma unroll
                for (int h = 0; h < 2; h++) {
                    float v0 = acc[mt][nt][2 * h] + bv0;
                    float v1 = acc[mt][nt][2 * h + 1] + bv1;
                    if (do_relu) { v0 = fmaxf(v0, 0.f); v1 = fmaxf(v1, 0.f); }
                    s0 += v0; s1 += v1;
                }
#pragma unroll
            for (int off = 16; off >= 4; off >>= 1) {
                s0 += __shfl_xor_sync(0xffffffffu, s0, off);
                s1 += __shfl_xor_sync(0xffffffffu, s1, off);
            }
            if (g == 0) {
                atomicAdd(&P[col], s0);
                atomicAdd(&P[col + 1], s1);
            }
        }
        return;
    }

    if (expT) {
        // E = fp16(exp(acc) * 2^-4): row-major out, transposed out, masked sums.
        __syncthreads();   // mainloop smem now free
        __half* tile = reinterpret_cast<__half*>(sm);             // [128][TP]
        float* em_s = reinterpret_cast<float*>(sm + 128 * TP * 2); // col masks
        float* cm_s = em_s + 128;                                  // row masks
        if (tid < 128) em_s[tid] = emcol[n0 + tid] ? 1.f : 0.f;
        else           cm_s[tid - 128] = cmrow[m0 + tid - 128] ? 1.f : 0.f;

#pragma unroll
        for (int mt = 0; mt < 4; mt++)
#pragma unroll
            for (int nt = 0; nt < 4; nt++)
#pragma unroll
                for (int h = 0; h < 2; h++) {
                    int rl = wm + mt * 16 + g + h * 8;
                    int cl = wn + nt * 8 + tg * 2;
                    float e0 = __expf(acc[mt][nt][2 * h]) * 0.0625f;
                    float e1 = __expf(acc[mt][nt][2 * h + 1]) * 0.0625f;
                    __half2 hv = __floats2half2_rn(e0, e1);
                    *reinterpret_cast<__half2*>(
                        (__half*)Cv + (long)(m0 + rl) * N + n0 + cl) = hv;
                    *reinterpret_cast<__half2*>(&tile[rl * TP + cl]) = hv;
                }
        __syncthreads();

        if (tid < 128) {                 // rowsum (em-masked cols)
            float s = 0.f;
#pragma unroll 4
            for (int c = 0; c < 128; c++)
                s += __half2float(tile[tid * TP + c]) * em_s[c];
            atomicAdd(&rowsum[m0 + tid], s);
        } else {                         // colsum (cm-masked rows)
            int c = tid - 128;
            float s = 0.f;
#pragma unroll 4
            for (int l = 0; l < 128; l++)
                s += __half2float(tile[l * TP + c]) * cm_s[l];
            atomicAdd(&colsum[n0 + c], s);
        }
        __syncthreads();

        // transposed write: thread -> (e_local, 64-half l-span)
        {
            int e_l = tid >> 1, l0h = (tid & 1) * 64;
            __half* dst = expT + (long)(n0 + e_l) * expT_ld + m0 + l0h;
#pragma unroll
            for (int j = 0; j < 8; j++) {
                __half tmp[8];
#pragma unroll
                for (int i = 0; i < 8; i++)
                    tmp[i] = tile[(l0h + j * 8 + i) * TP + e_l];
                *reinterpret_cast<uint4*>(dst + j * 8) =
                    *reinterpret_cast<uint4*>(tmp);
            }
        }
        return;
    }

    float rsv[4][2];
    if (rowscale) {
#pragma unroll
        for (int mt = 0; mt < 4; mt++)
#pragma unroll
            for (int h = 0; h < 2; h++)
                rsv[mt][h] = 1.f / rowscale[m0 + wm + mt * 16 + g + h * 8];
    }

#pragma unroll
    for (int mt = 0; mt < 4; mt++) {
#pragma unroll
        for (int nt = 0; nt < 4; nt++) {
            int row = m0 + wm + mt * 16 + g;
            int col = n0 + wn + nt * 8 + tg * 2;
            float bv0 = 0.f, bv1 = 0.f;
            if (bias) { bv0 = bias[col]; bv1 = bias[col + 1]; }
#pragma unroll
            for (int h = 0; h < 2; h++) {
                long ci = (long)(row + h * 8) * N + col;
                float v0 = acc[mt][nt][2 * h] + bv0;
                float v1 = acc[mt][nt][2 * h + 1] + bv1;
                if (rowscale) { v0 *= rsv[mt][h]; v1 *= rsv[mt][h]; }
                if (do_relu) { v0 = fmaxf(v0, 0.f); v1 = fmaxf(v1, 0.f); }
                if (out_half) {
                    __half2 hv = __floats2half2_rn(v0, v1);
                    *reinterpret_cast<__half2*>((__half*)Cv + ci) = hv;
                } else {
                    *reinterpret_cast<float2*>((float*)Cv + ci) = make_float2(v0, v1);
                }
            }
        }
    }
}

// ---------------- plain wrapper (ce-GEMM, r-GEMM) ------------------------------
__global__ __launch_bounds__(256, 2) void gemm_h(
    const __half* __restrict__ A, const __half* __restrict__ A2, int Ksplit,
    const __half* __restrict__ B, const float* __restrict__ bias,
    void* __restrict__ Cv, int N, int K, long sAm, long sBn,
    int do_relu, int out_half, int sum_out)
{
    extern __shared__ char sm[];
    gemm_core(A, A2, Ksplit, B, bias, Cv, N, K, sAm, sBn,
              do_relu, out_half, sum_out, nullptr,
              nullptr, nullptr, nullptr, nullptr, nullptr, 0,
              blockIdx.y * BM, blockIdx.x * BN, sm);
}

// ---------------- align wrapper: E + E^T + masked row/col sums -----------------
__global__ __launch_bounds__(256, 2) void gemm_align(
    const __half* __restrict__ cH, const __half* __restrict__ eH,
    __half* __restrict__ E, __half* __restrict__ ET,
    float* __restrict__ rowsum, float* __restrict__ colsum,
    const int* __restrict__ cmask, const int* __restrict__ emask)
{
    extern __shared__ char sm[];
    const long LCD = (long)LCDIM * DDIM;
    const long LED = (long)LEDIM * DDIM;
    const long LCE = (long)LCDIM * LEDIM;
    long z = blockIdx.z;
    gemm_core(cH + z * LCD, nullptr, 0, eH + z * LED, nullptr,
              E + z * LCE, LEDIM, DDIM, DDIM, DDIM,
              0, 1, 0, nullptr,
              ET + z * LCE, rowsum + z * LCDIM, colsum + z * LEDIM,
              cmask + z * LCDIM, emask + z * LEDIM, LCDIM,
              blockIdx.y * BM, blockIdx.x * BN, sm);
}

// ---------------- merged att wrapper (1-D grid, long-K tiles first) ------------
__global__ __launch_bounds__(256, 2) void gemm_att(
    const __half* __restrict__ E, const __half* __restrict__ ehrTH,
    __half* __restrict__ attcH,
    const __half* __restrict__ ET, const __half* __restrict__ critTH,
    __half* __restrict__ atteH,
    const float* __restrict__ rowsum, const float* __restrict__ colsum)
{
    extern __shared__ char sm[];
    const long LCD = (long)LCDIM * DDIM;
    const long LED = (long)LEDIM * DDIM;
    const long LCE = (long)LCDIM * LEDIM;
    int idx = blockIdx.x;
    if (idx < 512) {
        // att_c = (E . em) @ ehr / rowsum : M=256, N=256, K=1024
        int z = idx >> 2, r = idx & 3;
        gemm_core(E + (long)z * LCE, nullptr, 0, ehrTH + (long)z * LED, nullptr,
                  attcH + (long)z * LCD, DDIM, LEDIM, LEDIM, LEDIM,
                  0, 1, 0, rowsum + (long)z * LCDIM,
                  nullptr, nullptr, nullptr, nullptr, nullptr, 0,
                  (r >> 1) * BM, (r & 1) * BN, sm);
    } else {
        // att_e = (E^T . cm) @ crit / colsum : M=1024, N=256, K=256
        int i2 = idx - 512;
        int z = i2 >> 4, r = i2 & 15;
        gemm_core(ET + (long)z * LCE, nullptr, 0, critTH + (long)z * LCD, nullptr,
                  atteH + (long)z * LED, DDIM, LCDIM, LCDIM, LCDIM,
                  0, 1, 0, colsum + (long)z * LEDIM,
                  nullptr, nullptr, nullptr, nullptr, nullptr, 0,
                  (r >> 1) * BM, (r & 1) * BN, sm);
    }
}

// ---------------- merged prep: fp16 row + MASKED fp16 transposed ---------------
__global__ __launch_bounds__(256) void prep2_k(
    const float* __restrict__ crit, __half* __restrict__ critH,
    __half* __restrict__ critTH,
    const float* __restrict__ ehr, __half* __restrict__ ehrH,
    __half* __restrict__ ehrTH,
    const int* __restrict__ cmask, const int* __restrict__ emask)
{
    __shared__ float tile[32][33];
    const long LCD = (long)LCDIM * DDIM, LED = (long)LEDIM * DDIM;
    int b = blockIdx.z, ty = blockIdx.y;
    const float* in; __half *outR, *outT; const int* mask; int R, r0;
    if (ty < 8) {
        in = crit + b * LCD; outR = critH + b * LCD; outT = critTH + b * LCD;
        mask = cmask + b * LCDIM; R = LCDIM; r0 = ty * 32;
    } else {
        in = ehr + b * LED; outR = ehrH + b * LED; outT = ehrTH + b * LED;
        mask = emask + b * LEDIM; R = LEDIM; r0 = (ty - 8) * 32;
    }
    const int C = DDIM;
    int c0 = blockIdx.x * 32;
#pragma unroll
    for (int j = 0; j < 32; j += 8) {
        float v = in[(long)(r0 + threadIdx.y + j) * C + c0 + threadIdx.x];
        tile[threadIdx.y + j][threadIdx.x] = v;
        outR[(long)(r0 + threadIdx.y + j) * C + c0 + threadIdx.x] = __float2half_rn(v);
    }
    float mfac = mask[r0 + threadIdx.x] ? 1.f : 0.f;  // masks original row index
    __syncthreads();
#pragma unroll
    for (int j = 0; j < 32; j += 8)
        outT[(long)(c0 + threadIdx.y + j) * R + r0 + threadIdx.x] =
            __float2half_rn(tile[threadIdx.x][threadIdx.y + j] * mfac);
}

// ---------------- setup: Wa^T + Wr^T + zero (rp, colsum, rowsum) ---------------
__global__ __launch_bounds__(256) void setup_k(
    const float* __restrict__ Wa, __half* __restrict__ WaT,
    const float* __restrict__ Wr, __half* __restrict__ WrT,
    float* __restrict__ z1, int n1, float* __restrict__ z2, int n2,
    float* __restrict__ z3, int n3)
{
    int ty = blockIdx.y;
    if (ty == 24) {
        int i = blockIdx.x * 256 + threadIdx.y * 32 + threadIdx.x;
        for (int j = i; j < n1; j += 2048) z1[j] = 0.f;
        for (int j = i; j < n2; j += 2048) z2[j] = 0.f;
        for (int j = i; j < n3; j += 2048) z3[j] = 0.f;
        return;
    }
    const float* in; __half* out; int R, r0;
    if (ty < 8) { in = Wa; out = WaT; R = DDIM;     r0 = ty * 32; }
    else        { in = Wr; out = WrT; R = 2 * DDIM; r0 = (ty - 8) * 32; }
    const int C = DDIM;
    __shared__ float tile[32][33];
    int c0 = blockIdx.x * 32;
#pragma unroll
    for (int j = 0; j < 32; j += 8)
        tile[threadIdx.y + j][threadIdx.x] =
            in[(long)(r0 + threadIdx.y + j) * C + c0 + threadIdx.x];
    __syncthreads();
#pragma unroll
    for (int j = 0; j < 32; j += 8)
        out[(long)(c0 + threadIdx.y + j) * R + r0 + threadIdx.x] =
            __float2half_rn(tile[threadIdx.x][threadIdx.y + j]);
}

// ---------------- final MLP ----------------------------------------------------
__global__ __launch_bounds__(512) void final_kernel(
    const float* __restrict__ r1p, const float* __restrict__ r2p,
    const float* __restrict__ Wm, const float* __restrict__ bm,
    const float* __restrict__ Wo, const float* __restrict__ bo,
    float* __restrict__ out)
{
    int b = blockIdx.x;
    int t = threadIdx.x;

    __shared__ float ms[4 * DDIM];
    __shared__ float hs[MMDIM];

    if (t < DDIM) {
        float r1 = 0.f, r2 = 0.f;
#pragma unroll
        for (int s = 0; s < 2; s++) r1 += r1p[(b * 2 + s) * DDIM + t];
#pragma unroll
        for (int s = 0; s < 8; s++) r2 += r2p[(b * 8 + s) * DDIM + t];
        ms[t] = r1;
        ms[DDIM + t] = r2;
        ms[2 * DDIM + t] = r1 * r2;
        ms[3 * DDIM + t] = r1 - r2;
    }
    __syncthreads();

    float acc = bm[t];
#pragma unroll 8
    for (int k = 0; k < 4 * DDIM; k++) acc += ms[k] * Wm[(long)k * MMDIM + t];
    hs[t] = fmaxf(acc, 0.f);
    __syncthreads();

    int w = t >> 5, lane = t & 31;
    if (w < 3) {
        float s = 0.f;
        for (int j = lane; j < MMDIM; j += 32) s += hs[j] * Wo[j * 3 + w];
#pragma unroll
        for (int off = 16; off; off >>= 1) s += __shfl_down_sync(0xffffffffu, s, off);
        if (lane == 0) out[b * 3 + w] = s + bo[w];
    }
}

// ---------------- launch -------------------------------------------------------
extern "C" void kernel_launch(void* const* d_in, const int* in_sizes, int n_in,
                              void* d_out, int out_size)
{
    const float *criteria, *ehr, *Wa, *ba, *Wr, *br, *Wm, *bm, *Wo, *bo;
    const int *cmask, *emask;

    if (in_sizes[2] == BB * LCDIM) {
        criteria = (const float*)d_in[0]; ehr = (const float*)d_in[1];
        cmask = (const int*)d_in[2]; emask = (const int*)d_in[3];
        Wa = (const float*)d_in[4]; ba = (const float*)d_in[5];
        Wr = (const float*)d_in[6]; br = (const float*)d_in[7];
        Wm = (const float*)d_in[8]; bm = (const float*)d_in[9];
        Wo = (const float*)d_in[10]; bo = (const float*)d_in[11];
    } else {
        criteria = (const float*)d_in[0]; ehr = (const float*)d_in[1];
        Wa = (const float*)d_in[2]; ba = (const float*)d_in[3];
        Wr = (const float*)d_in[4]; br = (const float*)d_in[5];
        Wm = (const float*)d_in[6]; bm = (const float*)d_in[7];
        Wo = (const float*)d_in[8]; bo = (const float*)d_in[9];
        cmask = (const int*)d_in[10]; emask = (const int*)d_in[11];
    }

    __half *inH, *ceH, *attH, *alignH, *alignTH, *ehrTH, *critTH, *WaTH, *WrTH;
    float *rp, *colsum, *rowsum;
    cudaGetSymbolAddress((void**)&inH,     g_inH);
    cudaGetSymbolAddress((void**)&ceH,     g_ceH);
    cudaGetSymbolAddress((void**)&attH,    g_attH);
    cudaGetSymbolAddress((void**)&alignH,  g_alignH);
    cudaGetSymbolAddress((void**)&alignTH, g_alignTH);
    cudaGetSymbolAddress((void**)&ehrTH,   g_ehrTH);
    cudaGetSymbolAddress((void**)&critTH,  g_critTH);
    cudaGetSymbolAddress((void**)&WaTH,    g_WaTH);
    cudaGetSymbolAddress((void**)&WrTH,    g_WrTH);
    cudaGetSymbolAddress((void**)&rp,      g_rp);
    cudaGetSymbolAddress((void**)&colsum,  g_colsum);
    cudaGetSymbolAddress((void**)&rowsum,  g_rowsum);

    const long LCD = (long)LCDIM * DDIM;   // 65536

    __half* critH = inH;
    __half* ehrH  = inH + (size_t)BB * LCD;
    __half* cH    = ceH;
    __half* eH    = ceH + (size_t)BB * LCD;
    float*  r1p   = rp;
    float*  r2p   = rp + (size_t)BB * 2 * DDIM;

    cudaFuncSetAttribute(gemm_h, cudaFuncAttributeMaxDynamicSharedMemorySize,
                         GSM_TOTAL);
    cudaFuncSetAttribute(gemm_align, cudaFuncAttributeMaxDynamicSharedMemorySize,
                         GSM_TOTAL);
    cudaFuncSetAttribute(gemm_att, cudaFuncAttributeMaxDynamicSharedMemorySize,
                         GSM_TOTAL);

    dim3 tb(32, 8);
    const int MTOT = BB * (LCDIM + LEDIM);          // 163840 rows, 1280 tiles

    // prologue
    prep2_k<<<dim3(8, 40, BB), tb>>>(criteria, critH, critTH, ehr, ehrH, ehrTH,
                                     cmask, emask);
    setup_k<<<dim3(8, 25), tb>>>(Wa, WaTH, Wr, WrTH,
                                 rp, (2 + 8) * BB * DDIM,
                                 colsum, BB * LEDIM, rowsum, BB * LCDIM);

    // [c ; e] = relu([criteria; ehr] @ Wa + ba) -> fp16
    gemm_h<<<dim3(DDIM / BN, MTOT / BM, 1), 256, GSM_TOTAL>>>(
        inH, nullptr, 0, WaTH, ba, ceH, DDIM, DDIM, DDIM, DDIM, 1, 1, 0);

    // E = fp16(exp(c@e^T) * 2^-4) + E^T + masked row/col sums (fused)
    gemm_align<<<dim3(LEDIM / BN, LCDIM / BM, BB), 256, GSM_TOTAL>>>(
        cH, eH, alignH, alignTH, rowsum, colsum, cmask, emask);

    // att_c + att_e with 1/rowsum, 1/colsum scaling (one launch)
    gemm_att<<<2560, 256, GSM_TOTAL>>>(alignH, ehrTH, attH,
                                       alignTH, critTH, attH + (size_t)BB * LCD,
                                       rowsum, colsum);

    // [r1p ; r2p] = rowsum(relu([att ; in] @ Wr + br))
    gemm_h<<<dim3(DDIM / BN, MTOT / BM, 1), 256, GSM_TOTAL>>>(
        attH, inH, DDIM, WrTH, br, rp, DDIM, 2 * DDIM, DDIM, 2 * DDIM, 1, 0, 1);

    final_kernel<<<BB, 512>>>(r1p, r2p, Wm, bm, Wo, bo, (float*)d_out);
}

// round 16
// speedup vs baseline: 2.4019x; 1.0161x over previous
#include <cuda_runtime.h>
#include <cuda_fp16.h>
#include <cstdint>

#define BB 128
#define LCDIM 256
#define LEDIM 1024
#define DDIM 256
#define MMDIM 512
#define NEGV -1e9f

// ---------------- scratch ----------------------------------------------------
__device__ __align__(16) __half g_inH[(size_t)BB * (LCDIM + LEDIM) * DDIM];  // critH | ehrH
__device__ __align__(16) __half g_ceH[(size_t)BB * (LCDIM + LEDIM) * DDIM];  // cH | eH
__device__ __align__(16) __half g_attH[(size_t)BB * (LCDIM + LEDIM) * DDIM]; // attcH | atteH
__device__ __align__(16) __half g_alignH[(size_t)BB * LCDIM * LEDIM];   // E row-major
__device__ __align__(16) __half g_alignTH[(size_t)BB * LCDIM * LEDIM];  // E^T (Le,Lc)
__device__ __align__(16) __half g_ehrTH[(size_t)BB * LEDIM * DDIM];     // masked by em
__device__ __align__(16) __half g_critTH[(size_t)BB * LCDIM * DDIM];    // masked by cm
__device__ __align__(16) __half g_WaTH[DDIM * DDIM];
__device__ __align__(16) __half g_WrTH[DDIM * 2 * DDIM];
__device__ float g_rp[(2 + 8) * BB * DDIM];
__device__ float g_colsum[BB * LEDIM];
__device__ float g_rowsum[BB * LCDIM];

// ---------------- helpers -----------------------------------------------------
__device__ __forceinline__ uint32_t smem_u32(const void* p) {
    uint32_t a;
    asm("{ .reg .u64 t; cvta.to.shared.u64 t, %1; cvt.u32.u64 %0, t; }"
        : "=r"(a) : "l"(p));
    return a;
}

#define SW128B(o) ((o) ^ (((o) >> 3) & 0x70))

__device__ __forceinline__ void ldsm4h(uint32_t& r0, uint32_t& r1, uint32_t& r2,
                                       uint32_t& r3, uint32_t addr) {
    asm volatile("ldmatrix.sync.aligned.m8n8.x4.shared.b16 {%0,%1,%2,%3}, [%4];"
                 : "=r"(r0), "=r"(r1), "=r"(r2), "=r"(r3) : "r"(addr));
}

__device__ __forceinline__ void mma16(float* c, const uint32_t* a, uint32_t b0, uint32_t b1) {
    asm volatile(
        "mma.sync.aligned.m16n8k16.row.col.f32.f16.f16.f32 "
        "{%0,%1,%2,%3}, {%4,%5,%6,%7}, {%8,%9}, {%0,%1,%2,%3};"
        : "+f"(c[0]), "+f"(c[1]), "+f"(c[2]), "+f"(c[3])
        : "r"(a[0]), "r"(a[1]), "r"(a[2]), "r"(a[3]), "r"(b0), "r"(b1));
}

#define CP16(d, g) \
    asm volatile("cp.async.cg.shared.global [%0], [%1], 16;" :: "r"(d), "l"(g))

// ---------------- FP16 tensor-core GEMM core (validated mainloop) --------------
#define BM 128
#define BN 128
#define BKH 64
#define SA_OFF(s) ((s) * 16384)
#define SB_OFF(s) (49152 + (s) * 16384)
#define GSM_TOTAL 98304
#define TP  130   // row-major epilogue tile pad (halves)
#define TPT 136   // transposed tile pad (halves): 272B rows -> 16B-aligned

__device__ __forceinline__ void gemm_core(
    const __half* __restrict__ A, const __half* __restrict__ A2, int Ksplit,
    const __half* __restrict__ B, const float* __restrict__ bias,
    void* __restrict__ Cv,
    int N, int K, long sAm, long sBn,
    int do_relu, int out_half, int sum_out,
    const float* __restrict__ rowscale,
    __half* __restrict__ expT, float* __restrict__ rowsum,
    float* __restrict__ colsum,
    const int* __restrict__ cmrow, const int* __restrict__ emcol, int expT_ld,
    int m0, int n0, char* sm)
{
    const int tid = threadIdx.x;
    const int lane = tid & 31;
    const int w = tid >> 5;
    const int wm = (w & 1) * 64;
    const int wn = (w >> 1) * 32;
    const uint32_t sb = smem_u32(sm);

    auto issueA = [&](int k0, int s) {
        const __half* Ap = A; int kb = k0;
        if (A2 && k0 >= Ksplit) { Ap = A2; kb = k0 - Ksplit; }
        uint32_t base = sb + SA_OFF(s);
#pragma unroll
        for (int i = 0; i < 4; i++) {
            int f = tid + i * 256;
            int row = f >> 3, hq = (f & 7) * 8;
            CP16(base + SW128B(row * 128 + hq * 2),
                 Ap + (long)(m0 + row) * sAm + kb + hq);
        }
    };
    auto issueB = [&](int k0, int s) {
        uint32_t base = sb + SB_OFF(s);
#pragma unroll
        for (int i = 0; i < 4; i++) {
            int f = tid + i * 256;
            int row = f >> 3, hq = (f & 7) * 8;
            CP16(base + SW128B(row * 128 + hq * 2),
                 B + (long)(n0 + row) * sBn + k0 + hq);
        }
    };

    float acc[4][4][4];
#pragma unroll
    for (int i = 0; i < 4; i++)
#pragma unroll
        for (int j = 0; j < 4; j++)
#pragma unroll
            for (int r = 0; r < 4; r++) acc[i][j][r] = 0.f;

    const int T = K / BKH;
    issueA(0, 0); issueB(0, 0);
    asm volatile("cp.async.commit_group;" ::: "memory");
    if (T > 1) {
        issueA(BKH, 1); issueB(BKH, 1);
        asm volatile("cp.async.commit_group;" ::: "memory");
    }

    for (int t = 0; t < T; t++) {
        const int s = t % 3;
        if (t == T - 1)
            asm volatile("cp.async.wait_group 0;" ::: "memory");
        else
            asm volatile("cp.async.wait_group 1;" ::: "memory");
        __syncthreads();
        if (t + 2 < T) {
            issueA((t + 2) * BKH, (t + 2) % 3);
            issueB((t + 2) * BKH, (t + 2) % 3);
            asm volatile("cp.async.commit_group;" ::: "memory");
        }

        const uint32_t abase = sb + SA_OFF(s);
        const uint32_t bbase = sb + SB_OFF(s);
#pragma unroll
        for (int ks = 0; ks < 4; ks++) {
            uint32_t a[4][4], bf[2][4];

            const int arow = lane & 15;
            const int acolh = ks * 16 + (lane >> 4) * 8;
#pragma unroll
            for (int mt = 0; mt < 4; mt++)
                ldsm4h(a[mt][0], a[mt][1], a[mt][2], a[mt][3],
                       abase + SW128B((wm + mt * 16 + arow) * 128 + acolh * 2));

            const int brow = (lane & 7) + (lane >= 16 ? 8 : 0);
            const int bcolh = ks * 16 + ((lane >> 3) & 1) * 8;
#pragma unroll
            for (int np = 0; np < 2; np++)
                ldsm4h(bf[np][0], bf[np][1], bf[np][2], bf[np][3],
                       bbase + SW128B((wn + np * 16 + brow) * 128 + bcolh * 2));

#pragma unroll
            for (int mt = 0; mt < 4; mt++)
#pragma unroll
                for (int nt = 0; nt < 4; nt++)
                    mma16(acc[mt][nt], a[mt],
                          bf[nt >> 1][(nt & 1) * 2], bf[nt >> 1][(nt & 1) * 2 + 1]);
        }
    }

    const int g = lane >> 2, tg = lane & 3;

    if (sum_out) {
        float* P = (float*)Cv + (long)(m0 / BM) * N;
#pragma unroll
        for (int nt = 0; nt < 4; nt++) {
            int col = n0 + wn + nt * 8 + tg * 2;
            float bv0 = bias ? bias[col] : 0.f;
            float bv1 = bias ? bias[col + 1] : 0.f;
            float s0 = 0.f, s1 = 0.f;
#pragma unroll
            for (int mt = 0; mt < 4; mt++)
#pragma unroll
                for (int h = 0; h < 2; h++) {
                    float v0 = acc[mt][nt][2 * h] + bv0;
                    float v1 = acc[mt][nt][2 * h + 1] + bv1;
                    if (do_relu) { v0 = fmaxf(v0, 0.f); v1 = fmaxf(v1, 0.f); }
                    s0 += v0; s1 += v1;
                }
#pragma unroll
            for (int off = 16; off >= 4; off >>= 1) {
                s0 += __shfl_xor_sync(0xffffffffu, s0, off);
                s1 += __shfl_xor_sync(0xffffffffu, s1, off);
            }
            if (g == 0) {
                atomicAdd(&P[col], s0);
                atomicAdd(&P[col + 1], s1);
            }
        }
        return;
    }

    if (expT) {
        // E = fp16(exp(acc) * 2^-4): dual-staged (row tile + transposed tile),
        // masked sums vectorized, ET write vectorized.
        __syncthreads();   // mainloop smem now free
        __half* tile  = reinterpret_cast<__half*>(sm);                    // [128][TP]
        __half* tileT = reinterpret_cast<__half*>(sm + 128 * TP * 2);     // [128][TPT]
        float* em_s = reinterpret_cast<float*>(sm + 128 * (TP + TPT) * 2);
        float* cm_s = em_s + 128;
        if (tid < 128) em_s[tid] = emcol[n0 + tid] ? 1.f : 0.f;
        else           cm_s[tid - 128] = cmrow[m0 + tid - 128] ? 1.f : 0.f;

#pragma unroll
        for (int mt = 0; mt < 4; mt++)
#pragma unroll
            for (int nt = 0; nt < 4; nt++)
#pragma unroll
                for (int h = 0; h < 2; h++) {
                    int rl = wm + mt * 16 + g + h * 8;
                    int cl = wn + nt * 8 + tg * 2;
                    float e0 = __expf(acc[mt][nt][2 * h]) * 0.0625f;
                    float e1 = __expf(acc[mt][nt][2 * h + 1]) * 0.0625f;
                    __half2 hv = __floats2half2_rn(e0, e1);
                    *reinterpret_cast<__half2*>(
                        (__half*)Cv + (long)(m0 + rl) * N + n0 + cl) = hv;
                    *reinterpret_cast<__half2*>(&tile[rl * TP + cl]) = hv;
                    tileT[cl * TPT + rl] = __low2half(hv);
                    tileT[(cl + 1) * TPT + rl] = __high2half(hv);
                }
        __syncthreads();

        if (tid < 128) {                 // rowsum (em-masked cols), vectorized
            float s = 0.f;
            const __half2* rw = reinterpret_cast<const __half2*>(&tile[tid * TP]);
#pragma unroll 8
            for (int c = 0; c < 64; c++) {
                float2 v = __half22float2(rw[c]);
                s += v.x * em_s[2 * c] + v.y * em_s[2 * c + 1];
            }
            atomicAdd(&rowsum[m0 + tid], s);
        } else {                         // colsum (cm-masked rows), vectorized
            int c = tid - 128;
            float s = 0.f;
            const __half2* rw = reinterpret_cast<const __half2*>(&tileT[c * TPT]);
#pragma unroll 8
            for (int l = 0; l < 64; l++) {
                float2 v = __half22float2(rw[l]);
                s += v.x * cm_s[2 * l] + v.y * cm_s[2 * l + 1];
            }
            atomicAdd(&colsum[n0 + c], s);
        }
        __syncthreads();

        // ET write: vectorized from tileT (16B-aligned rows)
        {
            int e_l = tid >> 1, l0h = (tid & 1) * 64;
            const uint4* src = reinterpret_cast<const uint4*>(&tileT[e_l * TPT + l0h]);
            uint4* dst = reinterpret_cast<uint4*>(
                expT + (long)(n0 + e_l) * expT_ld + m0 + l0h);
#pragma unroll
            for (int j = 0; j < 8; j++) dst[j] = src[j];
        }
        return;
    }

    float rsv[4][2];
    if (rowscale) {
#pragma unroll
        for (int mt = 0; mt < 4; mt++)
#pragma unroll
            for (int h = 0; h < 2; h++)
                rsv[mt][h] = 1.f / rowscale[m0 + wm + mt * 16 + g + h * 8];
    }

#pragma unroll
    for (int mt = 0; mt < 4; mt++) {
#pragma unroll
        for (int nt = 0; nt < 4; nt++) {
            int row = m0 + wm + mt * 16 + g;
            int col = n0 + wn + nt * 8 + tg * 2;
            float bv0 = 0.f, bv1 = 0.f;
            if (bias) { bv0 = bias[col]; bv1 = bias[col + 1]; }
#pragma unroll
            for (int h = 0; h < 2; h++) {
                long ci = (long)(row + h * 8) * N + col;
                float v0 = acc[mt][nt][2 * h] + bv0;
                float v1 = acc[mt][nt][2 * h + 1] + bv1;
                if (rowscale) { v0 *= rsv[mt][h]; v1 *= rsv[mt][h]; }
                if (do_relu) { v0 = fmaxf(v0, 0.f); v1 = fmaxf(v1, 0.f); }
                if (out_half) {
                    __half2 hv = __floats2half2_rn(v0, v1);
                    *reinterpret_cast<__half2*>((__half*)Cv + ci) = hv;
                } else {
                    *reinterpret_cast<float2*>((float*)Cv + ci) = make_float2(v0, v1);
                }
            }
        }
    }
}

// ---------------- plain wrapper (ce-GEMM, r-GEMM) ------------------------------
__global__ __launch_bounds__(256, 2) void gemm_h(
    const __half* __restrict__ A, const __half* __restrict__ A2, int Ksplit,
    const __half* __restrict__ B, const float* __restrict__ bias,
    void* __restrict__ Cv, int N, int K, long sAm, long sBn,
    int do_relu, int out_half, int sum_out)
{
    extern __shared__ char sm[];
    gemm_core(A, A2, Ksplit, B, bias, Cv, N, K, sAm, sBn,
              do_relu, out_half, sum_out, nullptr,
              nullptr, nullptr, nullptr, nullptr, nullptr, 0,
              blockIdx.y * BM, blockIdx.x * BN, sm);
}

// ---------------- align wrapper: E + E^T + masked row/col sums -----------------
__global__ __launch_bounds__(256, 2) void gemm_align(
    const __half* __restrict__ cH, const __half* __restrict__ eH,
    __half* __restrict__ E, __half* __restrict__ ET,
    float* __restrict__ rowsum, float* __restrict__ colsum,
    const int* __restrict__ cmask, const int* __restrict__ emask)
{
    extern __shared__ char sm[];
    const long LCD = (long)LCDIM * DDIM;
    const long LED = (long)LEDIM * DDIM;
    const long LCE = (long)LCDIM * LEDIM;
    long z = blockIdx.z;
    gemm_core(cH + z * LCD, nullptr, 0, eH + z * LED, nullptr,
              E + z * LCE, LEDIM, DDIM, DDIM, DDIM,
              0, 1, 0, nullptr,
              ET + z * LCE, rowsum + z * LCDIM, colsum + z * LEDIM,
              cmask + z * LCDIM, emask + z * LEDIM, LCDIM,
              blockIdx.y * BM, blockIdx.x * BN, sm);
}

// ---------------- merged att wrapper (1-D grid, long-K tiles first) ------------
__global__ __launch_bounds__(256, 2) void gemm_att(
    const __half* __restrict__ E, const __half* __restrict__ ehrTH,
    __half* __restrict__ attcH,
    const __half* __restrict__ ET, const __half* __restrict__ critTH,
    __half* __restrict__ atteH,
    const float* __restrict__ rowsum, const float* __restrict__ colsum)
{
    extern __shared__ char sm[];
    const long LCD = (long)LCDIM * DDIM;
    const long LED = (long)LEDIM * DDIM;
    const long LCE = (long)LCDIM * LEDIM;
    int idx = blockIdx.x;
    if (idx < 512) {
        int z = idx >> 2, r = idx & 3;
        gemm_core(E + (long)z * LCE, nullptr, 0, ehrTH + (long)z * LED, nullptr,
                  attcH + (long)z * LCD, DDIM, LEDIM, LEDIM, LEDIM,
                  0, 1, 0, rowsum + (long)z * LCDIM,
                  nullptr, nullptr, nullptr, nullptr, nullptr, 0,
                  (r >> 1) * BM, (r & 1) * BN, sm);
    } else {
        int i2 = idx - 512;
        int z = i2 >> 4, r = i2 & 15;
        gemm_core(ET + (long)z * LCE, nullptr, 0, critTH + (long)z * LCD, nullptr,
                  atteH + (long)z * LED, DDIM, LCDIM, LCDIM, LCDIM,
                  0, 1, 0, colsum + (long)z * LEDIM,
                  nullptr, nullptr, nullptr, nullptr, nullptr, 0,
                  (r >> 1) * BM, (r & 1) * BN, sm);
    }
}

// ---------------- merged prep + setup ------------------------------------------
// grid (8, 65, BB): ty<8 crit, 8<=ty<40 ehr; z==0 && ty>=40: weights (tw 0..23)
// and tw==24: zeroing. (R15 bug: grid-y was 57, so Wr tiles 17..23 and the
// zeroing slice never ran -> garbage accumulators.)
__global__ __launch_bounds__(256) void prep2_k(
    const float* __restrict__ crit, __half* __restrict__ critH,
    __half* __restrict__ critTH,
    const float* __restrict__ ehr, __half* __restrict__ ehrH,
    __half* __restrict__ ehrTH,
    const int* __restrict__ cmask, const int* __restrict__ emask,
    const float* __restrict__ Wa, __half* __restrict__ WaT,
    const float* __restrict__ Wr, __half* __restrict__ WrT,
    float* __restrict__ z1, int n1, float* __restrict__ z2, int n2,
    float* __restrict__ z3, int n3)
{
    __shared__ float tile[32][33];
    const long LCD = (long)LCDIM * DDIM, LED = (long)LEDIM * DDIM;
    int b = blockIdx.z, ty = blockIdx.y;

    if (ty >= 40) {
        if (b != 0) return;
        int tw = ty - 40;
        if (tw == 24) {
            int i = blockIdx.x * 256 + threadIdx.y * 32 + threadIdx.x;
            for (int j = i; j < n1; j += 2048) z1[j] = 0.f;
            for (int j = i; j < n2; j += 2048) z2[j] = 0.f;
            for (int j = i; j < n3; j += 2048) z3[j] = 0.f;
            return;
        }
        const float* in; __half* out; int R, r0;
        if (tw < 8) { in = Wa; out = WaT; R = DDIM;     r0 = tw * 32; }
        else        { in = Wr; out = WrT; R = 2 * DDIM; r0 = (tw - 8) * 32; }
        int c0 = blockIdx.x * 32;
#pragma unroll
        for (int j = 0; j < 32; j += 8)
            tile[threadIdx.y + j][threadIdx.x] =
                in[(long)(r0 + threadIdx.y + j) * DDIM + c0 + threadIdx.x];
        __syncthreads();
#pragma unroll
        for (int j = 0; j < 32; j += 8)
            out[(long)(c0 + threadIdx.y + j) * R + r0 + threadIdx.x] =
                __float2half_rn(tile[threadIdx.x][threadIdx.y + j]);
        return;
    }

    const float* in; __half *outR, *outT; const int* mask; int R, r0;
    if (ty < 8) {
        in = crit + b * LCD; outR = critH + b * LCD; outT = critTH + b * LCD;
        mask = cmask + b * LCDIM; R = LCDIM; r0 = ty * 32;
    } else {
        in = ehr + b * LED; outR = ehrH + b * LED; outT = ehrTH + b * LED;
        mask = emask + b * LEDIM; R = LEDIM; r0 = (ty - 8) * 32;
    }
    const int C = DDIM;
    int c0 = blockIdx.x * 32;
#pragma unroll
    for (int j = 0; j < 32; j += 8) {
        float v = in[(long)(r0 + threadIdx.y + j) * C + c0 + threadIdx.x];
        tile[threadIdx.y + j][threadIdx.x] = v;
        outR[(long)(r0 + threadIdx.y + j) * C + c0 + threadIdx.x] = __float2half_rn(v);
    }
    float mfac = mask[r0 + threadIdx.x] ? 1.f : 0.f;
    __syncthreads();
#pragma unroll
    for (int j = 0; j < 32; j += 8)
        outT[(long)(c0 + threadIdx.y + j) * R + r0 + threadIdx.x] =
            __float2half_rn(tile[threadIdx.x][threadIdx.y + j] * mfac);
}

// ---------------- final MLP ----------------------------------------------------
__global__ __launch_bounds__(512) void final_kernel(
    const float* __restrict__ r1p, const float* __restrict__ r2p,
    const float* __restrict__ Wm, const float* __restrict__ bm,
    const float* __restrict__ Wo, const float* __restrict__ bo,
    float* __restrict__ out)
{
    int b = blockIdx.x;
    int t = threadIdx.x;

    __shared__ float ms[4 * DDIM];
    __shared__ float hs[MMDIM];

    if (t < DDIM) {
        float r1 = 0.f, r2 = 0.f;
#pragma unroll
        for (int s = 0; s < 2; s++) r1 += r1p[(b * 2 + s) * DDIM + t];
#pragma unroll
        for (int s = 0; s < 8; s++) r2 += r2p[(b * 8 + s) * DDIM + t];
        ms[t] = r1;
        ms[DDIM + t] = r2;
        ms[2 * DDIM + t] = r1 * r2;
        ms[3 * DDIM + t] = r1 - r2;
    }
    __syncthreads();

    float acc = bm[t];
#pragma unroll 8
    for (int k = 0; k < 4 * DDIM; k++) acc += ms[k] * Wm[(long)k * MMDIM + t];
    hs[t] = fmaxf(acc, 0.f);
    __syncthreads();

    int w = t >> 5, lane = t & 31;
    if (w < 3) {
        float s = 0.f;
        for (int j = lane; j < MMDIM; j += 32) s += hs[j] * Wo[j * 3 + w];
#pragma unroll
        for (int off = 16; off; off >>= 1) s += __shfl_down_sync(0xffffffffu, s, off);
        if (lane == 0) out[b * 3 + w] = s + bo[w];
    }
}

// ---------------- launch -------------------------------------------------------
extern "C" void kernel_launch(void* const* d_in, const int* in_sizes, int n_in,
                              void* d_out, int out_size)
{
    const float *criteria, *ehr, *Wa, *ba, *Wr, *br, *Wm, *bm, *Wo, *bo;
    const int *cmask, *emask;

    if (in_sizes[2] == BB * LCDIM) {
        criteria = (const float*)d_in[0]; ehr = (const float*)d_in[1];
        cmask = (const int*)d_in[2]; emask = (const int*)d_in[3];
        Wa = (const float*)d_in[4]; ba = (const float*)d_in[5];
        Wr = (const float*)d_in[6]; br = (const float*)d_in[7];
        Wm = (const float*)d_in[8]; bm = (const float*)d_in[9];
        Wo = (const float*)d_in[10]; bo = (const float*)d_in[11];
    } else {
        criteria = (const float*)d_in[0]; ehr = (const float*)d_in[1];
        Wa = (const float*)d_in[2]; ba = (const float*)d_in[3];
        Wr = (const float*)d_in[4]; br = (const float*)d_in[5];
        Wm = (const float*)d_in[6]; bm = (const float*)d_in[7];
        Wo = (const float*)d_in[8]; bo = (const float*)d_in[9];
        cmask = (const int*)d_in[10]; emask = (const int*)d_in[11];
    }

    __half *inH, *ceH, *attH, *alignH, *alignTH, *ehrTH, *critTH, *WaTH, *WrTH;
    float *rp, *colsum, *rowsum;
    cudaGetSymbolAddress((void**)&inH,     g_inH);
    cudaGetSymbolAddress((void**)&ceH,     g_ceH);
    cudaGetSymbolAddress((void**)&attH,    g_attH);
    cudaGetSymbolAddress((void**)&alignH,  g_alignH);
    cudaGetSymbolAddress((void**)&alignTH, g_alignTH);
    cudaGetSymbolAddress((void**)&ehrTH,   g_ehrTH);
    cudaGetSymbolAddress((void**)&critTH,  g_critTH);
    cudaGetSymbolAddress((void**)&WaTH,    g_WaTH);
    cudaGetSymbolAddress((void**)&WrTH,    g_WrTH);
    cudaGetSymbolAddress((void**)&rp,      g_rp);
    cudaGetSymbolAddress((void**)&colsum,  g_colsum);
    cudaGetSymbolAddress((void**)&rowsum,  g_rowsum);

    const long LCD = (long)LCDIM * DDIM;   // 65536

    __half* critH = inH;
    __half* ehrH  = inH + (size_t)BB * LCD;
    __half* cH    = ceH;
    __half* eH    = ceH + (size_t)BB * LCD;
    float*  r1p   = rp;
    float*  r2p   = rp + (size_t)BB * 2 * DDIM;

    cudaFuncSetAttribute(gemm_h, cudaFuncAttributeMaxDynamicSharedMemorySize,
                         GSM_TOTAL);
    cudaFuncSetAttribute(gemm_align, cudaFuncAttributeMaxDynamicSharedMemorySize,
                         GSM_TOTAL);
    cudaFuncSetAttribute(gemm_att, cudaFuncAttributeMaxDynamicSharedMemorySize,
                         GSM_TOTAL);

    dim3 tb(32, 8);
    const int MTOT = BB * (LCDIM + LEDIM);          // 163840 rows, 1280 tiles

    // prologue (merged prep + weights + zeroing); grid-y = 65 (40 data + 25)
    prep2_k<<<dim3(8, 65, BB), tb>>>(criteria, critH, critTH, ehr, ehrH, ehrTH,
                                     cmask, emask, Wa, WaTH, Wr, WrTH,
                                     rp, (2 + 8) * BB * DDIM,
                                     colsum, BB * LEDIM, rowsum, BB * LCDIM);

    // [c ; e] = relu([criteria; ehr] @ Wa + ba) -> fp16
    gemm_h<<<dim3(DDIM / BN, MTOT / BM, 1), 256, GSM_TOTAL>>>(
        inH, nullptr, 0, WaTH, ba, ceH, DDIM, DDIM, DDIM, DDIM, 1, 1, 0);

    // E = fp16(exp(c@e^T) * 2^-4) + E^T + masked row/col sums (fused)
    gemm_align<<<dim3(LEDIM / BN, LCDIM / BM, BB), 256, GSM_TOTAL>>>(
        cH, eH, alignH, alignTH, rowsum, colsum, cmask, emask);

    // att_c + att_e with 1/rowsum, 1/colsum scaling (one launch)
    gemm_att<<<2560, 256, GSM_TOTAL>>>(alignH, ehrTH, attH,
                                       alignTH, critTH, attH + (size_t)BB * LCD,
                                       rowsum, colsum);

    // [r1p ; r2p] = rowsum(relu([att ; in] @ Wr + br))
    gemm_h<<<dim3(DDIM / BN, MTOT / BM, 1), 256, GSM_TOTAL>>>(
        attH, inH, DDIM, WrTH, br, rp, DDIM, 2 * DDIM, DDIM, 2 * DDIM, 1, 0, 1);

    final_kernel<<<BB, 512>>>(r1p, r2p, Wm, bm, Wo, bo, (float*)d_out);
}